// round 1
// baseline (speedup 1.0000x reference)
#include <cuda_runtime.h>
#include <cstdint>

#define FSZ   50
#define NPIX  2500
#define OC    512
#define ICC   512
#define KTOT  4608      // 512*9
#define NANCH 22500     // 2500*9
#define SORTN 32768
#define PRE   6000
#define NW    94        // ceil(6000/64) -> 94 words, 6016 bits
#define ROWS  6016
#define POST  300

// ---------------- scratch (static device allocations; no cudaMalloc) ----------------
__device__ float               g_feat[OC * NPIX];          // conv output (batch 7)
__device__ float4              g_boxes[NANCH];             // decoded boxes x1,y1,x2,y2
__device__ unsigned long long  g_keys[SORTN];              // sort keys
__device__ float4              g_sbox[ROWS];               // top-6000 boxes (padded)
__device__ float               g_area[ROWS];
__device__ unsigned long long  g_mask[(size_t)ROWS * NW];  // IoU suppression bitmask
__device__ unsigned long long  g_keep[NW];
__device__ int4                g_decode[KTOT];             // (c*2500, ky-1, kx-1, 0)

// ---------------- setup: decode table + key padding ----------------
__global__ void setup_kernel() {
    int i = blockIdx.x * blockDim.x + threadIdx.x;
    if (i < KTOT) {
        int c = i / 9, r = i - 9 * c;
        int ky = r / 3, kx = r - 3 * ky;
        g_decode[i] = make_int4(c * NPIX, ky - 1, kx - 1, 0);
    }
    if (i >= NANCH && i < SORTN) g_keys[i] = ~0ull;
}

// ---------------- conv 3x3 (batch 7 only) + leaky relu ----------------
// implicit GEMM: M=512 (oc), N=2500 (pix), K=4608. BM=BN=64, BK=32, 64 threads, 8x8 micro.
#define BM 64
#define BN 64
#define BK 32
__global__ __launch_bounds__(64) void conv3_kernel(const float* __restrict__ in,
                                                   const float* __restrict__ w,
                                                   const float* __restrict__ bias) {
    __shared__ float As[BK][BM + 4];   // stride 68 floats (272B, 16B aligned)
    __shared__ float Bs[BK][BN + 4];
    int t   = threadIdx.x;
    int p0  = blockIdx.x * BN;     // pixel tile (40 tiles)
    int oc0 = blockIdx.y * BM;     // oc tile (8 tiles)
    int pix = p0 + t;
    int py  = pix / FSZ;
    int px  = pix - py * FSZ;
    bool pv = pix < NPIX;
    int ty = t >> 3, tx = t & 7;

    float acc[8][8];
#pragma unroll
    for (int i = 0; i < 8; i++)
#pragma unroll
        for (int j = 0; j < 8; j++) acc[i][j] = 0.f;

    for (int k0 = 0; k0 < KTOT; k0 += BK) {
        // A tile: weights [64 oc][32 k]
#pragma unroll
        for (int j = 0; j < 8; j++) {
            int m  = j * 8 + (t >> 3);
            int kk = (t & 7) * 4;
            float4 v = *reinterpret_cast<const float4*>(&w[(size_t)(oc0 + m) * KTOT + k0 + kk]);
            As[kk + 0][m] = v.x; As[kk + 1][m] = v.y;
            As[kk + 2][m] = v.z; As[kk + 3][m] = v.w;
        }
        // B tile: input patches [32 k][64 pix]
#pragma unroll 8
        for (int j = 0; j < BK; j++) {
            int4 d = g_decode[k0 + j];
            int iy = py + d.y, ix = px + d.z;
            float v = 0.f;
            if (pv && iy >= 0 && iy < FSZ && ix >= 0 && ix < FSZ)
                v = in[d.x + iy * FSZ + ix];
            Bs[j][t] = v;
        }
        __syncthreads();
#pragma unroll
        for (int kk = 0; kk < BK; kk++) {
            float a[8], b[8];
            *(float4*)(a)     = *(float4*)&As[kk][ty * 8];
            *(float4*)(a + 4) = *(float4*)&As[kk][ty * 8 + 4];
            *(float4*)(b)     = *(float4*)&Bs[kk][tx * 8];
            *(float4*)(b + 4) = *(float4*)&Bs[kk][tx * 8 + 4];
#pragma unroll
            for (int i = 0; i < 8; i++)
#pragma unroll
                for (int j = 0; j < 8; j++) acc[i][j] += a[i] * b[j];
        }
        __syncthreads();
    }
#pragma unroll
    for (int i = 0; i < 8; i++) {
        int oc = oc0 + ty * 8 + i;
        float bv = bias[oc];
#pragma unroll
        for (int j = 0; j < 8; j++) {
            int p = p0 + tx * 8 + j;
            if (p < NPIX) {
                float f = acc[i][j] + bv;
                f = (f >= 0.f) ? f : 0.01f * f;
                g_feat[(size_t)oc * NPIX + p] = f;
            }
        }
    }
}

// ---------------- heads: 1x1 convs + softmax + anchor decode + keys ----------------
__global__ __launch_bounds__(128) void heads_kernel(const float* __restrict__ reg_w,
                                                    const float* __restrict__ reg_b,
                                                    const float* __restrict__ cls_w,
                                                    const float* __restrict__ cls_b) {
    __shared__ float wsm[128][56];  // [c][o] chunk, o: 0..35 reg, 36..53 cls
    int t = threadIdx.x;
    int p = blockIdx.x * 128 + t;
    float acc[54];
#pragma unroll
    for (int o = 0; o < 54; o++) acc[o] = 0.f;

    for (int c0 = 0; c0 < 512; c0 += 128) {
        for (int i = t; i < 54 * 128; i += 128) {
            int o = i / 128, c = i - o * 128;
            float v = (o < 36) ? reg_w[o * 512 + c0 + c] : cls_w[(o - 36) * 512 + c0 + c];
            wsm[c][o] = v;
        }
        __syncthreads();
        if (p < NPIX) {
            for (int c = 0; c < 128; c++) {
                float f = g_feat[(size_t)(c0 + c) * NPIX + p];
#pragma unroll
                for (int o = 0; o < 54; o++) acc[o] += f * wsm[c][o];
            }
        }
        __syncthreads();
    }
    if (p >= NPIX) return;

#pragma unroll
    for (int o = 0; o < 36; o++) acc[o] += reg_b[o];
#pragma unroll
    for (int o = 0; o < 18; o++) acc[36 + o] += cls_b[o];

    // anchors: cx = c[p//50], cy = c[p%50], c[i] = 16*i + 8
    int pq = p / FSZ, pr = p - pq * FSZ;
    float cxv = 16.f * (float)pq + 8.f;
    float cyv = 16.f * (float)pr + 8.f;
    const float ssv[3]  = {8.f, 16.f, 32.f};
    const float sqr[3]  = {0.70710678f, 1.0f, 1.41421356f};   // sqrt(rs)
    const float sqi[3]  = {1.41421356f, 1.0f, 0.70710678f};   // sqrt(1/rs)
    const float NEGINF = __int_as_float(0xff800000);

#pragma unroll
    for (int k = 0; k < 9; k++) {
        float pr0 = acc[k * 4 + 0], pr1 = acc[k * 4 + 1];
        float pr2 = acc[k * 4 + 2], pr3 = acc[k * 4 + 3];
        float l0 = acc[36 + k * 2], l1 = acc[36 + k * 2 + 1];
        float m  = fmaxf(l0, l1);
        float e0 = expf(l0 - m), e1 = expf(l1 - m);
        float sc = e1 / (e0 + e1);

        int ri = k / 3, si = k - 3 * ri;
        float hk = (16.f * ssv[si]) * sqr[ri];
        float wk = (16.f * ssv[si]) * sqi[ri];
        float ax1 = cxv - wk * 0.5f;
        float ay1 = cyv - hk * 0.5f;
        const float hi = 799.f;
        float rx1 = fminf(fmaxf(pr0 + ax1, 0.f), hi);
        float ry1 = fminf(fmaxf(pr1 + ay1, 0.f), hi);
        float rx2 = fminf(fmaxf(((pr0 + ax1) + pr2) + wk, 0.f), hi);
        float ry2 = fminf(fmaxf(((pr1 + ay1) + pr3) + hk, 0.f), hi);
        float wv = pr2 + wk, hv = pr3 + hk;
        bool valid = (wv >= 16.f) && (hv >= 16.f);
        float s = valid ? sc : NEGINF;

        int a = p * 9 + k;
        g_boxes[a] = make_float4(rx1, ry1, rx2, ry2);
        unsigned u = __float_as_uint(s);
        u = (u >> 31) ? ~u : (u | 0x80000000u);
        g_keys[a] = ((unsigned long long)(~u) << 32) | (unsigned)a;
    }
}

// ---------------- bitonic sort (u64 keys, n=32768) ----------------
__global__ void bitonic_global(int k, int j) {
    int i = blockIdx.x * blockDim.x + threadIdx.x;
    int l = i ^ j;
    if (l > i) {
        unsigned long long a = g_keys[i], b = g_keys[l];
        bool asc = ((i & k) == 0);
        if (asc ? (a > b) : (a < b)) { g_keys[i] = b; g_keys[l] = a; }
    }
}

__global__ __launch_bounds__(1024) void bitonic_shared(int kout) {
    __shared__ unsigned long long s[2048];
    int t = threadIdx.x;
    int base = blockIdx.x * 2048;
    s[t] = g_keys[base + t];
    s[t + 1024] = g_keys[base + t + 1024];
    __syncthreads();
    if (kout == 2048) {
        for (int k = 2; k <= 2048; k <<= 1) {
            for (int j = k >> 1; j > 0; j >>= 1) {
                int low = t & (j - 1);
                int i1 = ((t - low) << 1) + low;
                int i2 = i1 | j;
                bool asc = (((base + i1) & k) == 0);
                unsigned long long a = s[i1], b = s[i2];
                if (asc ? (a > b) : (a < b)) { s[i1] = b; s[i2] = a; }
                __syncthreads();
            }
        }
    } else {
        int k = kout;
        for (int j = 1024; j > 0; j >>= 1) {
            int low = t & (j - 1);
            int i1 = ((t - low) << 1) + low;
            int i2 = i1 | j;
            bool asc = (((base + i1) & k) == 0);
            unsigned long long a = s[i1], b = s[i2];
            if (asc ? (a > b) : (a < b)) { s[i1] = b; s[i2] = a; }
            __syncthreads();
        }
    }
    g_keys[base + t] = s[t];
    g_keys[base + t + 1024] = s[t + 1024];
}

// ---------------- gather top-6000 ----------------
__global__ void gather_kernel() {
    int i = blockIdx.x * blockDim.x + threadIdx.x;
    if (i >= ROWS) return;
    if (i < PRE) {
        unsigned idx = (unsigned)(g_keys[i] & 0xFFFFFFFFull);
        float4 b = g_boxes[idx];
        g_sbox[i] = b;
        g_area[i] = (b.z - b.x + 1.f) * (b.w - b.y + 1.f);
    } else {
        g_sbox[i] = make_float4(0.f, 0.f, 0.f, 0.f);
        g_area[i] = 1.f;
    }
}

// ---------------- NMS mask (replicates reference's yy2 = max bug) ----------------
__global__ __launch_bounds__(64) void nms_mask_kernel() {
    int gi = blockIdx.y, gj = blockIdx.x;
    if (gj < gi) return;   // only upper triangle (incl diagonal) is consulted
    __shared__ float4 cbx[64];
    __shared__ float  car[64];
    int t = threadIdx.x;
    int j0 = gj * 64;
    cbx[t] = g_sbox[j0 + t];
    car[t] = g_area[j0 + t];
    __syncthreads();
    int i = gi * 64 + t;
    float4 bi = g_sbox[i];
    float  ai = g_area[i];
    unsigned long long word = 0;
#pragma unroll 8
    for (int jj = 0; jj < 64; jj++) {
        float4 bj = cbx[jj];
        float xx1 = fmaxf(bi.x, bj.x);
        float yy1 = fmaxf(bi.y, bj.y);
        float xx2 = fminf(bi.z, bj.z);
        float yy2 = fmaxf(bi.w, bj.w);   // reference bug: maximum, not minimum
        float w = fmaxf(0.f, xx2 - xx1 + 1.f);
        float h = fmaxf(0.f, yy2 - yy1 + 1.f);
        float inter = w * h;
        float ov = inter / (ai + car[jj] - inter);
        word |= ((unsigned long long)(ov > 0.7f)) << jj;
    }
    g_mask[(size_t)i * NW + gj] = word;
}

// ---------------- greedy NMS scan (exact equivalent of reference fori_loop) ----------------
__global__ __launch_bounds__(128) void nms_scan_kernel() {
    __shared__ unsigned long long remv[NW];
    __shared__ unsigned long long ms[64];
    __shared__ unsigned long long s_kept;
    int t = threadIdx.x;
    if (t < NW) remv[t] = 0ull;
    __syncthreads();
    for (int cb = 0; cb < NW; cb++) {
        if (t < 64) ms[t] = g_mask[(size_t)(cb * 64 + t) * NW + cb];
        __syncthreads();
        if (t == 0) {
            unsigned long long v = remv[cb], kept = 0ull;
#pragma unroll
            for (int j = 0; j < 64; j++) {
                if (!((v >> j) & 1ull) && (cb * 64 + j) < PRE) {
                    kept |= 1ull << j;
                    v |= ms[j];
                }
            }
            s_kept = kept;
            g_keep[cb] = kept;
        }
        __syncthreads();
        unsigned long long kept = s_kept;
        for (int g = cb + 1 + t; g < NW; g += blockDim.x) {
            unsigned long long a = remv[g];
            unsigned long long kk = kept;
            while (kk) {
                int j = __ffsll(kk) - 1;
                kk &= kk - 1;
                a |= g_mask[(size_t)(cb * 64 + j) * NW + g];
            }
            remv[g] = a;
        }
        __syncthreads();
    }
}

// ---------------- emit top-300 (kept in order, then non-kept by index) ----------------
__global__ __launch_bounds__(256) void output_kernel(float* __restrict__ out) {
    __shared__ int cnts[256];
    __shared__ int offs[256];
    __shared__ int Ktot;
    int t = threadIdx.x;
    int lo = t * 24;
    int hi = lo + 24; if (hi > PRE) hi = PRE;
    int c = 0;
    for (int i = lo; i < hi; i++)
        c += (int)((g_keep[i >> 6] >> (i & 63)) & 1ull);
    cnts[t] = c;
    __syncthreads();
    if (t == 0) {
        int r = 0;
        for (int q = 0; q < 256; q++) { offs[q] = r; r += cnts[q]; }
        Ktot = r;
    }
    __syncthreads();
    int K = Ktot;
    int pk = offs[t];
    for (int i = lo; i < hi; i++) {
        bool kept = (g_keep[i >> 6] >> (i & 63)) & 1ull;
        int pos = kept ? pk : (K + (i - pk));
        if (kept) pk++;
        if (pos < POST) {
            float4 b = g_sbox[i];
            out[pos * 4 + 0] = b.x;
            out[pos * 4 + 1] = b.y;
            out[pos * 4 + 2] = b.z - b.x + 1.f;
            out[pos * 4 + 3] = b.w - b.y + 1.f;
        }
    }
}

// ---------------- launch ----------------
extern "C" void kernel_launch(void* const* d_in, const int* in_sizes, int n_in,
                              void* d_out, int out_size) {
    const float* in_features = (const float*)d_in[0];
    const float* conv_w = (const float*)d_in[1];
    const float* conv_b = (const float*)d_in[2];
    const float* reg_w  = (const float*)d_in[3];
    const float* reg_b  = (const float*)d_in[4];
    const float* cls_w  = (const float*)d_in[5];
    const float* cls_b  = (const float*)d_in[6];
    float* out = (float*)d_out;

    // only batch index 7 feeds the output
    const float* in7 = in_features + (size_t)7 * ICC * NPIX;

    setup_kernel<<<SORTN / 256, 256>>>();
    conv3_kernel<<<dim3(40, 8), 64>>>(in7, conv_w, conv_b);
    heads_kernel<<<20, 128>>>(reg_w, reg_b, cls_w, cls_b);

    bitonic_shared<<<16, 1024>>>(2048);
    for (int k = 4096; k <= SORTN; k <<= 1) {
        for (int j = k >> 1; j >= 2048; j >>= 1)
            bitonic_global<<<SORTN / 1024, 1024>>>(k, j);
        bitonic_shared<<<16, 1024>>>(k);
    }

    gather_kernel<<<(ROWS + 127) / 128, 128>>>();
    nms_mask_kernel<<<dim3(NW, NW), 64>>>();
    nms_scan_kernel<<<1, 128>>>();
    output_kernel<<<1, 256>>>(out);
}

// round 2
// speedup vs baseline: 1.5218x; 1.5218x over previous
#include <cuda_runtime.h>
#include <cstdint>

#define FSZ   50
#define NPIX  2500
#define OC    512
#define ICC   512
#define KTOT  4608      // 512*9
#define NANCH 22500     // 2500*9
#define SORTN 32768
#define PRE   6000
#define NW    94        // ceil(6000/64) -> 94 words, 6016 bits
#define ROWS  6016
#define POST  300

// ---------------- scratch (static device allocations; no cudaMalloc) ----------------
__device__ float               g_feat[OC * NPIX];          // conv output (batch 7)
__device__ float4              g_boxes[NANCH];             // decoded boxes x1,y1,x2,y2
__device__ unsigned long long  g_keys[SORTN];              // sort keys
__device__ float4              g_sbox[ROWS];               // top-6000 boxes (padded)
__device__ float               g_area[ROWS];
__device__ unsigned long long  g_mask[(size_t)ROWS * NW];  // IoU suppression bitmask
__device__ unsigned long long  g_keep[NW];
__device__ int4                g_decode[KTOT];             // (c*2500, ky-1, kx-1, 0)

// ---------------- setup: decode table + key padding ----------------
__global__ void setup_kernel() {
    int i = blockIdx.x * blockDim.x + threadIdx.x;
    if (i < KTOT) {
        int c = i / 9, r = i - 9 * c;
        int ky = r / 3, kx = r - 3 * ky;
        g_decode[i] = make_int4(c * NPIX, ky - 1, kx - 1, 0);
    }
    if (i >= NANCH && i < SORTN) g_keys[i] = ~0ull;
}

// ---------------- conv 3x3 (batch 7 only) + leaky relu ----------------
// implicit GEMM: M=512 (oc), N=2500 (pix), K=4608. BM=BN=64, BK=32, 64 threads, 8x8 micro.
#define BM 64
#define BN 64
#define BK 32
__global__ __launch_bounds__(64) void conv3_kernel(const float* __restrict__ in,
                                                   const float* __restrict__ w,
                                                   const float* __restrict__ bias) {
    __shared__ float As[BK][BM + 4];   // stride 68 floats (272B, 16B aligned)
    __shared__ float Bs[BK][BN + 4];
    int t   = threadIdx.x;
    int p0  = blockIdx.x * BN;     // pixel tile (40 tiles)
    int oc0 = blockIdx.y * BM;     // oc tile (8 tiles)
    int pix = p0 + t;
    int py  = pix / FSZ;
    int px  = pix - py * FSZ;
    bool pv = pix < NPIX;
    int ty = t >> 3, tx = t & 7;

    float acc[8][8];
#pragma unroll
    for (int i = 0; i < 8; i++)
#pragma unroll
        for (int j = 0; j < 8; j++) acc[i][j] = 0.f;

    for (int k0 = 0; k0 < KTOT; k0 += BK) {
        // A tile: weights [64 oc][32 k]
#pragma unroll
        for (int j = 0; j < 8; j++) {
            int m  = j * 8 + (t >> 3);
            int kk = (t & 7) * 4;
            float4 v = *reinterpret_cast<const float4*>(&w[(size_t)(oc0 + m) * KTOT + k0 + kk]);
            As[kk + 0][m] = v.x; As[kk + 1][m] = v.y;
            As[kk + 2][m] = v.z; As[kk + 3][m] = v.w;
        }
        // B tile: input patches [32 k][64 pix]
#pragma unroll 8
        for (int j = 0; j < BK; j++) {
            int4 d = g_decode[k0 + j];
            int iy = py + d.y, ix = px + d.z;
            float v = 0.f;
            if (pv && iy >= 0 && iy < FSZ && ix >= 0 && ix < FSZ)
                v = in[d.x + iy * FSZ + ix];
            Bs[j][t] = v;
        }
        __syncthreads();
#pragma unroll
        for (int kk = 0; kk < BK; kk++) {
            float a[8], b[8];
            *(float4*)(a)     = *(float4*)&As[kk][ty * 8];
            *(float4*)(a + 4) = *(float4*)&As[kk][ty * 8 + 4];
            *(float4*)(b)     = *(float4*)&Bs[kk][tx * 8];
            *(float4*)(b + 4) = *(float4*)&Bs[kk][tx * 8 + 4];
#pragma unroll
            for (int i = 0; i < 8; i++)
#pragma unroll
                for (int j = 0; j < 8; j++) acc[i][j] += a[i] * b[j];
        }
        __syncthreads();
    }
#pragma unroll
    for (int i = 0; i < 8; i++) {
        int oc = oc0 + ty * 8 + i;
        float bv = bias[oc];
#pragma unroll
        for (int j = 0; j < 8; j++) {
            int p = p0 + tx * 8 + j;
            if (p < NPIX) {
                float f = acc[i][j] + bv;
                f = (f >= 0.f) ? f : 0.01f * f;
                g_feat[(size_t)oc * NPIX + p] = f;
            }
        }
    }
}

// ---------------- heads: 1x1 convs + softmax + anchor decode + keys ----------------
__global__ __launch_bounds__(128) void heads_kernel(const float* __restrict__ reg_w,
                                                    const float* __restrict__ reg_b,
                                                    const float* __restrict__ cls_w,
                                                    const float* __restrict__ cls_b) {
    __shared__ float wsm[128][56];  // [c][o] chunk, o: 0..35 reg, 36..53 cls
    int t = threadIdx.x;
    int p = blockIdx.x * 128 + t;
    float acc[54];
#pragma unroll
    for (int o = 0; o < 54; o++) acc[o] = 0.f;

    for (int c0 = 0; c0 < 512; c0 += 128) {
        for (int i = t; i < 54 * 128; i += 128) {
            int o = i / 128, c = i - o * 128;
            float v = (o < 36) ? reg_w[o * 512 + c0 + c] : cls_w[(o - 36) * 512 + c0 + c];
            wsm[c][o] = v;
        }
        __syncthreads();
        if (p < NPIX) {
            for (int c = 0; c < 128; c++) {
                float f = g_feat[(size_t)(c0 + c) * NPIX + p];
#pragma unroll
                for (int o = 0; o < 54; o++) acc[o] += f * wsm[c][o];
            }
        }
        __syncthreads();
    }
    if (p >= NPIX) return;

#pragma unroll
    for (int o = 0; o < 36; o++) acc[o] += reg_b[o];
#pragma unroll
    for (int o = 0; o < 18; o++) acc[36 + o] += cls_b[o];

    // anchors: cx = c[p//50], cy = c[p%50], c[i] = 16*i + 8
    int pq = p / FSZ, pr = p - pq * FSZ;
    float cxv = 16.f * (float)pq + 8.f;
    float cyv = 16.f * (float)pr + 8.f;
    const float ssv[3]  = {8.f, 16.f, 32.f};
    const float sqr[3]  = {0.70710678f, 1.0f, 1.41421356f};   // sqrt(rs)
    const float sqi[3]  = {1.41421356f, 1.0f, 0.70710678f};   // sqrt(1/rs)
    const float NEGINF = __int_as_float(0xff800000);

#pragma unroll
    for (int k = 0; k < 9; k++) {
        float pr0 = acc[k * 4 + 0], pr1 = acc[k * 4 + 1];
        float pr2 = acc[k * 4 + 2], pr3 = acc[k * 4 + 3];
        float l0 = acc[36 + k * 2], l1 = acc[36 + k * 2 + 1];
        float m  = fmaxf(l0, l1);
        float e0 = expf(l0 - m), e1 = expf(l1 - m);
        float sc = e1 / (e0 + e1);

        int ri = k / 3, si = k - 3 * ri;
        float hk = (16.f * ssv[si]) * sqr[ri];
        float wk = (16.f * ssv[si]) * sqi[ri];
        float ax1 = cxv - wk * 0.5f;
        float ay1 = cyv - hk * 0.5f;
        const float hi = 799.f;
        float rx1 = fminf(fmaxf(pr0 + ax1, 0.f), hi);
        float ry1 = fminf(fmaxf(pr1 + ay1, 0.f), hi);
        float rx2 = fminf(fmaxf(((pr0 + ax1) + pr2) + wk, 0.f), hi);
        float ry2 = fminf(fmaxf(((pr1 + ay1) + pr3) + hk, 0.f), hi);
        float wv = pr2 + wk, hv = pr3 + hk;
        bool valid = (wv >= 16.f) && (hv >= 16.f);
        float s = valid ? sc : NEGINF;

        int a = p * 9 + k;
        g_boxes[a] = make_float4(rx1, ry1, rx2, ry2);
        unsigned u = __float_as_uint(s);
        u = (u >> 31) ? ~u : (u | 0x80000000u);
        g_keys[a] = ((unsigned long long)(~u) << 32) | (unsigned)a;
    }
}

// ---------------- bitonic sort (u64 keys, n=32768) ----------------
__global__ void bitonic_global(int k, int j) {
    int i = blockIdx.x * blockDim.x + threadIdx.x;
    int l = i ^ j;
    if (l > i) {
        unsigned long long a = g_keys[i], b = g_keys[l];
        bool asc = ((i & k) == 0);
        if (asc ? (a > b) : (a < b)) { g_keys[i] = b; g_keys[l] = a; }
    }
}

__global__ __launch_bounds__(1024) void bitonic_shared(int kout) {
    __shared__ unsigned long long s[2048];
    int t = threadIdx.x;
    int base = blockIdx.x * 2048;
    s[t] = g_keys[base + t];
    s[t + 1024] = g_keys[base + t + 1024];
    __syncthreads();
    if (kout == 2048) {
        for (int k = 2; k <= 2048; k <<= 1) {
            for (int j = k >> 1; j > 0; j >>= 1) {
                int low = t & (j - 1);
                int i1 = ((t - low) << 1) + low;
                int i2 = i1 | j;
                bool asc = (((base + i1) & k) == 0);
                unsigned long long a = s[i1], b = s[i2];
                if (asc ? (a > b) : (a < b)) { s[i1] = b; s[i2] = a; }
                __syncthreads();
            }
        }
    } else {
        int k = kout;
        for (int j = 1024; j > 0; j >>= 1) {
            int low = t & (j - 1);
            int i1 = ((t - low) << 1) + low;
            int i2 = i1 | j;
            bool asc = (((base + i1) & k) == 0);
            unsigned long long a = s[i1], b = s[i2];
            if (asc ? (a > b) : (a < b)) { s[i1] = b; s[i2] = a; }
            __syncthreads();
        }
    }
    g_keys[base + t] = s[t];
    g_keys[base + t + 1024] = s[t + 1024];
}

// ---------------- gather top-6000 ----------------
__global__ void gather_kernel() {
    int i = blockIdx.x * blockDim.x + threadIdx.x;
    if (i >= ROWS) return;
    if (i < PRE) {
        unsigned idx = (unsigned)(g_keys[i] & 0xFFFFFFFFull);
        float4 b = g_boxes[idx];
        g_sbox[i] = b;
        g_area[i] = (b.z - b.x + 1.f) * (b.w - b.y + 1.f);
    } else {
        g_sbox[i] = make_float4(0.f, 0.f, 0.f, 0.f);
        g_area[i] = 1.f;
    }
}

// ---------------- NMS mask (replicates reference's yy2 = max bug) ----------------
__global__ __launch_bounds__(64) void nms_mask_kernel() {
    int gi = blockIdx.y, gj = blockIdx.x;
    if (gj < gi) return;   // only upper triangle (incl diagonal) is consulted
    __shared__ float4 cbx[64];
    __shared__ float  car[64];
    int t = threadIdx.x;
    int j0 = gj * 64;
    cbx[t] = g_sbox[j0 + t];
    car[t] = g_area[j0 + t];
    __syncthreads();
    int i = gi * 64 + t;
    float4 bi = g_sbox[i];
    float  ai = g_area[i];
    unsigned long long word = 0;
#pragma unroll 8
    for (int jj = 0; jj < 64; jj++) {
        float4 bj = cbx[jj];
        float xx1 = fmaxf(bi.x, bj.x);
        float yy1 = fmaxf(bi.y, bj.y);
        float xx2 = fminf(bi.z, bj.z);
        float yy2 = fmaxf(bi.w, bj.w);   // reference bug: maximum, not minimum
        float w = fmaxf(0.f, xx2 - xx1 + 1.f);
        float h = fmaxf(0.f, yy2 - yy1 + 1.f);
        float inter = w * h;
        float ov = inter / (ai + car[jj] - inter);
        word |= ((unsigned long long)(ov > 0.7f)) << jj;
    }
    g_mask[(size_t)i * NW + gj] = word;
}

// ---------------- greedy NMS scan (exact equivalent of reference fori_loop) ----------------
__global__ __launch_bounds__(128) void nms_scan_kernel() {
    __shared__ unsigned long long remv[NW];
    __shared__ unsigned long long ms[64];
    __shared__ unsigned long long s_kept;
    int t = threadIdx.x;
    if (t < NW) remv[t] = 0ull;
    __syncthreads();
    for (int cb = 0; cb < NW; cb++) {
        if (t < 64) ms[t] = g_mask[(size_t)(cb * 64 + t) * NW + cb];
        __syncthreads();
        if (t == 0) {
            unsigned long long v = remv[cb], kept = 0ull;
#pragma unroll
            for (int j = 0; j < 64; j++) {
                if (!((v >> j) & 1ull) && (cb * 64 + j) < PRE) {
                    kept |= 1ull << j;
                    v |= ms[j];
                }
            }
            s_kept = kept;
            g_keep[cb] = kept;
        }
        __syncthreads();
        unsigned long long kept = s_kept;
        for (int g = cb + 1 + t; g < NW; g += blockDim.x) {
            unsigned long long a = remv[g];
            unsigned long long kk = kept;
            while (kk) {
                int j = __ffsll(kk) - 1;
                kk &= kk - 1;
                a |= g_mask[(size_t)(cb * 64 + j) * NW + g];
            }
            remv[g] = a;
        }
        __syncthreads();
    }
}

// ---------------- emit top-300 (kept in order, then non-kept by index) ----------------
__global__ __launch_bounds__(256) void output_kernel(float* __restrict__ out) {
    __shared__ int cnts[256];
    __shared__ int offs[256];
    __shared__ int Ktot;
    int t = threadIdx.x;
    int lo = t * 24;
    int hi = lo + 24; if (hi > PRE) hi = PRE;
    int c = 0;
    for (int i = lo; i < hi; i++)
        c += (int)((g_keep[i >> 6] >> (i & 63)) & 1ull);
    cnts[t] = c;
    __syncthreads();
    if (t == 0) {
        int r = 0;
        for (int q = 0; q < 256; q++) { offs[q] = r; r += cnts[q]; }
        Ktot = r;
    }
    __syncthreads();
    int K = Ktot;
    int pk = offs[t];
    for (int i = lo; i < hi; i++) {
        bool kept = (g_keep[i >> 6] >> (i & 63)) & 1ull;
        int pos = kept ? pk : (K + (i - pk));
        if (kept) pk++;
        if (pos < POST) {
            float4 b = g_sbox[i];
            out[pos * 4 + 0] = b.x;
            out[pos * 4 + 1] = b.y;
            out[pos * 4 + 2] = b.z - b.x + 1.f;
            out[pos * 4 + 3] = b.w - b.y + 1.f;
        }
    }
}

// ---------------- launch ----------------
extern "C" void kernel_launch(void* const* d_in, const int* in_sizes, int n_in,
                              void* d_out, int out_size) {
    const float* in_features = (const float*)d_in[0];
    const float* conv_w = (const float*)d_in[1];
    const float* conv_b = (const float*)d_in[2];
    const float* reg_w  = (const float*)d_in[3];
    const float* reg_b  = (const float*)d_in[4];
    const float* cls_w  = (const float*)d_in[5];
    const float* cls_b  = (const float*)d_in[6];
    float* out = (float*)d_out;

    // only batch index 7 feeds the output
    const float* in7 = in_features + (size_t)7 * ICC * NPIX;

    setup_kernel<<<SORTN / 256, 256>>>();
    conv3_kernel<<<dim3(40, 8), 64>>>(in7, conv_w, conv_b);
    heads_kernel<<<20, 128>>>(reg_w, reg_b, cls_w, cls_b);

    bitonic_shared<<<16, 1024>>>(2048);
    for (int k = 4096; k <= SORTN; k <<= 1) {
        for (int j = k >> 1; j >= 2048; j >>= 1)
            bitonic_global<<<SORTN / 1024, 1024>>>(k, j);
        bitonic_shared<<<16, 1024>>>(k);
    }

    gather_kernel<<<(ROWS + 127) / 128, 128>>>();
    nms_mask_kernel<<<dim3(NW, NW), 64>>>();
    nms_scan_kernel<<<1, 128>>>();
    output_kernel<<<1, 256>>>(out);
}

// round 4
// speedup vs baseline: 1.5701x; 1.0318x over previous
#include <cuda_runtime.h>
#include <cstdint>

#define FSZ   50
#define NPIX  2500
#define OC    512
#define ICC   512
#define KTOT  4608      // 512*9
#define NANCH 22500     // 2500*9
#define SORTN 32768
#define PRE   6000
#define NW    94        // ceil(6000/64) -> 94 words, 6016 bits
#define ROWS  6016
#define POST  300

// ---------------- scratch (static device allocations; no cudaMalloc) ----------------
__device__ float               g_feat[OC * NPIX];          // conv output (batch 7)
__device__ float4              g_boxes[NANCH];             // decoded boxes x1,y1,x2,y2
__device__ unsigned long long  g_keys[SORTN];              // sort keys
__device__ float4              g_sbox[ROWS];               // top-6000 boxes (padded)
__device__ float               g_area[ROWS];
__device__ unsigned long long  g_mask[(size_t)ROWS * NW];  // IoU suppression bitmask
__device__ unsigned long long  g_keep[NW];
__device__ int4                g_decode[KTOT];             // (c*2500, ky-1, kx-1, 0)

// packed fp32x2 FMA (sm_103a FFMA2 — only reachable via PTX)
#define FMA2(c, a, b) asm("fma.rn.f32x2 %0, %1, %2, %3;" : "=l"(c) : "l"(a), "l"(b), "l"(c))

__device__ __forceinline__ unsigned long long dup2(float x) {
    unsigned long long d;
    asm("mov.b64 %0, {%1, %1};" : "=l"(d) : "f"(x));
    return d;
}

// ---------------- setup: decode table + key padding ----------------
__global__ void setup_kernel() {
    int i = blockIdx.x * blockDim.x + threadIdx.x;
    if (i < KTOT) {
        int c = i / 9, r = i - 9 * c;
        int ky = r / 3, kx = r - 3 * ky;
        g_decode[i] = make_int4(c * NPIX, ky - 1, kx - 1, 0);
    }
    if (i >= NANCH && i < SORTN) g_keys[i] = ~0ull;
}

// ---------------- conv 3x3 (batch 7 only) + leaky relu ----------------
// implicit GEMM: M=512 (oc), N=2500 (pix), K=4608. BM=BN=64, BK=32, 64 threads.
// FFMA2 micro-tile: 8 oc x 4 pixel-pairs per thread. Weights stored duplicated
// in shared so the broadcast operand is pre-packed (no per-k dup MOVs).
#define BK 32
__global__ __launch_bounds__(64) void conv3_kernel(const float* __restrict__ in,
                                                   const float* __restrict__ w,
                                                   const float* __restrict__ bias) {
    __shared__ unsigned long long As2[BK][66];  // dup weight pairs [k][oc], 16B-aligned rows
    __shared__ float              Bs[BK][68];   // input patches [k][pix]
    int t   = threadIdx.x;
    int p0  = blockIdx.x * 64;     // pixel tile (40 tiles)
    int oc0 = blockIdx.y * 64;     // oc tile (8 tiles)
    int pix = p0 + t;
    int py  = pix / FSZ;
    int px  = pix - py * FSZ;
    bool pv = pix < NPIX;
    int ty = t >> 3, tx = t & 7;

    unsigned long long acc[8][4];
#pragma unroll
    for (int i = 0; i < 8; i++)
#pragma unroll
        for (int j = 0; j < 4; j++) acc[i][j] = 0ull;

    for (int k0 = 0; k0 < KTOT; k0 += BK) {
        // A tile: weights [32 k][64 oc], each value duplicated into a 64-bit pair
#pragma unroll
        for (int j = 0; j < 8; j++) {
            int m  = j * 8 + ty;
            int kk = tx * 4;
            float4 v = *reinterpret_cast<const float4*>(&w[(size_t)(oc0 + m) * KTOT + k0 + kk]);
            As2[kk + 0][m] = dup2(v.x); As2[kk + 1][m] = dup2(v.y);
            As2[kk + 2][m] = dup2(v.z); As2[kk + 3][m] = dup2(v.w);
        }
        // B tile: input patches [32 k][64 pix]
#pragma unroll 8
        for (int j = 0; j < BK; j++) {
            int4 d = g_decode[k0 + j];
            int iy = py + d.y, ix = px + d.z;
            float v = 0.f;
            if (pv && iy >= 0 && iy < FSZ && ix >= 0 && ix < FSZ)
                v = in[d.x + iy * FSZ + ix];
            Bs[j][t] = v;
        }
        __syncthreads();
#pragma unroll
        for (int kk = 0; kk < BK; kk++) {
            unsigned long long a2[8], b2[4];
            *(ulonglong2*)&a2[0] = *(const ulonglong2*)&As2[kk][ty * 8 + 0];
            *(ulonglong2*)&a2[2] = *(const ulonglong2*)&As2[kk][ty * 8 + 2];
            *(ulonglong2*)&a2[4] = *(const ulonglong2*)&As2[kk][ty * 8 + 4];
            *(ulonglong2*)&a2[6] = *(const ulonglong2*)&As2[kk][ty * 8 + 6];
            *(ulonglong2*)&b2[0] = *(const ulonglong2*)(const void*)&Bs[kk][tx * 8 + 0];
            *(ulonglong2*)&b2[2] = *(const ulonglong2*)(const void*)&Bs[kk][tx * 8 + 4];
#pragma unroll
            for (int i = 0; i < 8; i++)
#pragma unroll
                for (int j = 0; j < 4; j++)
                    FMA2(acc[i][j], a2[i], b2[j]);
        }
        __syncthreads();
    }
#pragma unroll
    for (int i = 0; i < 8; i++) {
        int oc = oc0 + ty * 8 + i;
        float bv = bias[oc];
#pragma unroll
        for (int j = 0; j < 4; j++) {
            int p = p0 + tx * 8 + 2 * j;
            if (p < NPIX) {   // NPIX even -> pair-granular validity
                float lo, hi;
                asm("mov.b64 {%0, %1}, %2;" : "=f"(lo), "=f"(hi) : "l"(acc[i][j]));
                lo += bv; hi += bv;
                lo = (lo >= 0.f) ? lo : 0.01f * lo;
                hi = (hi >= 0.f) ? hi : 0.01f * hi;
                *(float2*)&g_feat[(size_t)oc * NPIX + p] = make_float2(lo, hi);
            }
        }
    }
}

// ---------------- heads: 1x1 convs + softmax + anchor decode + keys ----------------
__global__ __launch_bounds__(128) void heads_kernel(const float* __restrict__ reg_w,
                                                    const float* __restrict__ reg_b,
                                                    const float* __restrict__ cls_w,
                                                    const float* __restrict__ cls_b) {
    __shared__ float wsm[128][56];  // [c][o] chunk, o: 0..35 reg, 36..53 cls
    int t = threadIdx.x;
    int p = blockIdx.x * 128 + t;
    float acc[54];
#pragma unroll
    for (int o = 0; o < 54; o++) acc[o] = 0.f;

    for (int c0 = 0; c0 < 512; c0 += 128) {
        for (int i = t; i < 54 * 128; i += 128) {
            int o = i / 128, c = i - o * 128;
            float v = (o < 36) ? reg_w[o * 512 + c0 + c] : cls_w[(o - 36) * 512 + c0 + c];
            wsm[c][o] = v;
        }
        __syncthreads();
        if (p < NPIX) {
            for (int c = 0; c < 128; c++) {
                float f = g_feat[(size_t)(c0 + c) * NPIX + p];
#pragma unroll
                for (int o = 0; o < 54; o++) acc[o] += f * wsm[c][o];
            }
        }
        __syncthreads();
    }
    if (p >= NPIX) return;

#pragma unroll
    for (int o = 0; o < 36; o++) acc[o] += reg_b[o];
#pragma unroll
    for (int o = 0; o < 18; o++) acc[36 + o] += cls_b[o];

    int pq = p / FSZ, pr = p - pq * FSZ;
    float cxv = 16.f * (float)pq + 8.f;
    float cyv = 16.f * (float)pr + 8.f;
    const float ssv[3]  = {8.f, 16.f, 32.f};
    const float sqr[3]  = {0.70710678f, 1.0f, 1.41421356f};   // sqrt(rs)
    const float sqi[3]  = {1.41421356f, 1.0f, 0.70710678f};   // sqrt(1/rs)
    const float NEGINF = __int_as_float(0xff800000);

#pragma unroll
    for (int k = 0; k < 9; k++) {
        float pr0 = acc[k * 4 + 0], pr1 = acc[k * 4 + 1];
        float pr2 = acc[k * 4 + 2], pr3 = acc[k * 4 + 3];
        float l0 = acc[36 + k * 2], l1 = acc[36 + k * 2 + 1];
        float m  = fmaxf(l0, l1);
        float e0 = expf(l0 - m), e1 = expf(l1 - m);
        float sc = e1 / (e0 + e1);

        int ri = k / 3, si = k - 3 * ri;
        float hk = (16.f * ssv[si]) * sqr[ri];
        float wk = (16.f * ssv[si]) * sqi[ri];
        float ax1 = cxv - wk * 0.5f;
        float ay1 = cyv - hk * 0.5f;
        const float hi = 799.f;
        float rx1 = fminf(fmaxf(pr0 + ax1, 0.f), hi);
        float ry1 = fminf(fmaxf(pr1 + ay1, 0.f), hi);
        float rx2 = fminf(fmaxf(((pr0 + ax1) + pr2) + wk, 0.f), hi);
        float ry2 = fminf(fmaxf(((pr1 + ay1) + pr3) + hk, 0.f), hi);
        float wv = pr2 + wk, hv = pr3 + hk;
        bool valid = (wv >= 16.f) && (hv >= 16.f);
        float s = valid ? sc : NEGINF;

        int a = p * 9 + k;
        g_boxes[a] = make_float4(rx1, ry1, rx2, ry2);
        unsigned u = __float_as_uint(s);
        u = (u >> 31) ? ~u : (u | 0x80000000u);
        g_keys[a] = ((unsigned long long)(~u) << 32) | (unsigned)a;
    }
}

// ---------------- bitonic sort (u64 keys, n=32768) ----------------
__global__ void bitonic_global(int k, int j) {
    int i = blockIdx.x * blockDim.x + threadIdx.x;
    int l = i ^ j;
    if (l > i) {
        unsigned long long a = g_keys[i], b = g_keys[l];
        bool asc = ((i & k) == 0);
        if (asc ? (a > b) : (a < b)) { g_keys[i] = b; g_keys[l] = a; }
    }
}

// 4096 elements per block (4 per thread, 32KB smem)
__global__ __launch_bounds__(1024) void bitonic_shared4(int kout) {
    __shared__ unsigned long long s[4096];
    int t = threadIdx.x;
    int base = blockIdx.x * 4096;
#pragma unroll
    for (int q = 0; q < 4; q++) s[t + q * 1024] = g_keys[base + t + q * 1024];
    __syncthreads();

    if (kout == 4096) {
        for (int k = 2; k <= 4096; k <<= 1) {
            for (int j = k >> 1; j > 0; j >>= 1) {
#pragma unroll
                for (int q = 0; q < 2; q++) {
                    int p = t + q * 1024;
                    int low = p & (j - 1);
                    int i1 = ((p - low) << 1) + low;
                    int i2 = i1 + j;
                    bool asc = (((base + i1) & k) == 0);
                    unsigned long long a = s[i1], b = s[i2];
                    if (asc ? (a > b) : (a < b)) { s[i1] = b; s[i2] = a; }
                }
                __syncthreads();
            }
        }
    } else {
        int k = kout;
        for (int j = 2048; j > 0; j >>= 1) {
#pragma unroll
            for (int q = 0; q < 2; q++) {
                int p = t + q * 1024;
                int low = p & (j - 1);
                int i1 = ((p - low) << 1) + low;
                int i2 = i1 + j;
                bool asc = (((base + i1) & k) == 0);
                unsigned long long a = s[i1], b = s[i2];
                if (asc ? (a > b) : (a < b)) { s[i1] = b; s[i2] = a; }
            }
            __syncthreads();
        }
    }
#pragma unroll
    for (int q = 0; q < 4; q++) g_keys[base + t + q * 1024] = s[t + q * 1024];
}

// ---------------- gather top-6000 ----------------
__global__ void gather_kernel() {
    int i = blockIdx.x * blockDim.x + threadIdx.x;
    if (i >= ROWS) return;
    if (i < PRE) {
        unsigned idx = (unsigned)(g_keys[i] & 0xFFFFFFFFull);
        float4 b = g_boxes[idx];
        g_sbox[i] = b;
        g_area[i] = (b.z - b.x + 1.f) * (b.w - b.y + 1.f);
    } else {
        g_sbox[i] = make_float4(0.f, 0.f, 0.f, 0.f);
        g_area[i] = 1.f;
    }
}

// ---------------- NMS mask (replicates reference's yy2 = max bug) ----------------
__global__ __launch_bounds__(64) void nms_mask_kernel() {
    int gi = blockIdx.y, gj = blockIdx.x;
    if (gj < gi) return;   // only upper triangle (incl diagonal) is consulted
    __shared__ float4 cbx[64];
    __shared__ float  car[64];
    int t = threadIdx.x;
    int j0 = gj * 64;
    cbx[t] = g_sbox[j0 + t];
    car[t] = g_area[j0 + t];
    __syncthreads();
    int i = gi * 64 + t;
    float4 bi = g_sbox[i];
    float  ai = g_area[i];
    unsigned long long word = 0;
#pragma unroll 8
    for (int jj = 0; jj < 64; jj++) {
        float4 bj = cbx[jj];
        float xx1 = fmaxf(bi.x, bj.x);
        float yy1 = fmaxf(bi.y, bj.y);
        float xx2 = fminf(bi.z, bj.z);
        float yy2 = fmaxf(bi.w, bj.w);   // reference bug: maximum, not minimum
        float w = fmaxf(0.f, xx2 - xx1 + 1.f);
        float h = fmaxf(0.f, yy2 - yy1 + 1.f);
        float inter = w * h;
        float ov = inter / (ai + car[jj] - inter);
        word |= ((unsigned long long)(ov > 0.7f)) << jj;
    }
    g_mask[(size_t)i * NW + gj] = word;
}

// ---------------- greedy NMS scan (exact equivalent of reference fori_loop) ----------------
__global__ __launch_bounds__(128) void nms_scan_kernel() {
    __shared__ unsigned long long remv[NW];
    __shared__ unsigned long long ms[64];
    __shared__ unsigned long long s_kept;
    int t = threadIdx.x;
    if (t < NW) remv[t] = 0ull;
    __syncthreads();
    for (int cb = 0; cb < NW; cb++) {
        if (t < 64) ms[t] = g_mask[(size_t)(cb * 64 + t) * NW + cb];
        __syncthreads();
        if (t == 0) {
            unsigned long long v = remv[cb], kept = 0ull;
#pragma unroll
            for (int j = 0; j < 64; j++) {
                if (!((v >> j) & 1ull) && (cb * 64 + j) < PRE) {
                    kept |= 1ull << j;
                    v |= ms[j];
                }
            }
            s_kept = kept;
            g_keep[cb] = kept;
        }
        __syncthreads();
        unsigned long long kept = s_kept;
        for (int g = cb + 1 + t; g < NW; g += blockDim.x) {
            unsigned long long a = remv[g];
            unsigned long long kk = kept;
            while (kk) {
                int j = __ffsll(kk) - 1;
                kk &= kk - 1;
                a |= g_mask[(size_t)(cb * 64 + j) * NW + g];
            }
            remv[g] = a;
        }
        __syncthreads();
    }
}

// ---------------- emit top-300 (kept in order, then non-kept by index) ----------------
__global__ __launch_bounds__(256) void output_kernel(float* __restrict__ out) {
    __shared__ int cnts[256];
    __shared__ int offs[256];
    __shared__ int Ktot;
    int t = threadIdx.x;
    int lo = t * 24;
    int hi = lo + 24; if (hi > PRE) hi = PRE;
    int c = 0;
    for (int i = lo; i < hi; i++)
        c += (int)((g_keep[i >> 6] >> (i & 63)) & 1ull);
    cnts[t] = c;
    __syncthreads();
    if (t == 0) {
        int r = 0;
        for (int q = 0; q < 256; q++) { offs[q] = r; r += cnts[q]; }
        Ktot = r;
    }
    __syncthreads();
    int K = Ktot;
    int pk = offs[t];
    for (int i = lo; i < hi; i++) {
        bool kept = (g_keep[i >> 6] >> (i & 63)) & 1ull;
        int pos = kept ? pk : (K + (i - pk));
        if (kept) pk++;
        if (pos < POST) {
            float4 b = g_sbox[i];
            out[pos * 4 + 0] = b.x;
            out[pos * 4 + 1] = b.y;
            out[pos * 4 + 2] = b.z - b.x + 1.f;
            out[pos * 4 + 3] = b.w - b.y + 1.f;
        }
    }
}

// ---------------- launch ----------------
extern "C" void kernel_launch(void* const* d_in, const int* in_sizes, int n_in,
                              void* d_out, int out_size) {
    const float* in_features = (const float*)d_in[0];
    const float* conv_w = (const float*)d_in[1];
    const float* conv_b = (const float*)d_in[2];
    const float* reg_w  = (const float*)d_in[3];
    const float* reg_b  = (const float*)d_in[4];
    const float* cls_w  = (const float*)d_in[5];
    const float* cls_b  = (const float*)d_in[6];
    float* out = (float*)d_out;

    // only batch index 7 feeds the output
    const float* in7 = in_features + (size_t)7 * ICC * NPIX;

    setup_kernel<<<SORTN / 256, 256>>>();
    conv3_kernel<<<dim3(40, 8), 64>>>(in7, conv_w, conv_b);
    heads_kernel<<<20, 128>>>(reg_w, reg_b, cls_w, cls_b);

    bitonic_shared4<<<8, 1024>>>(4096);
    for (int k = 8192; k <= SORTN; k <<= 1) {
        for (int j = k >> 1; j >= 4096; j >>= 1)
            bitonic_global<<<SORTN / 1024, 1024>>>(k, j);
        bitonic_shared4<<<8, 1024>>>(k);
    }

    gather_kernel<<<(ROWS + 127) / 128, 128>>>();
    nms_mask_kernel<<<dim3(NW, NW), 64>>>();
    nms_scan_kernel<<<1, 128>>>();
    output_kernel<<<1, 256>>>(out);
}

// round 5
// speedup vs baseline: 1.8131x; 1.1547x over previous
#include <cuda_runtime.h>
#include <cstdint>

#define FSZ   50
#define NPIX  2500
#define OC    512
#define ICC   512
#define KTOT  4608      // 512*9
#define NANCH 22500     // 2500*9
#define NPAD  22528     // rank padding
#define PRE   6000
#define NW    94        // ceil(6000/64)
#define ROWS  6016
#define POST  300

// ---------------- scratch (static device allocations) ----------------
__device__ float               g_feat[OC * NPIX];
__device__ float4              g_boxes[NANCH];
__device__ unsigned            g_score[NANCH];            // monotonic u32 scores
__device__ unsigned            g_rankpart[4][NPAD];       // partial rank counts
__device__ float4              g_sbox[ROWS];
__device__ float               g_area[ROWS];
__device__ unsigned long long  g_mask[(size_t)ROWS * NW];
__device__ unsigned long long  g_keep[NW];
__device__ int4                g_decode[KTOT];            // (c*2500, ky-1, kx-1, 0)

// packed fp32x2 FMA (sm_103a FFMA2 — only reachable via PTX)
#define FMA2(c, a, b) asm("fma.rn.f32x2 %0, %1, %2, %3;" : "=l"(c) : "l"(a), "l"(b), "l"(c))

__device__ __forceinline__ unsigned long long dup2(float x) {
    unsigned long long d;
    asm("mov.b64 %0, {%1, %1};" : "=l"(d) : "f"(x));
    return d;
}

// ---------------- setup: decode table + pad rows ----------------
__global__ void setup_kernel() {
    int i = blockIdx.x * blockDim.x + threadIdx.x;
    if (i < KTOT) {
        int c = i / 9, r = i - 9 * c;
        int ky = r / 3, kx = r - 3 * ky;
        g_decode[i] = make_int4(c * NPIX, ky - 1, kx - 1, 0);
    }
    if (i < ROWS - PRE) {
        g_sbox[PRE + i] = make_float4(0.f, 0.f, 0.f, 0.f);
        g_area[PRE + i] = 1.f;
    }
}

// ---------------- conv 3x3 (batch 7 only) + leaky relu ----------------
// implicit GEMM: M=512 oc, N=2500 pix, K=4608. Block tile 128oc x 80pix, BK=16,
// 128 threads (4 warps -> 1/SMSP), grid 32x4 = 128 blocks = single wave.
// FFMA2 micro-tile: 8 oc x 5 pixel-pairs. Conflict-free padded smem layouts.
// Global loads software-pipelined into registers (next chunk during compute).
#define CBK 16
__global__ __launch_bounds__(128) void conv3_kernel(const float* __restrict__ in,
                                                    const float* __restrict__ w,
                                                    const float* __restrict__ bias) {
    __shared__ unsigned long long As2[CBK][160];     // dup weight pairs, f(m)=m+2*(m>>3)
    __shared__ __align__(16) float Bs[CBK][96];      // pixels, 8 groups * 48B stride
    int t   = threadIdx.x;
    int p0  = blockIdx.x * 80;
    int oc0 = blockIdx.y * 128;
    int ty = t >> 3, tx = t & 7;

    // B staging coords: 16 rows x 80 pix = 1280 values, 10 per thread
    int jv[10], slotv[10], pyv[10], pxv[10];
    bool pvv[10];
#pragma unroll
    for (int s = 0; s < 10; s++) {
        int l = t + 128 * s;
        int j = l / 80, c = l - 80 * j;
        int pix = p0 + c;
        int py = pix / 50, px = pix - 50 * py;
        int pp = c >> 1, g = pp / 5, q = pp - 5 * g;
        jv[s] = j; slotv[s] = g * 12 + q * 2 + (c & 1);
        pyv[s] = py; pxv[s] = px; pvv[s] = (pix < NPIX);
    }
    int fm = t + 2 * (t >> 3);   // A store slot

    float4 wa[4]; float bvv[10];
    // prefetch chunk 0
    {
        const float* wp = &w[(size_t)(oc0 + t) * KTOT];
#pragma unroll
        for (int q = 0; q < 4; q++) wa[q] = *(const float4*)(wp + q * 4);
#pragma unroll
        for (int s = 0; s < 10; s++) {
            int4 d = g_decode[jv[s]];
            int iy = pyv[s] + d.y, ix = pxv[s] + d.z;
            float v = 0.f;
            if (pvv[s] && iy >= 0 && iy < FSZ && ix >= 0 && ix < FSZ)
                v = in[d.x + iy * FSZ + ix];
            bvv[s] = v;
        }
    }

    unsigned long long acc[8][5];
#pragma unroll
    for (int i = 0; i < 8; i++)
#pragma unroll
        for (int j = 0; j < 5; j++) acc[i][j] = 0ull;

    for (int k0 = 0; k0 < KTOT; k0 += CBK) {
        // commit staged registers to shared
#pragma unroll
        for (int q = 0; q < 4; q++) {
            As2[q * 4 + 0][fm] = dup2(wa[q].x);
            As2[q * 4 + 1][fm] = dup2(wa[q].y);
            As2[q * 4 + 2][fm] = dup2(wa[q].z);
            As2[q * 4 + 3][fm] = dup2(wa[q].w);
        }
#pragma unroll
        for (int s = 0; s < 10; s++) Bs[jv[s]][slotv[s]] = bvv[s];
        __syncthreads();

        int kn = k0 + CBK;
        if (kn < KTOT) {
            const float* wp = &w[(size_t)(oc0 + t) * KTOT + kn];
#pragma unroll
            for (int q = 0; q < 4; q++) wa[q] = *(const float4*)(wp + q * 4);
#pragma unroll
            for (int s = 0; s < 10; s++) {
                int4 d = g_decode[kn + jv[s]];
                int iy = pyv[s] + d.y, ix = pxv[s] + d.z;
                float v = 0.f;
                if (pvv[s] && iy >= 0 && iy < FSZ && ix >= 0 && ix < FSZ)
                    v = in[d.x + iy * FSZ + ix];
                bvv[s] = v;
            }
        }

#pragma unroll
        for (int kk = 0; kk < CBK; kk++) {
            unsigned long long a2[8], b2[5];
            *(ulonglong2*)&a2[0] = *(const ulonglong2*)&As2[kk][10 * ty + 0];
            *(ulonglong2*)&a2[2] = *(const ulonglong2*)&As2[kk][10 * ty + 2];
            *(ulonglong2*)&a2[4] = *(const ulonglong2*)&As2[kk][10 * ty + 4];
            *(ulonglong2*)&a2[6] = *(const ulonglong2*)&As2[kk][10 * ty + 6];
            const unsigned long long* bp =
                (const unsigned long long*)&Bs[kk][tx * 12];
            *(ulonglong2*)&b2[0] = *(const ulonglong2*)(bp);
            *(ulonglong2*)&b2[2] = *(const ulonglong2*)(bp + 2);
            b2[4] = bp[4];
#pragma unroll
            for (int i = 0; i < 8; i++)
#pragma unroll
                for (int j = 0; j < 5; j++)
                    FMA2(acc[i][j], a2[i], b2[j]);
        }
        __syncthreads();
    }
    // epilogue
#pragma unroll
    for (int i = 0; i < 8; i++) {
        int oc = oc0 + ty * 8 + i;
        float bv = bias[oc];
#pragma unroll
        for (int j = 0; j < 5; j++) {
            int p = p0 + tx * 10 + 2 * j;
            if (p < NPIX) {   // NPIX even -> pair-granular validity
                float lo, hi;
                asm("mov.b64 {%0, %1}, %2;" : "=f"(lo), "=f"(hi) : "l"(acc[i][j]));
                lo += bv; hi += bv;
                lo = (lo >= 0.f) ? lo : 0.01f * lo;
                hi = (hi >= 0.f) ? hi : 0.01f * hi;
                *(float2*)&g_feat[(size_t)oc * NPIX + p] = make_float2(lo, hi);
            }
        }
    }
}

// ---------------- heads: 1x1 convs + softmax + anchor decode + scores ----------------
__global__ __launch_bounds__(128) void heads_kernel(const float* __restrict__ reg_w,
                                                    const float* __restrict__ reg_b,
                                                    const float* __restrict__ cls_w,
                                                    const float* __restrict__ cls_b) {
    __shared__ float wsm[128][56];
    int t = threadIdx.x;
    int p = blockIdx.x * 128 + t;
    float acc[54];
#pragma unroll
    for (int o = 0; o < 54; o++) acc[o] = 0.f;

    for (int c0 = 0; c0 < 512; c0 += 128) {
        for (int i = t; i < 54 * 128; i += 128) {
            int o = i / 128, c = i - o * 128;
            float v = (o < 36) ? reg_w[o * 512 + c0 + c] : cls_w[(o - 36) * 512 + c0 + c];
            wsm[c][o] = v;
        }
        __syncthreads();
        if (p < NPIX) {
            for (int c = 0; c < 128; c++) {
                float f = g_feat[(size_t)(c0 + c) * NPIX + p];
#pragma unroll
                for (int o = 0; o < 54; o++) acc[o] += f * wsm[c][o];
            }
        }
        __syncthreads();
    }
    if (p >= NPIX) return;

#pragma unroll
    for (int o = 0; o < 36; o++) acc[o] += reg_b[o];
#pragma unroll
    for (int o = 0; o < 18; o++) acc[36 + o] += cls_b[o];

    int pq = p / FSZ, pr = p - pq * FSZ;
    float cxv = 16.f * (float)pq + 8.f;
    float cyv = 16.f * (float)pr + 8.f;
    const float ssv[3]  = {8.f, 16.f, 32.f};
    const float sqr[3]  = {0.70710678f, 1.0f, 1.41421356f};
    const float sqi[3]  = {1.41421356f, 1.0f, 0.70710678f};
    const float NEGINF = __int_as_float(0xff800000);

#pragma unroll
    for (int k = 0; k < 9; k++) {
        float pr0 = acc[k * 4 + 0], pr1 = acc[k * 4 + 1];
        float pr2 = acc[k * 4 + 2], pr3 = acc[k * 4 + 3];
        float l0 = acc[36 + k * 2], l1 = acc[36 + k * 2 + 1];
        float m  = fmaxf(l0, l1);
        float e0 = expf(l0 - m), e1 = expf(l1 - m);
        float sc = e1 / (e0 + e1);

        int ri = k / 3, si = k - 3 * ri;
        float hk = (16.f * ssv[si]) * sqr[ri];
        float wk = (16.f * ssv[si]) * sqi[ri];
        float ax1 = cxv - wk * 0.5f;
        float ay1 = cyv - hk * 0.5f;
        const float hi = 799.f;
        float rx1 = fminf(fmaxf(pr0 + ax1, 0.f), hi);
        float ry1 = fminf(fmaxf(pr1 + ay1, 0.f), hi);
        float rx2 = fminf(fmaxf(((pr0 + ax1) + pr2) + wk, 0.f), hi);
        float ry2 = fminf(fmaxf(((pr1 + ay1) + pr3) + hk, 0.f), hi);
        float wv = pr2 + wk, hv = pr3 + hk;
        bool valid = (wv >= 16.f) && (hv >= 16.f);
        float s = valid ? sc : NEGINF;

        int a = p * 9 + k;
        g_boxes[a] = make_float4(rx1, ry1, rx2, ry2);
        unsigned u = __float_as_uint(s);
        u = (u >> 31) ? ~u : (u | 0x80000000u);
        g_score[a] = u;   // monotonic: larger u <=> larger score
    }
}

// ---------------- rank by counting (replaces sort+gather) ----------------
// rank_i = #{j<i: s_j >= s_i} + #{j>i: s_j > s_i}  == stable argsort(-s) position.
// grid (88 i-blocks, 4 j-chunks); each thread owns 2 consecutive i.
__global__ __launch_bounds__(128) void rank_count_kernel() {
    __shared__ unsigned sk[2048];
    int t = threadIdx.x;
    int bi = blockIdx.x, jc = blockIdx.y;
    int i0 = (bi * 128 + t) * 2;
    unsigned my0 = (i0     < NANCH) ? g_score[i0]     : 0u;
    unsigned my1 = (i0 + 1 < NANCH) ? g_score[i0 + 1] : 0u;
    int c0 = 0, c1 = 0;
    int tt0 = jc * 3;
    int tt1 = tt0 + 3; if (tt1 > 11) tt1 = 11;
    for (int tt = tt0; tt < tt1; tt++) {
        int base = tt * 2048;
#pragma unroll
        for (int q = 0; q < 16; q++) {
            int idx = base + q * 128 + t;
            sk[q * 128 + t] = (idx < NANCH) ? g_score[idx] : 0u;
        }
        __syncthreads();
        if (base + 2048 <= i0) {           // all j < i0 <= i1
#pragma unroll 8
            for (int jj = 0; jj < 2048; jj++) {
                unsigned v = sk[jj];
                c0 += (v >= my0); c1 += (v >= my1);
            }
        } else if (base > i0 + 1) {        // all j > i1 >= i0
#pragma unroll 8
            for (int jj = 0; jj < 2048; jj++) {
                unsigned v = sk[jj];
                c0 += (v > my0); c1 += (v > my1);
            }
        } else {                           // straddling tile
            for (int jj = 0; jj < 2048; jj++) {
                unsigned v = sk[jj];
                int j = base + jj;
                c0 += (j < i0)  ? (int)(v >= my0) : (int)(v > my0);
                c1 += (j <= i0) ? (int)(v >= my1) : (int)(v > my1);
            }
        }
        __syncthreads();
    }
    g_rankpart[jc][i0]     = (unsigned)c0;
    g_rankpart[jc][i0 + 1] = (unsigned)c1;
}

__global__ void rank_scatter_kernel() {
    int i = blockIdx.x * 256 + threadIdx.x;
    if (i >= NANCH) return;
    unsigned r = g_rankpart[0][i] + g_rankpart[1][i] + g_rankpart[2][i] + g_rankpart[3][i];
    if (r < PRE) {
        float4 b = g_boxes[i];
        g_sbox[r] = b;
        g_area[r] = (b.z - b.x + 1.f) * (b.w - b.y + 1.f);
    }
}

// ---------------- NMS mask (replicates reference's yy2 = max bug) ----------------
__global__ __launch_bounds__(64) void nms_mask_kernel() {
    int gi = blockIdx.y, gj = blockIdx.x;
    if (gj < gi) return;
    __shared__ float4 cbx[64];
    __shared__ float  car[64];
    int t = threadIdx.x;
    int j0 = gj * 64;
    cbx[t] = g_sbox[j0 + t];
    car[t] = g_area[j0 + t];
    __syncthreads();
    int i = gi * 64 + t;
    float4 bi = g_sbox[i];
    float  ai = g_area[i];
    unsigned long long word = 0;
#pragma unroll 8
    for (int jj = 0; jj < 64; jj++) {
        float4 bj = cbx[jj];
        float xx1 = fmaxf(bi.x, bj.x);
        float yy1 = fmaxf(bi.y, bj.y);
        float xx2 = fminf(bi.z, bj.z);
        float yy2 = fmaxf(bi.w, bj.w);   // reference bug: maximum, not minimum
        float w = fmaxf(0.f, xx2 - xx1 + 1.f);
        float h = fmaxf(0.f, yy2 - yy1 + 1.f);
        float inter = w * h;
        float ov = inter / (ai + car[jj] - inter);
        word |= ((unsigned long long)(ov > 0.7f)) << jj;
    }
    g_mask[(size_t)i * NW + gj] = word;
}

// ---------------- greedy NMS scan (register remv, coalesced loads, diag prefetch) ----------------
__global__ __launch_bounds__(128) void nms_scan_kernel() {
    __shared__ unsigned long long ms[64];
    __shared__ unsigned long long s_remv, s_kept;
    int t = threadIdx.x;
    unsigned long long remv = 0;                       // thread t owns word g=t
    unsigned long long nextdiag = (t < 64) ? g_mask[(size_t)t * NW] : 0ull;
    for (int cb = 0; cb < NW; cb++) {
        if (t < 64) ms[t] = nextdiag;
        if (t == cb) s_remv = remv;
        __syncthreads();
        if (t < 64 && cb + 1 < NW)
            nextdiag = g_mask[(size_t)((cb + 1) * 64 + t) * NW + (cb + 1)];
        if (t == 0) {
            unsigned long long v = s_remv, kept = 0ull;
            int lim = PRE - cb * 64; if (lim > 64) lim = 64;
            for (int j = 0; j < lim; j++) {
                if (!((v >> j) & 1ull)) { kept |= 1ull << j; v |= ms[j]; }
            }
            s_kept = kept;
            g_keep[cb] = kept;
        }
        __syncthreads();
        if (t > cb && t < NW) {
            unsigned long long kk = s_kept;
            const unsigned long long* rowbase = g_mask + (size_t)cb * 64 * NW + t;
            while (kk) {
                int j0 = __ffsll((long long)kk) - 1; kk &= kk - 1;
                unsigned long long m0 = rowbase[(size_t)j0 * NW];
                unsigned long long m1 = 0, m2 = 0, m3 = 0;
                if (kk) { int j1 = __ffsll((long long)kk) - 1; kk &= kk - 1; m1 = rowbase[(size_t)j1 * NW]; }
                if (kk) { int j2 = __ffsll((long long)kk) - 1; kk &= kk - 1; m2 = rowbase[(size_t)j2 * NW]; }
                if (kk) { int j3 = __ffsll((long long)kk) - 1; kk &= kk - 1; m3 = rowbase[(size_t)j3 * NW]; }
                remv |= (m0 | m1) | (m2 | m3);
            }
        }
    }
}

// ---------------- emit top-300 (kept in order, then non-kept by index) ----------------
__global__ __launch_bounds__(256) void output_kernel(float* __restrict__ out) {
    __shared__ int cnts[256];
    __shared__ int offs[256];
    __shared__ int Ktot;
    int t = threadIdx.x;
    int lo = t * 24;
    int hi = lo + 24; if (hi > PRE) hi = PRE;
    int c = 0;
    for (int i = lo; i < hi; i++)
        c += (int)((g_keep[i >> 6] >> (i & 63)) & 1ull);
    cnts[t] = c;
    __syncthreads();
    if (t == 0) {
        int r = 0;
        for (int q = 0; q < 256; q++) { offs[q] = r; r += cnts[q]; }
        Ktot = r;
    }
    __syncthreads();
    int K = Ktot;
    int pk = offs[t];
    for (int i = lo; i < hi; i++) {
        bool kept = (g_keep[i >> 6] >> (i & 63)) & 1ull;
        int pos = kept ? pk : (K + (i - pk));
        if (kept) pk++;
        if (pos < POST) {
            float4 b = g_sbox[i];
            out[pos * 4 + 0] = b.x;
            out[pos * 4 + 1] = b.y;
            out[pos * 4 + 2] = b.z - b.x + 1.f;
            out[pos * 4 + 3] = b.w - b.y + 1.f;
        }
    }
}

// ---------------- launch ----------------
extern "C" void kernel_launch(void* const* d_in, const int* in_sizes, int n_in,
                              void* d_out, int out_size) {
    const float* in_features = (const float*)d_in[0];
    const float* conv_w = (const float*)d_in[1];
    const float* conv_b = (const float*)d_in[2];
    const float* reg_w  = (const float*)d_in[3];
    const float* reg_b  = (const float*)d_in[4];
    const float* cls_w  = (const float*)d_in[5];
    const float* cls_b  = (const float*)d_in[6];
    float* out = (float*)d_out;

    // only batch index 7 feeds the output
    const float* in7 = in_features + (size_t)7 * ICC * NPIX;

    setup_kernel<<<18, 256>>>();
    conv3_kernel<<<dim3(32, 4), 128>>>(in7, conv_w, conv_b);
    heads_kernel<<<20, 128>>>(reg_w, reg_b, cls_w, cls_b);

    rank_count_kernel<<<dim3(88, 4), 128>>>();
    rank_scatter_kernel<<<88, 256>>>();

    nms_mask_kernel<<<dim3(NW, NW), 64>>>();
    nms_scan_kernel<<<1, 128>>>();
    output_kernel<<<1, 256>>>(out);
}

// round 6
// speedup vs baseline: 2.1727x; 1.1984x over previous
#include <cuda_runtime.h>
#include <cstdint>

#define FSZ   50
#define NPIX  2500
#define OC    512
#define ICC   512
#define KTOT  4608      // 512*9
#define NANCH 22500     // 2500*9
#define NPAD  22528
#define PRE   6000
#define NW    94        // ceil(6000/64)
#define ROWS  6016
#define POST  300
#define NJT   11        // rank j-tiles of 2048

// ---------------- scratch (static device allocations) ----------------
__device__ float               g_feat[OC * NPIX];
__device__ float4              g_boxes[NANCH];
__device__ unsigned            g_score[NANCH];
__device__ unsigned            g_rankpart[NJT][NPAD];
__device__ float               g_hpart[4][54 * NPIX];
__device__ float4              g_sbox[ROWS];
__device__ float               g_area[ROWS];
__device__ unsigned long long  g_mask[(size_t)ROWS * NW];
__device__ unsigned long long  g_keep[NW];
__device__ int4                g_decode[KTOT];            // (c*2500, ky-1, kx-1, 0)

// packed fp32x2 ops (sm_103a — only reachable via PTX)
#define FMA2(c, a, b) asm("fma.rn.f32x2 %0, %1, %2, %3;" : "=l"(c) : "l"(a), "l"(b), "l"(c))
#define ADD2(c, a, b) asm("add.rn.f32x2 %0, %1, %2;" : "=l"(c) : "l"(a), "l"(b))

__device__ __forceinline__ unsigned long long dup2(float x) {
    unsigned long long d;
    asm("mov.b64 %0, {%1, %1};" : "=l"(d) : "f"(x));
    return d;
}

// ---------------- setup (split so conv lands at launch index 3) ----------------
__global__ void setup_decode_kernel() {
    int i = blockIdx.x * blockDim.x + threadIdx.x;
    if (i < KTOT) {
        int c = i / 9, r = i - 9 * c;
        int ky = r / 3, kx = r - 3 * ky;
        g_decode[i] = make_int4(c * NPIX, ky - 1, kx - 1, 0);
    }
}
__global__ void setup_pad_kernel() {
    int i = threadIdx.x;
    if (i < ROWS - PRE) {
        g_sbox[PRE + i] = make_float4(0.f, 0.f, 0.f, 0.f);
        g_area[PRE + i] = 1.f;
    }
}
__global__ void zerokeep_kernel() {
    int i = threadIdx.x;
    if (i < NW) g_keep[i] = 0ull;
}

// ---------------- conv 3x3 (batch 7 only) + leaky relu ----------------
// implicit GEMM 512x2500x4608. Block: 128oc x 80pix, 256 threads = 2 warps/SMSP.
// Warp-group split-K: wg0 even 16-k chunks, wg1 odd; halves combined in smem epilogue.
// FFMA2 micro-tile 8oc x 5 pixel-pairs; conflict-free padded layouts; global
// loads software-pipelined (next chunk staged to regs during compute).
#define CBK 16
union SmemConv {
    struct { float As[2][CBK][188]; float Bs[2][CBK][96]; } mm;
    unsigned long long epi[128][41];
};
__global__ __launch_bounds__(256) void conv3_kernel(const float* __restrict__ in,
                                                    const float* __restrict__ w,
                                                    const float* __restrict__ bias) {
    __shared__ SmemConv sm;
    int t   = threadIdx.x;
    int wg  = t >> 7;          // warp-group 0/1
    int wt  = t & 127;
    int p0  = blockIdx.x * 80;
    int oc0 = blockIdx.y * 128;
    int ty = wt >> 3, tx = wt & 7;

    float (*As_)[188] = sm.mm.As[wg];
    float (*Bs_)[96]  = sm.mm.Bs[wg];

    // staging coords: 16 rows x 80 pix = 1280 values, 10 per thread (per wg)
    int jv[10], slotv[10], pyv[10], pxv[10];
    bool pvv[10];
#pragma unroll
    for (int s = 0; s < 10; s++) {
        int l = wt + 128 * s;
        int j = l / 80, c = l - 80 * j;
        int pix = p0 + c;
        int py = pix / 50, px = pix - 50 * py;
        int pp = c >> 1, g = pp / 5, q = pp - 5 * g;
        jv[s] = j; slotv[s] = g * 12 + q * 2 + (c & 1);
        pyv[s] = py; pxv[s] = px; pvv[s] = (pix < NPIX);
    }
    int fm = wt + 4 * (wt >> 3);   // A store slot (16B-aligned read groups)

    int kstart = wg * CBK;
    float4 wa[4]; float bvv[10];
    {   // prefetch first chunk of this wg
        const float* wp = &w[(size_t)(oc0 + wt) * KTOT + kstart];
#pragma unroll
        for (int q = 0; q < 4; q++) wa[q] = *(const float4*)(wp + q * 4);
#pragma unroll
        for (int s = 0; s < 10; s++) {
            int4 d = g_decode[kstart + jv[s]];
            int iy = pyv[s] + d.y, ix = pxv[s] + d.z;
            float v = 0.f;
            if (pvv[s] && iy >= 0 && iy < FSZ && ix >= 0 && ix < FSZ)
                v = in[d.x + iy * FSZ + ix];
            bvv[s] = v;
        }
    }

    unsigned long long acc[8][5];
#pragma unroll
    for (int i = 0; i < 8; i++)
#pragma unroll
        for (int j = 0; j < 5; j++) acc[i][j] = 0ull;

    for (int k0 = kstart; k0 < KTOT; k0 += 2 * CBK) {
        // commit staged registers to this wg's buffers
#pragma unroll
        for (int q = 0; q < 4; q++) {
            As_[q * 4 + 0][fm] = wa[q].x;
            As_[q * 4 + 1][fm] = wa[q].y;
            As_[q * 4 + 2][fm] = wa[q].z;
            As_[q * 4 + 3][fm] = wa[q].w;
        }
#pragma unroll
        for (int s = 0; s < 10; s++) Bs_[jv[s]][slotv[s]] = bvv[s];
        __syncthreads();

        int kn = k0 + 2 * CBK;
        if (kn < KTOT) {
            const float* wp = &w[(size_t)(oc0 + wt) * KTOT + kn];
#pragma unroll
            for (int q = 0; q < 4; q++) wa[q] = *(const float4*)(wp + q * 4);
#pragma unroll
            for (int s = 0; s < 10; s++) {
                int4 d = g_decode[kn + jv[s]];
                int iy = pyv[s] + d.y, ix = pxv[s] + d.z;
                float v = 0.f;
                if (pvv[s] && iy >= 0 && iy < FSZ && ix >= 0 && ix < FSZ)
                    v = in[d.x + iy * FSZ + ix];
                bvv[s] = v;
            }
        }

#pragma unroll
        for (int kk = 0; kk < CBK; kk++) {
            float a[8];
            *(float4*)&a[0] = *(const float4*)&As_[kk][12 * ty];
            *(float4*)&a[4] = *(const float4*)&As_[kk][12 * ty + 4];
            const unsigned long long* bq =
                (const unsigned long long*)&Bs_[kk][tx * 12];
            unsigned long long b2[5];
            *(ulonglong2*)&b2[0] = *(const ulonglong2*)bq;
            *(ulonglong2*)&b2[2] = *(const ulonglong2*)(bq + 2);
            b2[4] = bq[4];
#pragma unroll
            for (int i = 0; i < 8; i++) {
                unsigned long long a2 = dup2(a[i]);
#pragma unroll
                for (int j = 0; j < 5; j++)
                    FMA2(acc[i][j], a2, b2[j]);
            }
        }
        __syncthreads();
    }

    // combine wg halves, then bias + leaky + store (wg0 finishes)
    if (wg == 1) {
#pragma unroll
        for (int i = 0; i < 8; i++)
#pragma unroll
            for (int j = 0; j < 5; j++) sm.epi[wt][i * 5 + j] = acc[i][j];
    }
    __syncthreads();
    if (wg == 0) {
#pragma unroll
        for (int i = 0; i < 8; i++) {
            int oc = oc0 + ty * 8 + i;
            float bv = bias[oc];
#pragma unroll
            for (int j = 0; j < 5; j++) {
                unsigned long long other = sm.epi[wt][i * 5 + j];
                ADD2(acc[i][j], acc[i][j], other);
                int p = p0 + tx * 10 + 2 * j;
                if (p < NPIX) {   // NPIX even -> pair-granular validity
                    float lo, hi;
                    asm("mov.b64 {%0, %1}, %2;" : "=f"(lo), "=f"(hi) : "l"(acc[i][j]));
                    lo += bv; hi += bv;
                    lo = (lo >= 0.f) ? lo : 0.01f * lo;
                    hi = (hi >= 0.f) ? hi : 0.01f * hi;
                    *(float2*)&g_feat[(size_t)oc * NPIX + p] = make_float2(lo, hi);
                }
            }
        }
    }
}

// ---------------- heads part 1: 1x1 convs, 4 channel-group partials ----------------
__global__ __launch_bounds__(128) void heads_part_kernel(const float* __restrict__ reg_w,
                                                         const float* __restrict__ cls_w) {
    __shared__ float wsm[128][56];
    int t = threadIdx.x;
    int cg = blockIdx.y;
    int c0 = cg * 128;
    int p = blockIdx.x * 128 + t;

    for (int i = t; i < 54 * 128; i += 128) {
        int o = i / 128, c = i - o * 128;
        float v = (o < 36) ? reg_w[o * 512 + c0 + c] : cls_w[(o - 36) * 512 + c0 + c];
        wsm[c][o] = v;
    }
    __syncthreads();

    float acc[54];
#pragma unroll
    for (int o = 0; o < 54; o++) acc[o] = 0.f;
    if (p < NPIX) {
        for (int c = 0; c < 128; c++) {
            float f = g_feat[(size_t)(c0 + c) * NPIX + p];
#pragma unroll
            for (int o = 0; o < 54; o++) acc[o] += f * wsm[c][o];
        }
#pragma unroll
        for (int o = 0; o < 54; o++)
            g_hpart[cg][o * NPIX + p] = acc[o];
    }
}

// ---------------- heads part 2: combine + softmax + anchor decode + scores ----------------
__global__ __launch_bounds__(128) void heads_fin_kernel(const float* __restrict__ reg_b,
                                                        const float* __restrict__ cls_b) {
    int p = blockIdx.x * 128 + threadIdx.x;
    if (p >= NPIX) return;
    float acc[54];
#pragma unroll
    for (int o = 0; o < 54; o++)
        acc[o] = (g_hpart[0][o * NPIX + p] + g_hpart[1][o * NPIX + p]) +
                 (g_hpart[2][o * NPIX + p] + g_hpart[3][o * NPIX + p]);
#pragma unroll
    for (int o = 0; o < 36; o++) acc[o] += reg_b[o];
#pragma unroll
    for (int o = 0; o < 18; o++) acc[36 + o] += cls_b[o];

    int pq = p / FSZ, pr = p - pq * FSZ;
    float cxv = 16.f * (float)pq + 8.f;
    float cyv = 16.f * (float)pr + 8.f;
    const float ssv[3]  = {8.f, 16.f, 32.f};
    const float sqr[3]  = {0.70710678f, 1.0f, 1.41421356f};
    const float sqi[3]  = {1.41421356f, 1.0f, 0.70710678f};
    const float NEGINF = __int_as_float(0xff800000);

#pragma unroll
    for (int k = 0; k < 9; k++) {
        float pr0 = acc[k * 4 + 0], pr1 = acc[k * 4 + 1];
        float pr2 = acc[k * 4 + 2], pr3 = acc[k * 4 + 3];
        float l0 = acc[36 + k * 2], l1 = acc[36 + k * 2 + 1];
        float m  = fmaxf(l0, l1);
        float e0 = expf(l0 - m), e1 = expf(l1 - m);
        float sc = e1 / (e0 + e1);

        int ri = k / 3, si = k - 3 * ri;
        float hk = (16.f * ssv[si]) * sqr[ri];
        float wk = (16.f * ssv[si]) * sqi[ri];
        float ax1 = cxv - wk * 0.5f;
        float ay1 = cyv - hk * 0.5f;
        const float hi = 799.f;
        float rx1 = fminf(fmaxf(pr0 + ax1, 0.f), hi);
        float ry1 = fminf(fmaxf(pr1 + ay1, 0.f), hi);
        float rx2 = fminf(fmaxf(((pr0 + ax1) + pr2) + wk, 0.f), hi);
        float ry2 = fminf(fmaxf(((pr1 + ay1) + pr3) + hk, 0.f), hi);
        float wv = pr2 + wk, hv = pr3 + hk;
        bool valid = (wv >= 16.f) && (hv >= 16.f);
        float s = valid ? sc : NEGINF;

        int a = p * 9 + k;
        g_boxes[a] = make_float4(rx1, ry1, rx2, ry2);
        unsigned u = __float_as_uint(s);
        u = (u >> 31) ? ~u : (u | 0x80000000u);
        g_score[a] = u;   // monotonic: larger u <=> larger score
    }
}

// ---------------- rank by counting ----------------
// rank_i = #{j<i: s_j >= s_i} + #{j>i: s_j > s_i} == stable argsort(-s) position.
// grid (22 i-blocks, 11 j-tiles); 256 threads, 4 consecutive i per thread.
__global__ __launch_bounds__(256) void rank_count_kernel() {
    __shared__ unsigned sk[2048];
    int t = threadIdx.x;
    int bi = blockIdx.x, tt = blockIdx.y;
    int i0 = (bi * 256 + t) * 4;
    unsigned my[4];
#pragma unroll
    for (int q = 0; q < 4; q++)
        my[q] = (i0 + q < NANCH) ? g_score[i0 + q] : 0u;
    int c[4] = {0, 0, 0, 0};
    int base = tt * 2048;
#pragma unroll
    for (int q = 0; q < 8; q++) {
        int idx = base + q * 256 + t;
        sk[q * 256 + t] = (idx < NANCH) ? g_score[idx] : 0u;
    }
    __syncthreads();
    if (base + 2048 <= i0) {             // all j < i
#pragma unroll 8
        for (int jj = 0; jj < 2048; jj++) {
            unsigned v = sk[jj];
#pragma unroll
            for (int q = 0; q < 4; q++) c[q] += (v >= my[q]);
        }
    } else if (base > i0 + 3) {          // all j > i
#pragma unroll 8
        for (int jj = 0; jj < 2048; jj++) {
            unsigned v = sk[jj];
#pragma unroll
            for (int q = 0; q < 4; q++) c[q] += (v > my[q]);
        }
    } else {                             // straddling tile
        for (int jj = 0; jj < 2048; jj++) {
            unsigned v = sk[jj];
            int j = base + jj;
#pragma unroll
            for (int q = 0; q < 4; q++)
                c[q] += (j < i0 + q) ? (int)(v >= my[q]) : (int)(v > my[q]);
        }
    }
#pragma unroll
    for (int q = 0; q < 4; q++) g_rankpart[tt][i0 + q] = (unsigned)c[q];
}

__global__ void rank_scatter_kernel() {
    int i = blockIdx.x * 256 + threadIdx.x;
    if (i >= NANCH) return;
    unsigned r = 0;
#pragma unroll
    for (int q = 0; q < NJT; q++) r += g_rankpart[q][i];
    if (r < PRE) {
        float4 b = g_boxes[i];
        g_sbox[r] = b;
        g_area[r] = (b.z - b.x + 1.f) * (b.w - b.y + 1.f);
    }
}

// ---------------- NMS mask (replicates reference's yy2 = max bug) ----------------
__global__ __launch_bounds__(64) void nms_mask_kernel() {
    int gi = blockIdx.y, gj = blockIdx.x;
    if (gj < gi) return;
    __shared__ float4 cbx[64];
    __shared__ float  car[64];
    int t = threadIdx.x;
    int j0 = gj * 64;
    cbx[t] = g_sbox[j0 + t];
    car[t] = g_area[j0 + t];
    __syncthreads();
    int i = gi * 64 + t;
    float4 bi = g_sbox[i];
    float  ai = g_area[i];
    unsigned long long word = 0;
#pragma unroll 8
    for (int jj = 0; jj < 64; jj++) {
        float4 bj = cbx[jj];
        float xx1 = fmaxf(bi.x, bj.x);
        float yy1 = fmaxf(bi.y, bj.y);
        float xx2 = fminf(bi.z, bj.z);
        float yy2 = fmaxf(bi.w, bj.w);   // reference bug: maximum, not minimum
        float w = fmaxf(0.f, xx2 - xx1 + 1.f);
        float h = fmaxf(0.f, yy2 - yy1 + 1.f);
        float inter = w * h;
        float ov = inter / (ai + car[jj] - inter);
        word |= ((unsigned long long)(ov > 0.7f)) << jj;
    }
    g_mask[(size_t)i * NW + gj] = word;
}

// ---------------- greedy NMS scan ----------------
__global__ __launch_bounds__(128) void nms_scan_kernel() {
    __shared__ unsigned long long ms[64];
    __shared__ unsigned long long s_remv, s_kept;
    int t = threadIdx.x;
    unsigned long long remv = 0;                       // thread t owns word g=t
    unsigned long long nextdiag = (t < 64) ? g_mask[(size_t)t * NW] : 0ull;
    for (int cb = 0; cb < NW; cb++) {
        if (t < 64) ms[t] = nextdiag;
        if (t == cb) s_remv = remv;
        __syncthreads();
        if (t < 64 && cb + 1 < NW)
            nextdiag = g_mask[(size_t)((cb + 1) * 64 + t) * NW + (cb + 1)];
        if (t == 0) {
            unsigned long long v = s_remv, kept = 0ull;
            int lim = PRE - cb * 64; if (lim > 64) lim = 64;
            for (int j = 0; j < lim; j++) {
                if (!((v >> j) & 1ull)) { kept |= 1ull << j; v |= ms[j]; }
            }
            s_kept = kept;
            g_keep[cb] = kept;
        }
        __syncthreads();
        if (t > cb && t < NW) {
            unsigned long long kk = s_kept;
            const unsigned long long* rowbase = g_mask + (size_t)cb * 64 * NW + t;
            while (kk) {
                int j0 = __ffsll((long long)kk) - 1; kk &= kk - 1;
                unsigned long long m0 = rowbase[(size_t)j0 * NW];
                unsigned long long m1 = 0, m2 = 0, m3 = 0;
                if (kk) { int j1 = __ffsll((long long)kk) - 1; kk &= kk - 1; m1 = rowbase[(size_t)j1 * NW]; }
                if (kk) { int j2 = __ffsll((long long)kk) - 1; kk &= kk - 1; m2 = rowbase[(size_t)j2 * NW]; }
                if (kk) { int j3 = __ffsll((long long)kk) - 1; kk &= kk - 1; m3 = rowbase[(size_t)j3 * NW]; }
                remv |= (m0 | m1) | (m2 | m3);
            }
        }
    }
}

// ---------------- emit top-300 ----------------
__global__ __launch_bounds__(256) void output_kernel(float* __restrict__ out) {
    __shared__ int cnts[256];
    __shared__ int offs[256];
    __shared__ int Ktot;
    int t = threadIdx.x;
    int lo = t * 24;
    int hi = lo + 24; if (hi > PRE) hi = PRE;
    int c = 0;
    for (int i = lo; i < hi; i++)
        c += (int)((g_keep[i >> 6] >> (i & 63)) & 1ull);
    cnts[t] = c;
    __syncthreads();
    if (t == 0) {
        int r = 0;
        for (int q = 0; q < 256; q++) { offs[q] = r; r += cnts[q]; }
        Ktot = r;
    }
    __syncthreads();
    int K = Ktot;
    int pk = offs[t];
    for (int i = lo; i < hi; i++) {
        bool kept = (g_keep[i >> 6] >> (i & 63)) & 1ull;
        int pos = kept ? pk : (K + (i - pk));
        if (kept) pk++;
        if (pos < POST) {
            float4 b = g_sbox[i];
            out[pos * 4 + 0] = b.x;
            out[pos * 4 + 1] = b.y;
            out[pos * 4 + 2] = b.z - b.x + 1.f;
            out[pos * 4 + 3] = b.w - b.y + 1.f;
        }
    }
}

// ---------------- launch ----------------
extern "C" void kernel_launch(void* const* d_in, const int* in_sizes, int n_in,
                              void* d_out, int out_size) {
    const float* in_features = (const float*)d_in[0];
    const float* conv_w = (const float*)d_in[1];
    const float* conv_b = (const float*)d_in[2];
    const float* reg_w  = (const float*)d_in[3];
    const float* reg_b  = (const float*)d_in[4];
    const float* cls_w  = (const float*)d_in[5];
    const float* cls_b  = (const float*)d_in[6];
    float* out = (float*)d_out;

    // only batch index 7 feeds the output
    const float* in7 = in_features + (size_t)7 * ICC * NPIX;

    setup_decode_kernel<<<18, 256>>>();        // 0
    setup_pad_kernel<<<1, 32>>>();             // 1
    zerokeep_kernel<<<1, 96>>>();              // 2
    conv3_kernel<<<dim3(32, 4), 256>>>(in7, conv_w, conv_b);   // 3 <- profiled
    heads_part_kernel<<<dim3(20, 4), 128>>>(reg_w, cls_w);     // 4
    heads_fin_kernel<<<20, 128>>>(reg_b, cls_b);               // 5
    rank_count_kernel<<<dim3(22, NJT), 256>>>();               // 6
    rank_scatter_kernel<<<88, 256>>>();                        // 7
    nms_mask_kernel<<<dim3(NW, NW), 64>>>();                   // 8
    nms_scan_kernel<<<1, 128>>>();                             // 9
    output_kernel<<<1, 256>>>(out);                            // 10
}

// round 7
// speedup vs baseline: 2.5345x; 1.1665x over previous
#include <cuda_runtime.h>
#include <cstdint>

#define FSZ   50
#define NPIX  2500
#define OC    512
#define ICC   512
#define KTOT  4608      // 512*9
#define NANCH 22500     // 2500*9
#define PRE   6000
#define NW    94        // ceil(6000/64)
#define ROWS  6016
#define POST  300
#define PADW  52
#define PADCH 2704      // 52*52

// ---------------- scratch (static device allocations) ----------------
__device__ float               g_inpad[OC * PADCH + 256];  // padded batch-7 input (+OOB slack)
__device__ float               g_feat[OC * NPIX];
__device__ float4              g_boxes[NANCH];
__device__ unsigned            g_score[NANCH];
__device__ float               g_hpart[4][54 * NPIX];
__device__ unsigned            g_hist[65536];
__device__ unsigned            g_pref[65536];
__device__ unsigned            g_bfill[65536];
__device__ unsigned long long  g_bkey[NANCH];
__device__ float4              g_sbox[ROWS];
__device__ float               g_area[ROWS];
__device__ unsigned long long  g_maskT[(size_t)NW * ROWS];
__device__ unsigned long long  g_keep[NW];
__device__ int                 g_dpad[KTOT];               // c*2704 + ky*52 + kx

// packed fp32x2 ops (sm_103a — only reachable via PTX)
#define FMA2(c, a, b) asm("fma.rn.f32x2 %0, %1, %2, %3;" : "=l"(c) : "l"(a), "l"(b), "l"(c))
#define ADD2(c, a, b) asm("add.rn.f32x2 %0, %1, %2;" : "=l"(c) : "l"(a), "l"(b))

__device__ __forceinline__ unsigned long long dup2(float x) {
    unsigned long long d;
    asm("mov.b64 %0, {%1, %1};" : "=l"(d) : "f"(x));
    return d;
}

// ---------------- launch 0: zero hist + bucket fill ----------------
__global__ void zero_hist_kernel() {
    int i = blockIdx.x * 512 + threadIdx.x;
    g_hist[i & 65535] = 0u;
    if (i >= 65536) g_bfill[i - 65536] = 0u;
}

// ---------------- launch 1: pad input ----------------
__global__ void pad_input_kernel(const float* __restrict__ in) {
    int i = blockIdx.x * 256 + threadIdx.x;
    if (i >= OC * PADCH) return;
    int c = i / PADCH, rem = i - c * PADCH;
    int y = rem / PADW, x = rem - y * PADW;
    float v = 0.f;
    if (y >= 1 && y <= 50 && x >= 1 && x <= 50)
        v = in[c * NPIX + (y - 1) * FSZ + (x - 1)];
    g_inpad[i] = v;
}

// ---------------- launch 2: misc setup ----------------
__global__ void setup_misc_kernel() {
    int i = blockIdx.x * 256 + threadIdx.x;
    if (i < KTOT) {
        int c = i / 9, r = i - 9 * c;
        g_dpad[i] = c * PADCH + (r / 3) * PADW + (r - 3 * (r / 3));
    }
    if (i < ROWS - PRE) {
        g_sbox[PRE + i] = make_float4(0.f, 0.f, 0.f, 0.f);
        g_area[PRE + i] = 1.f;
    }
    if (i < NW) g_keep[i] = 0ull;
}

// ---------------- conv 3x3 (batch 7 only) + leaky relu ----------------
// implicit GEMM 512x2500x4608, tile 128oc x 80px, 256 threads (2 warpgroups,
// split-K interleaved 12-chunks). A stored as duplicated f32 pairs in smem.
// Padded input -> predicate-free B staging. Per-wg named barriers.
#define CBK 12
union SmemConv {
    struct { unsigned long long A[2][CBK][160]; float B[2][CBK][96]; } mm;
    unsigned long long epi[128][41];
};
__global__ __launch_bounds__(256) void conv3_kernel(const float* __restrict__ w,
                                                    const float* __restrict__ bias) {
    __shared__ SmemConv sm;
    int t   = threadIdx.x;
    int wg  = t >> 7;
    int wt  = t & 127;
    int p0  = blockIdx.x * 80;
    int oc0 = blockIdx.y * 128;
    int ty = wt >> 3, tx = wt & 7;
    int barid = wg + 1;

    unsigned long long (*As_)[160] = sm.mm.A[wg];
    float (*Bs_)[96] = sm.mm.B[wg];

    // B staging map: 8 slots/thread covering 12 rows x 80 px = 960 (s=7 half-active)
    int jv[8], boff[8], pbase[8];
#pragma unroll
    for (int s = 0; s < 8; s++) {
        int l = wt + 128 * s;
        int j = l / 80, c = l - 80 * j;
        int pix = p0 + c;
        int py = pix / 50, px = pix - 50 * py;
        int pp = c >> 1, g = pp / 5, q = pp - 5 * g;
        jv[s] = j;
        boff[s] = j * 96 + g * 12 + q * 2 + (c & 1);
        pbase[s] = py * PADW + px;
    }
    bool s7 = (wt < 64);                    // s==7 valid only for wt<64
    int aslot = (wt >> 3) * 10 + (wt & 7);  // dup-A store column

    const float* wrow = &w[(size_t)(oc0 + wt) * KTOT];

    float4 wa[3]; float bvv[8];
    int kb0 = wg * CBK;
    {   // prefetch chunk 0
#pragma unroll
        for (int q = 0; q < 3; q++) wa[q] = *(const float4*)(wrow + kb0 + q * 4);
#pragma unroll
        for (int s = 0; s < 8; s++) {
            if (s < 7 || s7)
                bvv[s] = g_inpad[g_dpad[kb0 + jv[s]] + pbase[s]];
        }
    }

    unsigned long long acc[8][5];
#pragma unroll
    for (int i = 0; i < 8; i++)
#pragma unroll
        for (int j = 0; j < 5; j++) acc[i][j] = 0ull;

    for (int kb = kb0; kb < KTOT; kb += 2 * CBK) {
        // commit staged values
#pragma unroll
        for (int q = 0; q < 3; q++) {
            As_[q * 4 + 0][aslot] = dup2(wa[q].x);
            As_[q * 4 + 1][aslot] = dup2(wa[q].y);
            As_[q * 4 + 2][aslot] = dup2(wa[q].z);
            As_[q * 4 + 3][aslot] = dup2(wa[q].w);
        }
#pragma unroll
        for (int s = 0; s < 8; s++)
            if (s < 7 || s7) (&Bs_[0][0])[boff[s]] = bvv[s];
        asm volatile("bar.sync %0, 128;" :: "r"(barid) : "memory");

        int kn = kb + 2 * CBK;
        if (kn < KTOT) {
#pragma unroll
            for (int q = 0; q < 3; q++) wa[q] = *(const float4*)(wrow + kn + q * 4);
#pragma unroll
            for (int s = 0; s < 8; s++) {
                if (s < 7 || s7)
                    bvv[s] = g_inpad[g_dpad[kn + jv[s]] + pbase[s]];
            }
        }

#pragma unroll
        for (int kk = 0; kk < CBK; kk++) {
            unsigned long long a2[8], b2[5];
            *(ulonglong2*)&a2[0] = *(const ulonglong2*)&As_[kk][ty * 10 + 0];
            *(ulonglong2*)&a2[2] = *(const ulonglong2*)&As_[kk][ty * 10 + 2];
            *(ulonglong2*)&a2[4] = *(const ulonglong2*)&As_[kk][ty * 10 + 4];
            *(ulonglong2*)&a2[6] = *(const ulonglong2*)&As_[kk][ty * 10 + 6];
            const unsigned long long* bq = (const unsigned long long*)&Bs_[kk][tx * 12];
            *(ulonglong2*)&b2[0] = *(const ulonglong2*)bq;
            *(ulonglong2*)&b2[2] = *(const ulonglong2*)(bq + 2);
            b2[4] = bq[4];
#pragma unroll
            for (int i = 0; i < 8; i++)
#pragma unroll
                for (int j = 0; j < 5; j++)
                    FMA2(acc[i][j], a2[i], b2[j]);
        }
        asm volatile("bar.sync %0, 128;" :: "r"(barid) : "memory");
    }

    // combine split-K halves; wg0 applies bias + leaky + store
    __syncthreads();
    if (wg == 1) {
#pragma unroll
        for (int i = 0; i < 8; i++)
#pragma unroll
            for (int j = 0; j < 5; j++) sm.epi[wt][i * 5 + j] = acc[i][j];
    }
    __syncthreads();
    if (wg == 0) {
#pragma unroll
        for (int i = 0; i < 8; i++) {
            int oc = oc0 + ty * 8 + i;
            float bv = bias[oc];
#pragma unroll
            for (int j = 0; j < 5; j++) {
                unsigned long long other = sm.epi[wt][i * 5 + j];
                ADD2(acc[i][j], acc[i][j], other);
                int p = p0 + tx * 10 + 2 * j;
                if (p < NPIX) {
                    float lo, hi;
                    asm("mov.b64 {%0, %1}, %2;" : "=f"(lo), "=f"(hi) : "l"(acc[i][j]));
                    lo += bv; hi += bv;
                    lo = (lo >= 0.f) ? lo : 0.01f * lo;
                    hi = (hi >= 0.f) ? hi : 0.01f * hi;
                    *(float2*)&g_feat[(size_t)oc * NPIX + p] = make_float2(lo, hi);
                }
            }
        }
    }
}

// ---------------- heads part 1: 1x1 convs, 4 channel-group partials ----------------
__global__ __launch_bounds__(128) void heads_part_kernel(const float* __restrict__ reg_w,
                                                         const float* __restrict__ cls_w) {
    __shared__ float wsm[128][56];
    int t = threadIdx.x;
    int cg = blockIdx.y;
    int c0 = cg * 128;
    int p = blockIdx.x * 128 + t;

    for (int i = t; i < 54 * 128; i += 128) {
        int o = i / 128, c = i - o * 128;
        float v = (o < 36) ? reg_w[o * 512 + c0 + c] : cls_w[(o - 36) * 512 + c0 + c];
        wsm[c][o] = v;
    }
    __syncthreads();

    float acc[54];
#pragma unroll
    for (int o = 0; o < 54; o++) acc[o] = 0.f;
    if (p < NPIX) {
        for (int c = 0; c < 128; c++) {
            float f = g_feat[(size_t)(c0 + c) * NPIX + p];
#pragma unroll
            for (int o = 0; o < 54; o++) acc[o] += f * wsm[c][o];
        }
#pragma unroll
        for (int o = 0; o < 54; o++)
            g_hpart[cg][o * NPIX + p] = acc[o];
    }
}

// ---------------- heads part 2: combine + softmax + decode + scores + histogram ----------------
__global__ __launch_bounds__(128) void heads_fin_kernel(const float* __restrict__ reg_b,
                                                        const float* __restrict__ cls_b) {
    int p = blockIdx.x * 128 + threadIdx.x;
    if (p >= NPIX) return;
    float acc[54];
#pragma unroll
    for (int o = 0; o < 54; o++)
        acc[o] = (g_hpart[0][o * NPIX + p] + g_hpart[1][o * NPIX + p]) +
                 (g_hpart[2][o * NPIX + p] + g_hpart[3][o * NPIX + p]);
#pragma unroll
    for (int o = 0; o < 36; o++) acc[o] += reg_b[o];
#pragma unroll
    for (int o = 0; o < 18; o++) acc[36 + o] += cls_b[o];

    int pq = p / FSZ, pr = p - pq * FSZ;
    float cxv = 16.f * (float)pq + 8.f;
    float cyv = 16.f * (float)pr + 8.f;
    const float ssv[3]  = {8.f, 16.f, 32.f};
    const float sqr[3]  = {0.70710678f, 1.0f, 1.41421356f};
    const float sqi[3]  = {1.41421356f, 1.0f, 0.70710678f};
    const float NEGINF = __int_as_float(0xff800000);

#pragma unroll
    for (int k = 0; k < 9; k++) {
        float pr0 = acc[k * 4 + 0], pr1 = acc[k * 4 + 1];
        float pr2 = acc[k * 4 + 2], pr3 = acc[k * 4 + 3];
        float l0 = acc[36 + k * 2], l1 = acc[36 + k * 2 + 1];
        float m  = fmaxf(l0, l1);
        float e0 = expf(l0 - m), e1 = expf(l1 - m);
        float sc = e1 / (e0 + e1);

        int ri = k / 3, si = k - 3 * ri;
        float hk = (16.f * ssv[si]) * sqr[ri];
        float wk = (16.f * ssv[si]) * sqi[ri];
        float ax1 = cxv - wk * 0.5f;
        float ay1 = cyv - hk * 0.5f;
        const float hi = 799.f;
        float rx1 = fminf(fmaxf(pr0 + ax1, 0.f), hi);
        float ry1 = fminf(fmaxf(pr1 + ay1, 0.f), hi);
        float rx2 = fminf(fmaxf(((pr0 + ax1) + pr2) + wk, 0.f), hi);
        float ry2 = fminf(fmaxf(((pr1 + ay1) + pr3) + hk, 0.f), hi);
        float wv = pr2 + wk, hv = pr3 + hk;
        bool valid = (wv >= 16.f) && (hv >= 16.f);
        float s = valid ? sc : NEGINF;

        int a = p * 9 + k;
        g_boxes[a] = make_float4(rx1, ry1, rx2, ry2);
        unsigned u = __float_as_uint(s);
        u = (u >> 31) ? ~u : (u | 0x80000000u);
        g_score[a] = u;
        atomicAdd(&g_hist[u >> 16], 1u);
    }
}

// ---------------- bucket suffix-prefix (1 block) ----------------
__global__ __launch_bounds__(1024) void bucket_prefix_kernel() {
    __shared__ unsigned part[1024];
    int t = threadIdx.x;
    int base = t * 64;
    unsigned s = 0;
    unsigned h[64];
#pragma unroll
    for (int q = 0; q < 64; q++) { h[q] = g_hist[base + q]; s += h[q]; }
    part[t] = s;
    __syncthreads();
    for (int off = 1; off < 1024; off <<= 1) {
        unsigned v = (t + off < 1024) ? part[t + off] : 0u;
        __syncthreads();
        part[t] += v;
        __syncthreads();
    }
    unsigned run = part[t] - s;   // total in strictly-higher chunks
    for (int q = 63; q >= 0; q--) {
        g_pref[base + q] = run;
        run += h[q];
    }
}

// ---------------- bucket fill ----------------
__global__ void bucket_fill_kernel() {
    int i = blockIdx.x * 256 + threadIdx.x;
    if (i >= NANCH) return;
    unsigned s = g_score[i];
    unsigned b = s >> 16;
    unsigned slot = atomicAdd(&g_bfill[b], 1u);
    g_bkey[g_pref[b] + slot] = ((unsigned long long)s << 32) | (unsigned)(~i);
}

// ---------------- exact rank + scatter ----------------
__global__ void rank_scatter_kernel() {
    int i = blockIdx.x * 256 + threadIdx.x;
    if (i >= NANCH) return;
    unsigned s = g_score[i];
    unsigned b = s >> 16;
    unsigned base = g_pref[b];
    unsigned cnt = g_hist[b];
    unsigned long long my = ((unsigned long long)s << 32) | (unsigned)(~i);
    unsigned r = base;
    for (unsigned q = 0; q < cnt; q++)
        r += (g_bkey[base + q] > my);
    if (r < PRE) {
        float4 bx = g_boxes[i];
        g_sbox[r] = bx;
        g_area[r] = (bx.z - bx.x + 1.f) * (bx.w - bx.y + 1.f);
    }
}

// ---------------- NMS mask, transposed layout (yy2 = max bug preserved) ----------------
__global__ __launch_bounds__(64) void nms_mask_kernel() {
    int gi = blockIdx.y, gj = blockIdx.x;
    if (gj < gi) return;
    __shared__ float4 cbx[64];
    __shared__ float  car[64];
    int t = threadIdx.x;
    int j0 = gj * 64;
    cbx[t] = g_sbox[j0 + t];
    car[t] = g_area[j0 + t];
    __syncthreads();
    int i = gi * 64 + t;
    float4 bi = g_sbox[i];
    float  ai = g_area[i];
    unsigned long long word = 0;
#pragma unroll 8
    for (int jj = 0; jj < 64; jj++) {
        float4 bj = cbx[jj];
        float xx1 = fmaxf(bi.x, bj.x);
        float yy1 = fmaxf(bi.y, bj.y);
        float xx2 = fminf(bi.z, bj.z);
        float yy2 = fmaxf(bi.w, bj.w);   // reference bug: maximum, not minimum
        float w = fmaxf(0.f, xx2 - xx1 + 1.f);
        float h = fmaxf(0.f, yy2 - yy1 + 1.f);
        float inter = w * h;
        float ov = inter / (ai + car[jj] - inter);
        word |= ((unsigned long long)(ov > 0.7f)) << jj;
    }
    g_maskT[(size_t)gj * ROWS + i] = word;   // coalesced across t
}

// ---------------- greedy NMS scan ----------------
__global__ __launch_bounds__(128) void nms_scan_kernel() {
    __shared__ unsigned long long ms[64];
    __shared__ unsigned long long s_remv, s_kept;
    int t = threadIdx.x;
    unsigned long long remv = 0;                       // thread t owns word g=t
    unsigned long long nextdiag = (t < 64) ? g_maskT[t] : 0ull;
    for (int cb = 0; cb < NW; cb++) {
        if (t < 64) ms[t] = nextdiag;
        if (t == cb) s_remv = remv;
        __syncthreads();
        if (t < 64 && cb + 1 < NW)
            nextdiag = g_maskT[(size_t)(cb + 1) * ROWS + (cb + 1) * 64 + t];
        if (t == 0) {
            unsigned long long v = s_remv, kept = 0ull;
            int lim = PRE - cb * 64; if (lim > 64) lim = 64;
            for (int j = 0; j < lim; j++) {
                if (!((v >> j) & 1ull)) { kept |= 1ull << j; v |= ms[j]; }
            }
            s_kept = kept;
            g_keep[cb] = kept;
        }
        __syncthreads();
        if (t > cb && t < NW) {
            unsigned long long kk = s_kept;
            const unsigned long long* rowT = g_maskT + (size_t)t * ROWS + cb * 64;
            while (kk) {
                int j0 = __ffsll((long long)kk) - 1; kk &= kk - 1;
                unsigned long long m0 = rowT[j0];
                unsigned long long m1 = 0, m2 = 0, m3 = 0;
                if (kk) { int j1 = __ffsll((long long)kk) - 1; kk &= kk - 1; m1 = rowT[j1]; }
                if (kk) { int j2 = __ffsll((long long)kk) - 1; kk &= kk - 1; m2 = rowT[j2]; }
                if (kk) { int j3 = __ffsll((long long)kk) - 1; kk &= kk - 1; m3 = rowT[j3]; }
                remv |= (m0 | m1) | (m2 | m3);
            }
        }
    }
}

// ---------------- emit top-300 ----------------
__global__ __launch_bounds__(256) void output_kernel(float* __restrict__ out) {
    __shared__ int cnts[256];
    __shared__ int offs[256];
    __shared__ int Ktot;
    int t = threadIdx.x;
    int lo = t * 24;
    int hi = lo + 24; if (hi > PRE) hi = PRE;
    int c = 0;
    for (int i = lo; i < hi; i++)
        c += (int)((g_keep[i >> 6] >> (i & 63)) & 1ull);
    cnts[t] = c;
    __syncthreads();
    if (t == 0) {
        int r = 0;
        for (int q = 0; q < 256; q++) { offs[q] = r; r += cnts[q]; }
        Ktot = r;
    }
    __syncthreads();
    int K = Ktot;
    int pk = offs[t];
    for (int i = lo; i < hi; i++) {
        bool kept = (g_keep[i >> 6] >> (i & 63)) & 1ull;
        int pos = kept ? pk : (K + (i - pk));
        if (kept) pk++;
        if (pos < POST) {
            float4 b = g_sbox[i];
            out[pos * 4 + 0] = b.x;
            out[pos * 4 + 1] = b.y;
            out[pos * 4 + 2] = b.z - b.x + 1.f;
            out[pos * 4 + 3] = b.w - b.y + 1.f;
        }
    }
}

// ---------------- launch ----------------
extern "C" void kernel_launch(void* const* d_in, const int* in_sizes, int n_in,
                              void* d_out, int out_size) {
    const float* in_features = (const float*)d_in[0];
    const float* conv_w = (const float*)d_in[1];
    const float* conv_b = (const float*)d_in[2];
    const float* reg_w  = (const float*)d_in[3];
    const float* reg_b  = (const float*)d_in[4];
    const float* cls_w  = (const float*)d_in[5];
    const float* cls_b  = (const float*)d_in[6];
    float* out = (float*)d_out;

    // only batch index 7 feeds the output
    const float* in7 = in_features + (size_t)7 * ICC * NPIX;

    zero_hist_kernel<<<256, 512>>>();                            // 0
    pad_input_kernel<<<(OC * PADCH + 255) / 256, 256>>>(in7);    // 1
    setup_misc_kernel<<<18, 256>>>();                            // 2
    conv3_kernel<<<dim3(32, 4), 256>>>(conv_w, conv_b);          // 3 <- profiled
    heads_part_kernel<<<dim3(20, 4), 128>>>(reg_w, cls_w);       // 4
    heads_fin_kernel<<<20, 128>>>(reg_b, cls_b);                 // 5
    bucket_prefix_kernel<<<1, 1024>>>();                         // 6
    bucket_fill_kernel<<<88, 256>>>();                           // 7
    rank_scatter_kernel<<<88, 256>>>();                          // 8
    nms_mask_kernel<<<dim3(NW, NW), 64>>>();                     // 9
    nms_scan_kernel<<<1, 128>>>();                               // 10
    output_kernel<<<1, 256>>>(out);                              // 11
}

// round 9
// speedup vs baseline: 2.7577x; 1.0881x over previous
#include <cuda_runtime.h>
#include <cstdint>

#define FSZ   50
#define NPIX  2500
#define OC    512
#define KTOT  4608      // 512*9
#define NANCH 22500     // 2500*9
#define PRE   6000
#define NW    94        // ceil(6000/64)
#define ROWS  6016
#define POST  300
#define PADW  52
#define PADCH 2704      // 52*52

// ---------------- scratch (static device allocations) ----------------
__device__ float               g_wre[OC * KTOT];           // weights, k' = r*512+ch
__device__ float               g_inpad[OC * PADCH + 256];  // padded batch-7 input
__device__ float               g_feat[OC * NPIX];
__device__ float4              g_boxes[NANCH];
__device__ unsigned            g_score[NANCH];
__device__ float               g_hpart[4][54 * NPIX];
__device__ unsigned            g_hist[65536];
__device__ unsigned            g_bsum[256];
__device__ unsigned            g_pref[65536];
__device__ unsigned            g_bfill[65536];
__device__ unsigned long long  g_bkey[NANCH];
__device__ float4              g_sbox[ROWS];
__device__ float               g_area[ROWS];
__device__ unsigned long long  g_maskT[(size_t)NW * ROWS];
__device__ unsigned long long  g_keep[NW];

// packed fp32x2 FMA (sm_103a FFMA2 — only reachable via PTX)
#define FMA2(c, a, b) asm("fma.rn.f32x2 %0, %1, %2, %3;" : "=l"(c) : "l"(a), "l"(b), "l"(c))
__device__ __forceinline__ unsigned long long dup2(float x) {
    unsigned long long d;
    asm("mov.b64 %0, {%1, %1};" : "=l"(d) : "f"(x));
    return d;
}
__device__ __forceinline__ uint32_t smem_u32(const void* p) {
    uint32_t a;
    asm("{ .reg .u64 t; cvta.to.shared.u64 t, %1; cvt.u32.u64 %0, t; }" : "=r"(a) : "l"(p));
    return a;
}
#define CPA16(dst, src) asm volatile("cp.async.cg.shared.global [%0], [%1], 16;" :: "r"(dst), "l"(src))
#define CPA4(dst, src)  asm volatile("cp.async.ca.shared.global [%0], [%1], 4;"  :: "r"(dst), "l"(src))
#define CPCOMMIT()      asm volatile("cp.async.commit_group;" ::: "memory")
#define CPWAIT1()       asm volatile("cp.async.wait_group 1;" ::: "memory")

// ---------------- launch 0: zero hist + bucket fill counters ----------------
__global__ void zero_hist_kernel() {
    int i = blockIdx.x * 512 + threadIdx.x;
    if (i < 65536) g_hist[i] = 0u;
    else g_bfill[i - 65536] = 0u;
}

// ---------------- launch 1: prep (weight reorder + input pad) ----------------
#define WN (OC * KTOT)
__global__ void prep_kernel(const float* __restrict__ in7, const float* __restrict__ cw) {
    int i = blockIdx.x * 256 + threadIdx.x;
    if (i < WN) {
        int oc = i / KTOT, rem = i - oc * KTOT;
        int r = rem >> 9, ch = rem & 511;
        g_wre[i] = cw[oc * KTOT + ch * 9 + r];
    } else {
        int j = i - WN;
        if (j >= OC * PADCH) return;
        int c = j / PADCH, rem = j - c * PADCH;
        int y = rem / PADW, x = rem - y * PADW;
        float v = 0.f;
        if (y >= 1 && y <= 50 && x >= 1 && x <= 50)
            v = in7[c * NPIX + (y - 1) * FSZ + (x - 1)];
        g_inpad[j] = v;
    }
}

// ---------------- launch 2: misc setup ----------------
__global__ void setup_misc_kernel() {
    int i = blockIdx.x * 256 + threadIdx.x;
    if (i < ROWS - PRE) {
        g_sbox[PRE + i] = make_float4(0.f, 0.f, 0.f, 0.f);
        g_area[PRE + i] = 1.f;
    }
    if (i < NW) g_keep[i] = 0ull;
}

// ---------------- launch 3: conv 3x3 (batch 7) + leaky relu ----------------
// implicit GEMM 512x2500x4608. 512 threads (4 warps/SMSP), CTA tile 128oc x 80px,
// K-chunks of 16, 3-stage cp.async pipeline, FFMA2 thread tile 2oc x 5 px-pairs.
#define CBK 16
#define NCHK 288    // 4608/16
struct ConvSmem {
    float A[3][128][20];   // [stage][oc][kk] rows padded to 20
    float B[3][CBK][96];   // [stage][kk][slot], 8 groups * 12 stride
};  // 3*(10240+6144) = 49152 bytes
__global__ __launch_bounds__(512) void conv3_kernel(const float* __restrict__ bias) {
    __shared__ ConvSmem sm;
    uint32_t sb = smem_u32(&sm);
    int t = threadIdx.x;
    int px0 = blockIdx.x * 80, oc0 = blockIdx.y * 128;
    int w = t >> 5, lane = t & 31;
    int tx = lane & 7, tyl = lane >> 3;
    int oc_loc = w * 8 + tyl * 2;

    // A staging map: thread loads 16B = 4 k for one oc
    int a_oc = t & 127, a_k0 = (t >> 7) * 4;
    const float* a_src = g_wre + (size_t)(oc0 + a_oc) * KTOT + a_k0;
    uint32_t a_soff = sb + (a_oc * 20 + a_k0) * 4;

    // B staging map: 3 slots of 4B (slot 2 active for t < 256)
    int b_kk[3], b_pix[3];
    uint32_t b_soff[3];
#pragma unroll
    for (int s = 0; s < 3; s++) {
        int idx = t + 512 * s;
        int kk = idx / 80, c = idx - 80 * kk;
        int p = px0 + c;
        int py = p / 50, px = p - 50 * py;
        b_kk[s] = kk;
        b_pix[s] = py * PADW + px;
        b_soff[s] = sb + 30720 + (kk * 96 + (c / 10) * 12 + (c % 10)) * 4;
    }
    bool s2 = (t < 256);

    unsigned long long acc0[5], acc1[5];
#pragma unroll
    for (int j = 0; j < 5; j++) { acc0[j] = 0ull; acc1[j] = 0ull; }

    // issue chunk q into stage st
    auto issue = [&](int q, int st) {
        int kb = q * CBK;
        int r = kb >> 9, ch0 = kb & 511;
        int ry = r / 3;
        int rr = ry * PADW + (r - 3 * ry);
        CPA16(a_soff + st * 10240, a_src + kb);
        const float* ib = g_inpad + rr;
#pragma unroll
        for (int s = 0; s < 3; s++) {
            if (s < 2 || s2)
                CPA4(b_soff[s] + st * 6144, ib + (size_t)(ch0 + b_kk[s]) * PADCH + b_pix[s]);
        }
    };

    issue(0, 0); CPCOMMIT();
    issue(1, 1); CPCOMMIT();

    int st = 0, st2 = 2;
    for (int q = 0; q < NCHK; q++) {
        CPWAIT1();
        __syncthreads();
        if (q + 2 < NCHK) issue(q + 2, st2);
        CPCOMMIT();

        const float (*A_)[20] = sm.A[st];
        const float* B_ = &sm.B[st][0][0];
#pragma unroll
        for (int kk = 0; kk < CBK; kk++) {
            float a0v = A_[oc_loc][kk];
            float a1v = A_[oc_loc + 1][kk];
            unsigned long long da0 = dup2(a0v), da1 = dup2(a1v);
            const unsigned long long* bq =
                (const unsigned long long*)(B_ + kk * 96 + tx * 12);
            unsigned long long b2[5];
            *(ulonglong2*)&b2[0] = *(const ulonglong2*)bq;
            *(ulonglong2*)&b2[2] = *(const ulonglong2*)(bq + 2);
            b2[4] = bq[4];
#pragma unroll
            for (int j = 0; j < 5; j++) {
                FMA2(acc0[j], da0, b2[j]);
                FMA2(acc1[j], da1, b2[j]);
            }
        }
        st = (st == 2) ? 0 : st + 1;
        st2 = (st2 == 2) ? 0 : st2 + 1;
    }

    // epilogue: bias + leaky + store
#pragma unroll
    for (int i = 0; i < 2; i++) {
        int oc = oc0 + oc_loc + i;
        float bv = bias[oc];
        unsigned long long* ac = i ? acc1 : acc0;
#pragma unroll
        for (int j = 0; j < 5; j++) {
            int p = px0 + tx * 10 + 2 * j;
            if (p < NPIX) {
                float lo, hi;
                asm("mov.b64 {%0, %1}, %2;" : "=f"(lo), "=f"(hi) : "l"(ac[j]));
                lo += bv; hi += bv;
                lo = (lo >= 0.f) ? lo : 0.01f * lo;
                hi = (hi >= 0.f) ? hi : 0.01f * hi;
                *(float2*)&g_feat[(size_t)oc * NPIX + p] = make_float2(lo, hi);
            }
        }
    }
}

// ---------------- heads part 1: 1x1 convs, 4 channel-group partials ----------------
__global__ __launch_bounds__(128) void heads_part_kernel(const float* __restrict__ reg_w,
                                                         const float* __restrict__ cls_w) {
    __shared__ float wsm[128][56];
    int t = threadIdx.x;
    int cg = blockIdx.y;
    int c0 = cg * 128;
    int p = blockIdx.x * 128 + t;

    for (int i = t; i < 54 * 128; i += 128) {
        int o = i / 128, c = i - o * 128;
        float v = (o < 36) ? reg_w[o * 512 + c0 + c] : cls_w[(o - 36) * 512 + c0 + c];
        wsm[c][o] = v;
    }
    __syncthreads();

    float acc[54];
#pragma unroll
    for (int o = 0; o < 54; o++) acc[o] = 0.f;
    if (p < NPIX) {
        for (int c = 0; c < 128; c++) {
            float f = g_feat[(size_t)(c0 + c) * NPIX + p];
#pragma unroll
            for (int o = 0; o < 54; o++) acc[o] += f * wsm[c][o];
        }
#pragma unroll
        for (int o = 0; o < 54; o++)
            g_hpart[cg][o * NPIX + p] = acc[o];
    }
}

// ---------------- heads part 2: combine + softmax + decode + scores + histogram ----------------
__global__ __launch_bounds__(128) void heads_fin_kernel(const float* __restrict__ reg_b,
                                                        const float* __restrict__ cls_b) {
    int p = blockIdx.x * 128 + threadIdx.x;
    if (p >= NPIX) return;
    float acc[54];
#pragma unroll
    for (int o = 0; o < 54; o++)
        acc[o] = (g_hpart[0][o * NPIX + p] + g_hpart[1][o * NPIX + p]) +
                 (g_hpart[2][o * NPIX + p] + g_hpart[3][o * NPIX + p]);
#pragma unroll
    for (int o = 0; o < 36; o++) acc[o] += reg_b[o];
#pragma unroll
    for (int o = 0; o < 18; o++) acc[36 + o] += cls_b[o];

    int pq = p / FSZ, pr = p - pq * FSZ;
    float cxv = 16.f * (float)pq + 8.f;
    float cyv = 16.f * (float)pr + 8.f;
    const float ssv[3]  = {8.f, 16.f, 32.f};
    const float sqr[3]  = {0.70710678f, 1.0f, 1.41421356f};
    const float sqi[3]  = {1.41421356f, 1.0f, 0.70710678f};
    const float NEGINF = __int_as_float(0xff800000);

#pragma unroll
    for (int k = 0; k < 9; k++) {
        float pr0 = acc[k * 4 + 0], pr1 = acc[k * 4 + 1];
        float pr2 = acc[k * 4 + 2], pr3 = acc[k * 4 + 3];
        float l0 = acc[36 + k * 2], l1 = acc[36 + k * 2 + 1];
        float m  = fmaxf(l0, l1);
        float e0 = expf(l0 - m), e1 = expf(l1 - m);
        float sc = e1 / (e0 + e1);

        int ri = k / 3, si = k - 3 * ri;
        float hk = (16.f * ssv[si]) * sqr[ri];
        float wk = (16.f * ssv[si]) * sqi[ri];
        float ax1 = cxv - wk * 0.5f;
        float ay1 = cyv - hk * 0.5f;
        const float hi = 799.f;
        float rx1 = fminf(fmaxf(pr0 + ax1, 0.f), hi);
        float ry1 = fminf(fmaxf(pr1 + ay1, 0.f), hi);
        float rx2 = fminf(fmaxf(((pr0 + ax1) + pr2) + wk, 0.f), hi);
        float ry2 = fminf(fmaxf(((pr1 + ay1) + pr3) + hk, 0.f), hi);
        float wv = pr2 + wk, hv = pr3 + hk;
        bool valid = (wv >= 16.f) && (hv >= 16.f);
        float s = valid ? sc : NEGINF;

        int a = p * 9 + k;
        g_boxes[a] = make_float4(rx1, ry1, rx2, ry2);
        unsigned u = __float_as_uint(s);
        u = (u >> 31) ? ~u : (u | 0x80000000u);
        g_score[a] = u;
        atomicAdd(&g_hist[u >> 16], 1u);
    }
}

// ---------------- bucket sums (coalesced) ----------------
__global__ __launch_bounds__(256) void bucket_sum_kernel() {
    __shared__ unsigned sh[256];
    int b = blockIdx.x, t = threadIdx.x;
    sh[t] = g_hist[b * 256 + t];
    __syncthreads();
    for (int off = 128; off; off >>= 1) {
        if (t < off) sh[t] += sh[t + off];
        __syncthreads();
    }
    if (t == 0) g_bsum[b] = sh[0];
}

// ---------------- suffix-prefix per bucket (coalesced) ----------------
__global__ __launch_bounds__(256) void bucket_pref_kernel() {
    __shared__ unsigned sh[256];
    __shared__ unsigned above_s;
    int b = blockIdx.x, t = threadIdx.x;
    unsigned v = (t > b) ? g_bsum[t] : 0u;
    sh[t] = v;
    __syncthreads();
    for (int off = 128; off; off >>= 1) {
        if (t < off) sh[t] += sh[t + off];
        __syncthreads();
    }
    if (t == 0) above_s = sh[0];
    __syncthreads();
    unsigned above = above_s;
    unsigned h = g_hist[b * 256 + t];
    __syncthreads();
    sh[t] = h;
    __syncthreads();
    for (int off = 1; off < 256; off <<= 1) {
        unsigned x = (t + off < 256) ? sh[t + off] : 0u;
        __syncthreads();
        sh[t] += x;
        __syncthreads();
    }
    g_pref[b * 256 + t] = above + sh[t] - h;   // count strictly higher
}

// ---------------- bucket fill (only buckets that can reach top-6000) ----------------
__global__ void bucket_fill_kernel() {
    int i = blockIdx.x * 256 + threadIdx.x;
    if (i >= NANCH) return;
    unsigned s = g_score[i];
    unsigned b = s >> 16;
    unsigned base = g_pref[b];
    if (base >= PRE) return;
    unsigned slot = atomicAdd(&g_bfill[b], 1u);
    g_bkey[base + slot] = ((unsigned long long)s << 32) | (unsigned)(~i);
}

// ---------------- exact rank + scatter ----------------
__global__ void rank_scatter_kernel() {
    int i = blockIdx.x * 256 + threadIdx.x;
    if (i >= NANCH) return;
    unsigned s = g_score[i];
    unsigned b = s >> 16;
    unsigned base = g_pref[b];
    if (base >= PRE) return;
    unsigned cnt = g_hist[b];
    unsigned long long my = ((unsigned long long)s << 32) | (unsigned)(~i);
    unsigned r = base;
    for (unsigned q = 0; q < cnt; q++)
        r += (g_bkey[base + q] > my);
    if (r < PRE) {
        float4 bx = g_boxes[i];
        g_sbox[r] = bx;
        g_area[r] = (bx.z - bx.x + 1.f) * (bx.w - bx.y + 1.f);
    }
}

// ---------------- NMS mask, transposed layout (yy2 = max bug preserved) ----------------
__global__ __launch_bounds__(64) void nms_mask_kernel() {
    int gi = blockIdx.y, gj = blockIdx.x;
    if (gj < gi) return;
    __shared__ float4 cbx[64];
    __shared__ float  car[64];
    int t = threadIdx.x;
    int j0 = gj * 64;
    cbx[t] = g_sbox[j0 + t];
    car[t] = g_area[j0 + t];
    __syncthreads();
    int i = gi * 64 + t;
    float4 bi = g_sbox[i];
    float  ai = g_area[i];
    unsigned long long word = 0;
#pragma unroll 8
    for (int jj = 0; jj < 64; jj++) {
        float4 bj = cbx[jj];
        float xx1 = fmaxf(bi.x, bj.x);
        float yy1 = fmaxf(bi.y, bj.y);
        float xx2 = fminf(bi.z, bj.z);
        float yy2 = fmaxf(bi.w, bj.w);   // reference bug: maximum, not minimum
        float w = fmaxf(0.f, xx2 - xx1 + 1.f);
        float h = fmaxf(0.f, yy2 - yy1 + 1.f);
        float inter = w * h;
        float ov = inter / (ai + car[jj] - inter);
        word |= ((unsigned long long)(ov > 0.7f)) << jj;
    }
    g_maskT[(size_t)gj * ROWS + i] = word;   // coalesced across t
}

// ---------------- greedy NMS scan (ffs skip-loop) ----------------
__global__ __launch_bounds__(128) void nms_scan_kernel() {
    __shared__ unsigned long long ms[64];
    __shared__ unsigned long long s_remv, s_kept;
    int t = threadIdx.x;
    unsigned long long remv = 0;                       // thread t owns word g=t
    unsigned long long nextdiag = (t < 64) ? g_maskT[t] : 0ull;
    for (int cb = 0; cb < NW; cb++) {
        if (t < 64) ms[t] = nextdiag;
        if (t == cb) s_remv = remv;
        __syncthreads();
        if (t < 64 && cb + 1 < NW)
            nextdiag = g_maskT[(size_t)(cb + 1) * ROWS + (cb + 1) * 64 + t];
        if (t == 0) {
            unsigned long long v = s_remv, kept = 0ull;
            int lim = PRE - cb * 64; if (lim > 64) lim = 64;
            unsigned long long avail = ~v;
            if (lim < 64) avail &= (1ull << lim) - 1ull;
            while (avail) {
                int j = __ffsll((long long)avail) - 1;
                kept |= 1ull << j;
                v |= ms[j];
                avail &= ~v;
                avail &= (j < 63) ? (~0ull << (j + 1)) : 0ull;
            }
            s_kept = kept;
            g_keep[cb] = kept;
        }
        __syncthreads();
        if (t > cb && t < NW) {
            unsigned long long kk = s_kept;
            const unsigned long long* rowT = g_maskT + (size_t)t * ROWS + cb * 64;
            while (kk) {
                int j0 = __ffsll((long long)kk) - 1; kk &= kk - 1;
                unsigned long long m0 = rowT[j0];
                unsigned long long m1 = 0, m2 = 0, m3 = 0;
                if (kk) { int j1 = __ffsll((long long)kk) - 1; kk &= kk - 1; m1 = rowT[j1]; }
                if (kk) { int j2 = __ffsll((long long)kk) - 1; kk &= kk - 1; m2 = rowT[j2]; }
                if (kk) { int j3 = __ffsll((long long)kk) - 1; kk &= kk - 1; m3 = rowT[j3]; }
                remv |= (m0 | m1) | (m2 | m3);
            }
        }
    }
}

// ---------------- emit top-300 ----------------
__global__ __launch_bounds__(256) void output_kernel(float* __restrict__ out) {
    __shared__ int cnts[256];
    __shared__ int offs[256];
    __shared__ int Ktot;
    int t = threadIdx.x;
    int lo = t * 24;
    int hi = lo + 24; if (hi > PRE) hi = PRE;
    int c = 0;
    for (int i = lo; i < hi; i++)
        c += (int)((g_keep[i >> 6] >> (i & 63)) & 1ull);
    cnts[t] = c;
    __syncthreads();
    if (t == 0) {
        int r = 0;
        for (int q = 0; q < 256; q++) { offs[q] = r; r += cnts[q]; }
        Ktot = r;
    }
    __syncthreads();
    int K = Ktot;
    int pk = offs[t];
    for (int i = lo; i < hi; i++) {
        bool kept = (g_keep[i >> 6] >> (i & 63)) & 1ull;
        int pos = kept ? pk : (K + (i - pk));
        if (kept) pk++;
        if (pos < POST) {
            float4 b = g_sbox[i];
            out[pos * 4 + 0] = b.x;
            out[pos * 4 + 1] = b.y;
            out[pos * 4 + 2] = b.z - b.x + 1.f;
            out[pos * 4 + 3] = b.w - b.y + 1.f;
        }
    }
}

// ---------------- launch ----------------
extern "C" void kernel_launch(void* const* d_in, const int* in_sizes, int n_in,
                              void* d_out, int out_size) {
    const float* in_features = (const float*)d_in[0];
    const float* conv_w = (const float*)d_in[1];
    const float* conv_b = (const float*)d_in[2];
    const float* reg_w  = (const float*)d_in[3];
    const float* reg_b  = (const float*)d_in[4];
    const float* cls_w  = (const float*)d_in[5];
    const float* cls_b  = (const float*)d_in[6];
    float* out = (float*)d_out;

    // only batch index 7 feeds the output
    const float* in7 = in_features + (size_t)7 * 512 * NPIX;

    int prep_total = WN + OC * PADCH;
    zero_hist_kernel<<<256, 512>>>();                            // 0
    prep_kernel<<<(prep_total + 255) / 256, 256>>>(in7, conv_w); // 1
    setup_misc_kernel<<<1, 256>>>();                             // 2
    conv3_kernel<<<dim3(32, 4), 512>>>(conv_b);                  // 3 <- profiled
    heads_part_kernel<<<dim3(20, 4), 128>>>(reg_w, cls_w);       // 4
    heads_fin_kernel<<<20, 128>>>(reg_b, cls_b);                 // 5
    bucket_sum_kernel<<<256, 256>>>();                           // 6
    bucket_pref_kernel<<<256, 256>>>();                          // 7
    bucket_fill_kernel<<<88, 256>>>();                           // 8
    rank_scatter_kernel<<<88, 256>>>();                          // 9
    nms_mask_kernel<<<dim3(NW, NW), 64>>>();                     // 10
    nms_scan_kernel<<<1, 128>>>();                               // 11
    output_kernel<<<1, 256>>>(out);                              // 12
}

// round 10
// speedup vs baseline: 3.9118x; 1.4185x over previous
#include <cuda_runtime.h>
#include <cstdint>

#define FSZ   50
#define NPIX  2500
#define OC    512
#define KTOT  4608      // 512*9
#define NANCH 22500     // 2500*9
#define PRE   6000
#define NW    94        // ceil(6000/64)
#define ROWS  6016
#define POST  300
#define PADW  52
#define PADCH 2704      // 52*52

// ---------------- scratch (static device allocations) ----------------
__device__ float               g_wre[OC * KTOT];           // weights, k' = r*512+ch
__device__ float               g_inpad[OC * PADCH + 256];  // padded batch-7 input
__device__ float               g_feat[OC * NPIX];
__device__ float4              g_boxes[NANCH];
__device__ unsigned            g_score[NANCH];
__device__ float               g_hpart[4][54 * NPIX];
__device__ unsigned            g_hist[65536];
__device__ unsigned            g_bsum[256];
__device__ unsigned            g_pref[65536];
__device__ unsigned            g_bfill[65536];
__device__ unsigned long long  g_bkey[NANCH];
__device__ float4              g_sbox[ROWS];
__device__ float               g_area[ROWS];
__device__ unsigned long long  g_maskT[(size_t)NW * ROWS];
__device__ unsigned long long  g_keep[NW];

// packed fp32x2 ops (sm_103a — only reachable via PTX)
#define FMA2(c, a, b) asm("fma.rn.f32x2 %0, %1, %2, %3;" : "=l"(c) : "l"(a), "l"(b), "l"(c))
#define ADD2(c, a, b) asm("add.rn.f32x2 %0, %1, %2;" : "=l"(c) : "l"(a), "l"(b))
__device__ __forceinline__ unsigned long long dup2(float x) {
    unsigned long long d;
    asm("mov.b64 %0, {%1, %1};" : "=l"(d) : "f"(x));
    return d;
}
__device__ __forceinline__ uint32_t smem_u32(const void* p) {
    uint32_t a;
    asm("{ .reg .u64 t; cvta.to.shared.u64 t, %1; cvt.u32.u64 %0, t; }" : "=r"(a) : "l"(p));
    return a;
}
#define CPA16(dst, src) asm volatile("cp.async.cg.shared.global [%0], [%1], 16;" :: "r"(dst), "l"(src))
#define CPA4(dst, src)  asm volatile("cp.async.ca.shared.global [%0], [%1], 4;"  :: "r"(dst), "l"(src))
#define CPCOMMIT()      asm volatile("cp.async.commit_group;" ::: "memory")
#define CPWAIT1()       asm volatile("cp.async.wait_group 1;" ::: "memory")

// ---------------- launch 0: zero hist + bucket fill counters ----------------
__global__ void zero_hist_kernel() {
    int i = blockIdx.x * 512 + threadIdx.x;
    if (i < 65536) g_hist[i] = 0u;
    else g_bfill[i - 65536] = 0u;
}

// ---------------- launch 1: prep (weight reorder + input pad) ----------------
#define WN (OC * KTOT)
__global__ void prep_kernel(const float* __restrict__ in7, const float* __restrict__ cw) {
    int i = blockIdx.x * 256 + threadIdx.x;
    if (i < WN) {
        int oc = i / KTOT, rem = i - oc * KTOT;
        int r = rem >> 9, ch = rem & 511;
        g_wre[i] = cw[oc * KTOT + ch * 9 + r];
    } else {
        int j = i - WN;
        if (j >= OC * PADCH) return;
        int c = j / PADCH, rem = j - c * PADCH;
        int y = rem / PADW, x = rem - y * PADW;
        float v = 0.f;
        if (y >= 1 && y <= 50 && x >= 1 && x <= 50)
            v = in7[c * NPIX + (y - 1) * FSZ + (x - 1)];
        g_inpad[j] = v;
    }
}

// ---------------- launch 2: misc setup ----------------
__global__ void setup_misc_kernel() {
    int i = blockIdx.x * 256 + threadIdx.x;
    if (i < ROWS - PRE) {
        g_sbox[PRE + i] = make_float4(0.f, 0.f, 0.f, 0.f);
        g_area[PRE + i] = 1.f;
    }
    if (i < NW) g_keep[i] = 0ull;
}

// ---------------- launch 3: conv 3x3 (batch 7) + leaky relu ----------------
// implicit GEMM 512x2500x4608. CTA tile 128oc x 80px, 512 threads = 2 split-K
// warpgroups x 256. Thread tile 4oc x 5 px-pairs, B pairs strided by 8 so each
// B LDS.64 is a single 64B wavefront. cp.async 2-stage pipeline per wg.
// Stage layout per wg: A [128oc][20f] (10240B) + B [16kk][84f] (5376B).
#define CBK    16
#define NCHK2  144                    // chunks per warpgroup (4608/2/16)
#define STG    15616                  // bytes per stage
#define WGB    31232                  // bytes per wg (2 stages)
#define DSMSZ  62464
extern __shared__ char dsm[];

__global__ __launch_bounds__(512) void conv3_kernel(const float* __restrict__ bias) {
    uint32_t sb = smem_u32(dsm);
    int t = threadIdx.x;
    int wg = t >> 8;                  // 0 / 1
    int wt = t & 255;
    int px0 = blockIdx.x * 80, oc0 = blockIdx.y * 128;
    int og = wt >> 3;                 // 0..31 (4 oc each)
    int pg = wt & 7;                  // 0..7  (pairs pg+8j)
    int wgk0 = wg * 2304;             // k-range start
    uint32_t wgbase = sb + wg * WGB;

    // A staging: 2 x 16B per thread
    int a_oc0 = (wt + 0)   >> 2, a_ks0 = (wt + 0)   & 3;
    int a_oc1 = (wt + 256) >> 2, a_ks1 = (wt + 256) & 3;
    const float* a_src0 = g_wre + (size_t)(oc0 + a_oc0) * KTOT + a_ks0 * 4 + wgk0;
    const float* a_src1 = g_wre + (size_t)(oc0 + a_oc1) * KTOT + a_ks1 * 4 + wgk0;
    uint32_t a_so0 = a_oc0 * 80 + a_ks0 * 16;
    uint32_t a_so1 = a_oc1 * 80 + a_ks1 * 16;

    // B staging: 5 x 4B per thread (1280 granules = 16kk x 80px)
    int b_kk[5], b_pix[5];
    uint32_t b_so[5];
#pragma unroll
    for (int s = 0; s < 5; s++) {
        int g = wt + 256 * s;
        int kk = g / 80, c = g - 80 * kk;
        int p = px0 + c;
        int py = p / 50, px = p - 50 * py;
        b_kk[s] = kk;
        b_pix[s] = py * PADW + px;
        b_so[s] = 10240 + kk * 336 + c * 4;
    }

    unsigned long long acc[4][5];
#pragma unroll
    for (int i = 0; i < 4; i++)
#pragma unroll
        for (int j = 0; j < 5; j++) acc[i][j] = 0ull;

    auto issue = [&](int q, int st) {
        int kb = wgk0 + q * CBK;
        int r = kb >> 9, ch0 = kb & 511;
        int ry = r / 3;
        const float* ib = g_inpad + (size_t)ch0 * PADCH + ry * PADW + (r - 3 * ry);
        uint32_t sbase = wgbase + st * STG;
        CPA16(sbase + a_so0, a_src0 + q * CBK);
        CPA16(sbase + a_so1, a_src1 + q * CBK);
#pragma unroll
        for (int s = 0; s < 5; s++)
            CPA4(sbase + b_so[s], ib + (size_t)b_kk[s] * PADCH + b_pix[s]);
    };

    issue(0, 0); CPCOMMIT();
    issue(1, 1); CPCOMMIT();

    int barid = wg + 1;
    for (int q = 0; q < NCHK2; q++) {
        int st = q & 1;
        CPWAIT1();
        asm volatile("bar.sync %0, 256;" :: "r"(barid) : "memory");
        const float* A_ = (const float*)(dsm + wg * WGB + st * STG);
        const char*  B_ = dsm + wg * WGB + st * STG + 10240;
#pragma unroll
        for (int kk4 = 0; kk4 < CBK; kk4 += 4) {
            float4 av[4];
#pragma unroll
            for (int i = 0; i < 4; i++)
                av[i] = *(const float4*)(A_ + (og * 4 + i) * 20 + kk4);
#pragma unroll
            for (int kk = 0; kk < 4; kk++) {
                unsigned long long b2[5];
                const char* brow = B_ + (kk4 + kk) * 336 + pg * 8;
#pragma unroll
                for (int j = 0; j < 5; j++)
                    b2[j] = *(const unsigned long long*)(brow + j * 64);
#pragma unroll
                for (int i = 0; i < 4; i++) {
                    float afv = (kk == 0) ? av[i].x : (kk == 1) ? av[i].y
                              : (kk == 2) ? av[i].z : av[i].w;
                    unsigned long long da = dup2(afv);
#pragma unroll
                    for (int j = 0; j < 5; j++)
                        FMA2(acc[i][j], da, b2[j]);
                }
            }
        }
        // issue next-next chunk into the stage just freed
        asm volatile("bar.sync %0, 256;" :: "r"(barid) : "memory");
        if (q + 2 < NCHK2) issue(q + 2, st);
        CPCOMMIT();
    }

    // combine split-K halves (reuse stage smem), wg0 finishes
    __syncthreads();
    unsigned long long* epi = (unsigned long long*)dsm;
    if (wg == 1) {
#pragma unroll
        for (int i = 0; i < 4; i++)
#pragma unroll
            for (int j = 0; j < 5; j++) epi[wt * 21 + i * 5 + j] = acc[i][j];
    }
    __syncthreads();
    if (wg == 0) {
#pragma unroll
        for (int i = 0; i < 4; i++) {
            int oc = oc0 + og * 4 + i;
            float bv = bias[oc];
#pragma unroll
            for (int j = 0; j < 5; j++) {
                ADD2(acc[i][j], acc[i][j], epi[wt * 21 + i * 5 + j]);
                int p = px0 + (pg + 8 * j) * 2;
                if (p < NPIX) {
                    float lo, hi;
                    asm("mov.b64 {%0, %1}, %2;" : "=f"(lo), "=f"(hi) : "l"(acc[i][j]));
                    lo += bv; hi += bv;
                    lo = (lo >= 0.f) ? lo : 0.01f * lo;
                    hi = (hi >= 0.f) ? hi : 0.01f * hi;
                    *(float2*)&g_feat[(size_t)oc * NPIX + p] = make_float2(lo, hi);
                }
            }
        }
    }
}

// ---------------- heads part 1: 1x1 convs, 4 channel-group partials ----------------
__global__ __launch_bounds__(128) void heads_part_kernel(const float* __restrict__ reg_w,
                                                         const float* __restrict__ cls_w) {
    __shared__ float wsm[128][56];
    int t = threadIdx.x;
    int cg = blockIdx.y;
    int c0 = cg * 128;
    int p = blockIdx.x * 128 + t;

    for (int i = t; i < 54 * 128; i += 128) {
        int o = i / 128, c = i - o * 128;
        float v = (o < 36) ? reg_w[o * 512 + c0 + c] : cls_w[(o - 36) * 512 + c0 + c];
        wsm[c][o] = v;
    }
    __syncthreads();

    float acc[54];
#pragma unroll
    for (int o = 0; o < 54; o++) acc[o] = 0.f;
    if (p < NPIX) {
        for (int c = 0; c < 128; c++) {
            float f = g_feat[(size_t)(c0 + c) * NPIX + p];
#pragma unroll
            for (int o = 0; o < 54; o++) acc[o] += f * wsm[c][o];
        }
#pragma unroll
        for (int o = 0; o < 54; o++)
            g_hpart[cg][o * NPIX + p] = acc[o];
    }
}

// ---------------- heads part 2: combine + softmax + decode + scores + histogram ----------------
__global__ __launch_bounds__(128) void heads_fin_kernel(const float* __restrict__ reg_b,
                                                        const float* __restrict__ cls_b) {
    int p = blockIdx.x * 128 + threadIdx.x;
    if (p >= NPIX) return;
    float acc[54];
#pragma unroll
    for (int o = 0; o < 54; o++)
        acc[o] = (g_hpart[0][o * NPIX + p] + g_hpart[1][o * NPIX + p]) +
                 (g_hpart[2][o * NPIX + p] + g_hpart[3][o * NPIX + p]);
#pragma unroll
    for (int o = 0; o < 36; o++) acc[o] += reg_b[o];
#pragma unroll
    for (int o = 0; o < 18; o++) acc[36 + o] += cls_b[o];

    int pq = p / FSZ, pr = p - pq * FSZ;
    float cxv = 16.f * (float)pq + 8.f;
    float cyv = 16.f * (float)pr + 8.f;
    const float ssv[3]  = {8.f, 16.f, 32.f};
    const float sqr[3]  = {0.70710678f, 1.0f, 1.41421356f};
    const float sqi[3]  = {1.41421356f, 1.0f, 0.70710678f};
    const float NEGINF = __int_as_float(0xff800000);

#pragma unroll
    for (int k = 0; k < 9; k++) {
        float pr0 = acc[k * 4 + 0], pr1 = acc[k * 4 + 1];
        float pr2 = acc[k * 4 + 2], pr3 = acc[k * 4 + 3];
        float l0 = acc[36 + k * 2], l1 = acc[36 + k * 2 + 1];
        float m  = fmaxf(l0, l1);
        float e0 = expf(l0 - m), e1 = expf(l1 - m);
        float sc = e1 / (e0 + e1);

        int ri = k / 3, si = k - 3 * ri;
        float hk = (16.f * ssv[si]) * sqr[ri];
        float wk = (16.f * ssv[si]) * sqi[ri];
        float ax1 = cxv - wk * 0.5f;
        float ay1 = cyv - hk * 0.5f;
        const float hi = 799.f;
        float rx1 = fminf(fmaxf(pr0 + ax1, 0.f), hi);
        float ry1 = fminf(fmaxf(pr1 + ay1, 0.f), hi);
        float rx2 = fminf(fmaxf(((pr0 + ax1) + pr2) + wk, 0.f), hi);
        float ry2 = fminf(fmaxf(((pr1 + ay1) + pr3) + hk, 0.f), hi);
        float wv = pr2 + wk, hv = pr3 + hk;
        bool valid = (wv >= 16.f) && (hv >= 16.f);
        float s = valid ? sc : NEGINF;

        int a = p * 9 + k;
        g_boxes[a] = make_float4(rx1, ry1, rx2, ry2);
        unsigned u = __float_as_uint(s);
        u = (u >> 31) ? ~u : (u | 0x80000000u);
        g_score[a] = u;
        atomicAdd(&g_hist[u >> 16], 1u);
    }
}

// ---------------- bucket sums (coalesced) ----------------
__global__ __launch_bounds__(256) void bucket_sum_kernel() {
    __shared__ unsigned sh[256];
    int b = blockIdx.x, t = threadIdx.x;
    sh[t] = g_hist[b * 256 + t];
    __syncthreads();
    for (int off = 128; off; off >>= 1) {
        if (t < off) sh[t] += sh[t + off];
        __syncthreads();
    }
    if (t == 0) g_bsum[b] = sh[0];
}

// ---------------- suffix-prefix per bucket (coalesced) ----------------
__global__ __launch_bounds__(256) void bucket_pref_kernel() {
    __shared__ unsigned sh[256];
    __shared__ unsigned above_s;
    int b = blockIdx.x, t = threadIdx.x;
    unsigned v = (t > b) ? g_bsum[t] : 0u;
    sh[t] = v;
    __syncthreads();
    for (int off = 128; off; off >>= 1) {
        if (t < off) sh[t] += sh[t + off];
        __syncthreads();
    }
    if (t == 0) above_s = sh[0];
    __syncthreads();
    unsigned above = above_s;
    unsigned h = g_hist[b * 256 + t];
    __syncthreads();
    sh[t] = h;
    __syncthreads();
    for (int off = 1; off < 256; off <<= 1) {
        unsigned x = (t + off < 256) ? sh[t + off] : 0u;
        __syncthreads();
        sh[t] += x;
        __syncthreads();
    }
    g_pref[b * 256 + t] = above + sh[t] - h;   // count strictly higher
}

// ---------------- bucket fill (only buckets that can reach top-6000) ----------------
__global__ void bucket_fill_kernel() {
    int i = blockIdx.x * 256 + threadIdx.x;
    if (i >= NANCH) return;
    unsigned s = g_score[i];
    unsigned b = s >> 16;
    unsigned base = g_pref[b];
    if (base >= PRE) return;
    unsigned slot = atomicAdd(&g_bfill[b], 1u);
    g_bkey[base + slot] = ((unsigned long long)s << 32) | (unsigned)(~i);
}

// ---------------- exact rank + scatter ----------------
__global__ void rank_scatter_kernel() {
    int i = blockIdx.x * 256 + threadIdx.x;
    if (i >= NANCH) return;
    unsigned s = g_score[i];
    unsigned b = s >> 16;
    unsigned base = g_pref[b];
    if (base >= PRE) return;
    unsigned cnt = g_hist[b];
    unsigned long long my = ((unsigned long long)s << 32) | (unsigned)(~i);
    unsigned r = base;
    for (unsigned q = 0; q < cnt; q++)
        r += (g_bkey[base + q] > my);
    if (r < PRE) {
        float4 bx = g_boxes[i];
        g_sbox[r] = bx;
        g_area[r] = (bx.z - bx.x + 1.f) * (bx.w - bx.y + 1.f);
    }
}

// ---------------- NMS mask, transposed layout (yy2 = max bug preserved) ----------------
__global__ __launch_bounds__(64) void nms_mask_kernel() {
    int gi = blockIdx.y, gj = blockIdx.x;
    if (gj < gi) return;
    __shared__ float4 cbx[64];
    __shared__ float  car[64];
    int t = threadIdx.x;
    int j0 = gj * 64;
    cbx[t] = g_sbox[j0 + t];
    car[t] = g_area[j0 + t];
    __syncthreads();
    int i = gi * 64 + t;
    float4 bi = g_sbox[i];
    float  ai = g_area[i];
    unsigned long long word = 0;
#pragma unroll 8
    for (int jj = 0; jj < 64; jj++) {
        float4 bj = cbx[jj];
        float xx1 = fmaxf(bi.x, bj.x);
        float yy1 = fmaxf(bi.y, bj.y);
        float xx2 = fminf(bi.z, bj.z);
        float yy2 = fmaxf(bi.w, bj.w);   // reference bug: maximum, not minimum
        float w = fmaxf(0.f, xx2 - xx1 + 1.f);
        float h = fmaxf(0.f, yy2 - yy1 + 1.f);
        float inter = w * h;
        float ov = inter / (ai + car[jj] - inter);
        word |= ((unsigned long long)(ov > 0.7f)) << jj;
    }
    g_maskT[(size_t)gj * ROWS + i] = word;   // coalesced across t
}

// ---------------- greedy NMS scan (ffs skip-loop) ----------------
__global__ __launch_bounds__(128) void nms_scan_kernel() {
    __shared__ unsigned long long ms[64];
    __shared__ unsigned long long s_remv, s_kept;
    int t = threadIdx.x;
    unsigned long long remv = 0;                       // thread t owns word g=t
    unsigned long long nextdiag = (t < 64) ? g_maskT[t] : 0ull;
    for (int cb = 0; cb < NW; cb++) {
        if (t < 64) ms[t] = nextdiag;
        if (t == cb) s_remv = remv;
        __syncthreads();
        if (t < 64 && cb + 1 < NW)
            nextdiag = g_maskT[(size_t)(cb + 1) * ROWS + (cb + 1) * 64 + t];
        if (t == 0) {
            unsigned long long v = s_remv, kept = 0ull;
            int lim = PRE - cb * 64; if (lim > 64) lim = 64;
            unsigned long long avail = ~v;
            if (lim < 64) avail &= (1ull << lim) - 1ull;
            while (avail) {
                int j = __ffsll((long long)avail) - 1;
                kept |= 1ull << j;
                v |= ms[j];
                avail &= ~v;
                avail &= (j < 63) ? (~0ull << (j + 1)) : 0ull;
            }
            s_kept = kept;
            g_keep[cb] = kept;
        }
        __syncthreads();
        if (t > cb && t < NW) {
            unsigned long long kk = s_kept;
            const unsigned long long* rowT = g_maskT + (size_t)t * ROWS + cb * 64;
            while (kk) {
                int j0 = __ffsll((long long)kk) - 1; kk &= kk - 1;
                unsigned long long m0 = rowT[j0];
                unsigned long long m1 = 0, m2 = 0, m3 = 0;
                if (kk) { int j1 = __ffsll((long long)kk) - 1; kk &= kk - 1; m1 = rowT[j1]; }
                if (kk) { int j2 = __ffsll((long long)kk) - 1; kk &= kk - 1; m2 = rowT[j2]; }
                if (kk) { int j3 = __ffsll((long long)kk) - 1; kk &= kk - 1; m3 = rowT[j3]; }
                remv |= (m0 | m1) | (m2 | m3);
            }
        }
    }
}

// ---------------- emit top-300 ----------------
__global__ __launch_bounds__(256) void output_kernel(float* __restrict__ out) {
    __shared__ int cnts[256];
    __shared__ int offs[256];
    __shared__ int Ktot;
    int t = threadIdx.x;
    int lo = t * 24;
    int hi = lo + 24; if (hi > PRE) hi = PRE;
    int c = 0;
    for (int i = lo; i < hi; i++)
        c += (int)((g_keep[i >> 6] >> (i & 63)) & 1ull);
    cnts[t] = c;
    __syncthreads();
    if (t == 0) {
        int r = 0;
        for (int q = 0; q < 256; q++) { offs[q] = r; r += cnts[q]; }
        Ktot = r;
    }
    __syncthreads();
    int K = Ktot;
    int pk = offs[t];
    for (int i = lo; i < hi; i++) {
        bool kept = (g_keep[i >> 6] >> (i & 63)) & 1ull;
        int pos = kept ? pk : (K + (i - pk));
        if (kept) pk++;
        if (pos < POST) {
            float4 b = g_sbox[i];
            out[pos * 4 + 0] = b.x;
            out[pos * 4 + 1] = b.y;
            out[pos * 4 + 2] = b.z - b.x + 1.f;
            out[pos * 4 + 3] = b.w - b.y + 1.f;
        }
    }
}

// ---------------- launch ----------------
extern "C" void kernel_launch(void* const* d_in, const int* in_sizes, int n_in,
                              void* d_out, int out_size) {
    const float* in_features = (const float*)d_in[0];
    const float* conv_w = (const float*)d_in[1];
    const float* conv_b = (const float*)d_in[2];
    const float* reg_w  = (const float*)d_in[3];
    const float* reg_b  = (const float*)d_in[4];
    const float* cls_w  = (const float*)d_in[5];
    const float* cls_b  = (const float*)d_in[6];
    float* out = (float*)d_out;

    // only batch index 7 feeds the output
    const float* in7 = in_features + (size_t)7 * 512 * NPIX;

    cudaFuncSetAttribute(conv3_kernel,
                         cudaFuncAttributeMaxDynamicSharedMemorySize, DSMSZ);

    int prep_total = WN + OC * PADCH;
    zero_hist_kernel<<<256, 512>>>();                            // 0
    prep_kernel<<<(prep_total + 255) / 256, 256>>>(in7, conv_w); // 1
    setup_misc_kernel<<<1, 256>>>();                             // 2
    conv3_kernel<<<dim3(32, 4), 512, DSMSZ>>>(conv_b);           // 3 <- profiled
    heads_part_kernel<<<dim3(20, 4), 128>>>(reg_w, cls_w);       // 4
    heads_fin_kernel<<<20, 128>>>(reg_b, cls_b);                 // 5
    bucket_sum_kernel<<<256, 256>>>();                           // 6
    bucket_pref_kernel<<<256, 256>>>();                          // 7
    bucket_fill_kernel<<<88, 256>>>();                           // 8
    rank_scatter_kernel<<<88, 256>>>();                          // 9
    nms_mask_kernel<<<dim3(NW, NW), 64>>>();                     // 10
    nms_scan_kernel<<<1, 128>>>();                               // 11
    output_kernel<<<1, 256>>>(out);                              // 12
}

// round 11
// speedup vs baseline: 3.9242x; 1.0032x over previous
#include <cuda_runtime.h>
#include <cstdint>

#define FSZ   50
#define NPIX  2500
#define OC    512
#define KTOT  4608      // 512*9
#define NANCH 22500     // 2500*9
#define PRE   6000
#define NW    94        // ceil(6000/64)
#define ROWS  6016
#define POST  300
#define PADW  52
#define PADCH 2704      // 52*52

// ---------------- scratch (static device allocations) ----------------
__device__ float               g_wre[OC * KTOT];           // weights, k' = r*512+ch
__device__ float               g_inpad[OC * PADCH + 256];  // padded batch-7 input
__device__ float               g_feat[OC * NPIX];
__device__ float4              g_boxes[NANCH];
__device__ unsigned            g_score[NANCH];
__device__ float               g_hpart[4][54 * NPIX];
__device__ unsigned            g_hist[65536];
__device__ unsigned            g_bsum[256];
__device__ unsigned            g_pref[65536];
__device__ unsigned            g_bfill[65536];
__device__ unsigned long long  g_bkey[NANCH];
__device__ float4              g_sbox[ROWS];
__device__ float               g_area[ROWS];
__device__ unsigned long long  g_maskT[(size_t)NW * ROWS];
__device__ unsigned long long  g_keep[NW];

// packed fp32x2 ops (sm_103a — only reachable via PTX)
#define FMA2(c, a, b) asm("fma.rn.f32x2 %0, %1, %2, %3;" : "=l"(c) : "l"(a), "l"(b), "l"(c))
#define ADD2(c, a, b) asm("add.rn.f32x2 %0, %1, %2;" : "=l"(c) : "l"(a), "l"(b))
__device__ __forceinline__ unsigned long long dup2(float x) {
    unsigned long long d;
    asm("mov.b64 %0, {%1, %1};" : "=l"(d) : "f"(x));
    return d;
}
__device__ __forceinline__ uint32_t smem_u32(const void* p) {
    uint32_t a;
    asm("{ .reg .u64 t; cvta.to.shared.u64 t, %1; cvt.u32.u64 %0, t; }" : "=r"(a) : "l"(p));
    return a;
}
#define CPA16(dst, src) asm volatile("cp.async.cg.shared.global [%0], [%1], 16;" :: "r"(dst), "l"(src))
#define CPA4(dst, src)  asm volatile("cp.async.ca.shared.global [%0], [%1], 4;"  :: "r"(dst), "l"(src))
#define CPCOMMIT()      asm volatile("cp.async.commit_group;" ::: "memory")
#define CPWAIT1()       asm volatile("cp.async.wait_group 1;" ::: "memory")

// ---------------- launch 0: zero hist + bucket fill counters ----------------
__global__ void zero_hist_kernel() {
    int i = blockIdx.x * 512 + threadIdx.x;
    if (i < 65536) g_hist[i] = 0u;
    else g_bfill[i - 65536] = 0u;
}

// ---------------- launch 1: prep (weight reorder + input pad) ----------------
#define WN (OC * KTOT)
__global__ void prep_kernel(const float* __restrict__ in7, const float* __restrict__ cw) {
    int i = blockIdx.x * 256 + threadIdx.x;
    if (i < WN) {
        int oc = i / KTOT, rem = i - oc * KTOT;
        int r = rem >> 9, ch = rem & 511;
        g_wre[i] = cw[oc * KTOT + ch * 9 + r];
    } else {
        int j = i - WN;
        if (j >= OC * PADCH) return;
        int c = j / PADCH, rem = j - c * PADCH;
        int y = rem / PADW, x = rem - y * PADW;
        float v = 0.f;
        if (y >= 1 && y <= 50 && x >= 1 && x <= 50)
            v = in7[c * NPIX + (y - 1) * FSZ + (x - 1)];
        g_inpad[j] = v;
    }
}

// ---------------- launch 2: misc setup ----------------
__global__ void setup_misc_kernel() {
    int i = blockIdx.x * 256 + threadIdx.x;
    if (i < ROWS - PRE) {
        g_sbox[PRE + i] = make_float4(0.f, 0.f, 0.f, 0.f);
        g_area[PRE + i] = 1.f;
    }
    if (i < NW) g_keep[i] = 0ull;
}

// ---------------- launch 3: conv 3x3 (batch 7) + leaky relu ----------------
// implicit GEMM 512x2500x4608. CTA tile 128oc x 80px, 512 threads = 2 split-K
// warpgroups x 256. Thread tile 4oc x 5 px-pairs; B pairs strided by 8 (one
// 64B wavefront per LDS.64); b2 double-buffered one kk ahead to cover LDS
// latency with FFMA2s. cp.async 2-stage pipeline per wg, named barriers.
#define CBK    16
#define NCHK2  144                    // chunks per warpgroup (4608/2/16)
#define STG    15616                  // bytes per stage
#define WGB    31232                  // bytes per wg (2 stages)
#define DSMSZ  62464
extern __shared__ char dsm[];

__global__ __launch_bounds__(512) void conv3_kernel(const float* __restrict__ bias) {
    uint32_t sb = smem_u32(dsm);
    int t = threadIdx.x;
    int wg = t >> 8;                  // 0 / 1
    int wt = t & 255;
    int px0 = blockIdx.x * 80, oc0 = blockIdx.y * 128;
    int og = wt >> 3;                 // 0..31 (4 oc each)
    int pg = wt & 7;                  // 0..7  (pairs pg+8j)
    int wgk0 = wg * 2304;             // k-range start
    uint32_t wgbase = sb + wg * WGB;

    // A staging: 2 x 16B per thread
    int a_oc0 = (wt + 0)   >> 2, a_ks0 = (wt + 0)   & 3;
    int a_oc1 = (wt + 256) >> 2, a_ks1 = (wt + 256) & 3;
    const float* a_src0 = g_wre + (size_t)(oc0 + a_oc0) * KTOT + a_ks0 * 4 + wgk0;
    const float* a_src1 = g_wre + (size_t)(oc0 + a_oc1) * KTOT + a_ks1 * 4 + wgk0;
    uint32_t a_so0 = a_oc0 * 80 + a_ks0 * 16;
    uint32_t a_so1 = a_oc1 * 80 + a_ks1 * 16;

    // B staging: 5 x 4B per thread (1280 granules = 16kk x 80px)
    int b_kk[5], b_pix[5];
    uint32_t b_so[5];
#pragma unroll
    for (int s = 0; s < 5; s++) {
        int g = wt + 256 * s;
        int kk = g / 80, c = g - 80 * kk;
        int p = px0 + c;
        int py = p / 50, px = p - 50 * py;
        b_kk[s] = kk;
        b_pix[s] = py * PADW + px;
        b_so[s] = 10240 + kk * 336 + c * 4;
    }

    unsigned long long acc[4][5];
#pragma unroll
    for (int i = 0; i < 4; i++)
#pragma unroll
        for (int j = 0; j < 5; j++) acc[i][j] = 0ull;

    auto issue = [&](int q, int st) {
        int kb = wgk0 + q * CBK;
        int r = kb >> 9, ch0 = kb & 511;
        int ry = r / 3;
        const float* ib = g_inpad + (size_t)ch0 * PADCH + ry * PADW + (r - 3 * ry);
        uint32_t sbase = wgbase + st * STG;
        CPA16(sbase + a_so0, a_src0 + q * CBK);
        CPA16(sbase + a_so1, a_src1 + q * CBK);
#pragma unroll
        for (int s = 0; s < 5; s++)
            CPA4(sbase + b_so[s], ib + (size_t)b_kk[s] * PADCH + b_pix[s]);
    };

    issue(0, 0); CPCOMMIT();
    issue(1, 1); CPCOMMIT();

    int barid = wg + 1;
    for (int q = 0; q < NCHK2; q++) {
        int st = q & 1;
        CPWAIT1();
        asm volatile("bar.sync %0, 256;" :: "r"(barid) : "memory");
        const float* A_ = (const float*)(dsm + wg * WGB + st * STG) + og * 80;
        const char*  B_ = dsm + wg * WGB + st * STG + 10240 + pg * 8;

        // b2 double buffer: preload kk=0
        unsigned long long b2c[5], b2n[5];
#pragma unroll
        for (int j = 0; j < 5; j++)
            b2c[j] = *(const unsigned long long*)(B_ + j * 64);

#pragma unroll
        for (int kk4 = 0; kk4 < CBK; kk4 += 4) {
            float4 av[4];
#pragma unroll
            for (int i = 0; i < 4; i++)
                av[i] = *(const float4*)(A_ + i * 20 + kk4);
#pragma unroll
            for (int kk = 0; kk < 4; kk++) {
                int gk = kk4 + kk;
                if (gk < CBK - 1) {
                    const char* brow = B_ + (gk + 1) * 336;
#pragma unroll
                    for (int j = 0; j < 5; j++)
                        b2n[j] = *(const unsigned long long*)(brow + j * 64);
                }
#pragma unroll
                for (int i = 0; i < 4; i++) {
                    float afv = (kk == 0) ? av[i].x : (kk == 1) ? av[i].y
                              : (kk == 2) ? av[i].z : av[i].w;
                    unsigned long long da = dup2(afv);
#pragma unroll
                    for (int j = 0; j < 5; j++)
                        FMA2(acc[i][j], da, b2c[j]);
                }
                if (gk < CBK - 1) {
#pragma unroll
                    for (int j = 0; j < 5; j++) b2c[j] = b2n[j];
                }
            }
        }
        // issue next-next chunk into the stage just freed
        asm volatile("bar.sync %0, 256;" :: "r"(barid) : "memory");
        if (q + 2 < NCHK2) issue(q + 2, st);
        CPCOMMIT();
    }

    // combine split-K halves (reuse stage smem), wg0 finishes
    __syncthreads();
    unsigned long long* epi = (unsigned long long*)dsm;
    if (wg == 1) {
#pragma unroll
        for (int i = 0; i < 4; i++)
#pragma unroll
            for (int j = 0; j < 5; j++) epi[wt * 21 + i * 5 + j] = acc[i][j];
    }
    __syncthreads();
    if (wg == 0) {
#pragma unroll
        for (int i = 0; i < 4; i++) {
            int oc = oc0 + og * 4 + i;
            float bv = bias[oc];
#pragma unroll
            for (int j = 0; j < 5; j++) {
                ADD2(acc[i][j], acc[i][j], epi[wt * 21 + i * 5 + j]);
                int p = px0 + (pg + 8 * j) * 2;
                if (p < NPIX) {
                    float lo, hi;
                    asm("mov.b64 {%0, %1}, %2;" : "=f"(lo), "=f"(hi) : "l"(acc[i][j]));
                    lo += bv; hi += bv;
                    lo = (lo >= 0.f) ? lo : 0.01f * lo;
                    hi = (hi >= 0.f) ? hi : 0.01f * hi;
                    *(float2*)&g_feat[(size_t)oc * NPIX + p] = make_float2(lo, hi);
                }
            }
        }
    }
}

// ---------------- heads part 1: 1x1 convs, 4 channel-group partials ----------------
// grid (37, 4): 148 blocks (one per SM), 68 px per block.
__global__ __launch_bounds__(128) void heads_part_kernel(const float* __restrict__ reg_w,
                                                         const float* __restrict__ cls_w) {
    __shared__ float wsm[128][56];
    int t = threadIdx.x;
    int cg = blockIdx.y;
    int c0 = cg * 128;
    int p = blockIdx.x * 68 + t;
    bool act = (t < 68) && (p < NPIX);

    for (int i = t; i < 54 * 128; i += 128) {
        int o = i / 128, c = i - o * 128;
        float v = (o < 36) ? reg_w[o * 512 + c0 + c] : cls_w[(o - 36) * 512 + c0 + c];
        wsm[c][o] = v;
    }
    __syncthreads();

    float acc[54];
#pragma unroll
    for (int o = 0; o < 54; o++) acc[o] = 0.f;
    if (act) {
        for (int c = 0; c < 128; c++) {
            float f = g_feat[(size_t)(c0 + c) * NPIX + p];
#pragma unroll
            for (int o = 0; o < 54; o++) acc[o] += f * wsm[c][o];
        }
#pragma unroll
        for (int o = 0; o < 54; o++)
            g_hpart[cg][o * NPIX + p] = acc[o];
    }
}

// ---------------- heads part 2: combine + softmax + decode + scores + histogram ----------------
__global__ __launch_bounds__(128) void heads_fin_kernel(const float* __restrict__ reg_b,
                                                        const float* __restrict__ cls_b) {
    int p = blockIdx.x * 128 + threadIdx.x;
    if (p >= NPIX) return;
    float acc[54];
#pragma unroll
    for (int o = 0; o < 54; o++)
        acc[o] = (g_hpart[0][o * NPIX + p] + g_hpart[1][o * NPIX + p]) +
                 (g_hpart[2][o * NPIX + p] + g_hpart[3][o * NPIX + p]);
#pragma unroll
    for (int o = 0; o < 36; o++) acc[o] += reg_b[o];
#pragma unroll
    for (int o = 0; o < 18; o++) acc[36 + o] += cls_b[o];

    int pq = p / FSZ, pr = p - pq * FSZ;
    float cxv = 16.f * (float)pq + 8.f;
    float cyv = 16.f * (float)pr + 8.f;
    const float ssv[3]  = {8.f, 16.f, 32.f};
    const float sqr[3]  = {0.70710678f, 1.0f, 1.41421356f};
    const float sqi[3]  = {1.41421356f, 1.0f, 0.70710678f};
    const float NEGINF = __int_as_float(0xff800000);

#pragma unroll
    for (int k = 0; k < 9; k++) {
        float pr0 = acc[k * 4 + 0], pr1 = acc[k * 4 + 1];
        float pr2 = acc[k * 4 + 2], pr3 = acc[k * 4 + 3];
        float l0 = acc[36 + k * 2], l1 = acc[36 + k * 2 + 1];
        float m  = fmaxf(l0, l1);
        float e0 = expf(l0 - m), e1 = expf(l1 - m);
        float sc = e1 / (e0 + e1);

        int ri = k / 3, si = k - 3 * ri;
        float hk = (16.f * ssv[si]) * sqr[ri];
        float wk = (16.f * ssv[si]) * sqi[ri];
        float ax1 = cxv - wk * 0.5f;
        float ay1 = cyv - hk * 0.5f;
        const float hi = 799.f;
        float rx1 = fminf(fmaxf(pr0 + ax1, 0.f), hi);
        float ry1 = fminf(fmaxf(pr1 + ay1, 0.f), hi);
        float rx2 = fminf(fmaxf(((pr0 + ax1) + pr2) + wk, 0.f), hi);
        float ry2 = fminf(fmaxf(((pr1 + ay1) + pr3) + hk, 0.f), hi);
        float wv = pr2 + wk, hv = pr3 + hk;
        bool valid = (wv >= 16.f) && (hv >= 16.f);
        float s = valid ? sc : NEGINF;

        int a = p * 9 + k;
        g_boxes[a] = make_float4(rx1, ry1, rx2, ry2);
        unsigned u = __float_as_uint(s);
        u = (u >> 31) ? ~u : (u | 0x80000000u);
        g_score[a] = u;
        atomicAdd(&g_hist[u >> 16], 1u);
    }
}

// ---------------- bucket sums (coalesced) ----------------
__global__ __launch_bounds__(256) void bucket_sum_kernel() {
    __shared__ unsigned sh[256];
    int b = blockIdx.x, t = threadIdx.x;
    sh[t] = g_hist[b * 256 + t];
    __syncthreads();
    for (int off = 128; off; off >>= 1) {
        if (t < off) sh[t] += sh[t + off];
        __syncthreads();
    }
    if (t == 0) g_bsum[b] = sh[0];
}

// ---------------- suffix-prefix per bucket (coalesced) ----------------
__global__ __launch_bounds__(256) void bucket_pref_kernel() {
    __shared__ unsigned sh[256];
    __shared__ unsigned above_s;
    int b = blockIdx.x, t = threadIdx.x;
    unsigned v = (t > b) ? g_bsum[t] : 0u;
    sh[t] = v;
    __syncthreads();
    for (int off = 128; off; off >>= 1) {
        if (t < off) sh[t] += sh[t + off];
        __syncthreads();
    }
    if (t == 0) above_s = sh[0];
    __syncthreads();
    unsigned above = above_s;
    unsigned h = g_hist[b * 256 + t];
    __syncthreads();
    sh[t] = h;
    __syncthreads();
    for (int off = 1; off < 256; off <<= 1) {
        unsigned x = (t + off < 256) ? sh[t + off] : 0u;
        __syncthreads();
        sh[t] += x;
        __syncthreads();
    }
    g_pref[b * 256 + t] = above + sh[t] - h;   // count strictly higher
}

// ---------------- bucket fill (only buckets that can reach top-6000) ----------------
__global__ void bucket_fill_kernel() {
    int i = blockIdx.x * 256 + threadIdx.x;
    if (i >= NANCH) return;
    unsigned s = g_score[i];
    unsigned b = s >> 16;
    unsigned base = g_pref[b];
    if (base >= PRE) return;
    unsigned slot = atomicAdd(&g_bfill[b], 1u);
    g_bkey[base + slot] = ((unsigned long long)s << 32) | (unsigned)(~i);
}

// ---------------- exact rank + scatter ----------------
__global__ void rank_scatter_kernel() {
    int i = blockIdx.x * 256 + threadIdx.x;
    if (i >= NANCH) return;
    unsigned s = g_score[i];
    unsigned b = s >> 16;
    unsigned base = g_pref[b];
    if (base >= PRE) return;
    unsigned cnt = g_hist[b];
    unsigned long long my = ((unsigned long long)s << 32) | (unsigned)(~i);
    unsigned r = base;
    for (unsigned q = 0; q < cnt; q++)
        r += (g_bkey[base + q] > my);
    if (r < PRE) {
        float4 bx = g_boxes[i];
        g_sbox[r] = bx;
        g_area[r] = (bx.z - bx.x + 1.f) * (bx.w - bx.y + 1.f);
    }
}

// ---------------- NMS mask, transposed layout (yy2 = max bug preserved) ----------------
__global__ __launch_bounds__(64) void nms_mask_kernel() {
    int gi = blockIdx.y, gj = blockIdx.x;
    if (gj < gi) return;
    __shared__ float4 cbx[64];
    __shared__ float  car[64];
    int t = threadIdx.x;
    int j0 = gj * 64;
    cbx[t] = g_sbox[j0 + t];
    car[t] = g_area[j0 + t];
    __syncthreads();
    int i = gi * 64 + t;
    float4 bi = g_sbox[i];
    float  ai = g_area[i];
    unsigned long long word = 0;
#pragma unroll 8
    for (int jj = 0; jj < 64; jj++) {
        float4 bj = cbx[jj];
        float xx1 = fmaxf(bi.x, bj.x);
        float yy1 = fmaxf(bi.y, bj.y);
        float xx2 = fminf(bi.z, bj.z);
        float yy2 = fmaxf(bi.w, bj.w);   // reference bug: maximum, not minimum
        float w = fmaxf(0.f, xx2 - xx1 + 1.f);
        float h = fmaxf(0.f, yy2 - yy1 + 1.f);
        float inter = w * h;
        float ov = inter / (ai + car[jj] - inter);
        word |= ((unsigned long long)(ov > 0.7f)) << jj;
    }
    g_maskT[(size_t)gj * ROWS + i] = word;   // coalesced across t
}

// ---------------- greedy NMS scan (ffs skip-loop, 8-wide MLP) ----------------
__global__ __launch_bounds__(128) void nms_scan_kernel() {
    __shared__ unsigned long long ms[64];
    __shared__ unsigned long long s_remv, s_kept;
    int t = threadIdx.x;
    unsigned long long remv = 0;                       // thread t owns word g=t
    unsigned long long nextdiag = (t < 64) ? g_maskT[t] : 0ull;
    for (int cb = 0; cb < NW; cb++) {
        if (t < 64) ms[t] = nextdiag;
        if (t == cb) s_remv = remv;
        __syncthreads();
        if (t < 64 && cb + 1 < NW)
            nextdiag = g_maskT[(size_t)(cb + 1) * ROWS + (cb + 1) * 64 + t];
        if (t == 0) {
            unsigned long long v = s_remv, kept = 0ull;
            int lim = PRE - cb * 64; if (lim > 64) lim = 64;
            unsigned long long avail = ~v;
            if (lim < 64) avail &= (1ull << lim) - 1ull;
            while (avail) {
                int j = __ffsll((long long)avail) - 1;
                kept |= 1ull << j;
                v |= ms[j];
                avail &= ~v;
                avail &= (j < 63) ? (~0ull << (j + 1)) : 0ull;
            }
            s_kept = kept;
            g_keep[cb] = kept;
        }
        __syncthreads();
        if (t > cb && t < NW) {
            unsigned long long kk = s_kept;
            const unsigned long long* rowT = g_maskT + (size_t)t * ROWS + cb * 64;
            while (kk) {
                unsigned long long m[8];
#pragma unroll
                for (int u = 0; u < 8; u++) m[u] = 0ull;
#pragma unroll
                for (int u = 0; u < 8; u++) {
                    if (!kk) break;
                    int j = __ffsll((long long)kk) - 1; kk &= kk - 1;
                    m[u] = rowT[j];
                }
                remv |= ((m[0] | m[1]) | (m[2] | m[3])) |
                        ((m[4] | m[5]) | (m[6] | m[7]));
            }
        }
    }
}

// ---------------- emit top-300 ----------------
__global__ __launch_bounds__(256) void output_kernel(float* __restrict__ out) {
    __shared__ int cnts[256];
    __shared__ int offs[256];
    __shared__ int Ktot;
    int t = threadIdx.x;
    int lo = t * 24;
    int hi = lo + 24; if (hi > PRE) hi = PRE;
    int c = 0;
    for (int i = lo; i < hi; i++)
        c += (int)((g_keep[i >> 6] >> (i & 63)) & 1ull);
    cnts[t] = c;
    __syncthreads();
    if (t == 0) {
        int r = 0;
        for (int q = 0; q < 256; q++) { offs[q] = r; r += cnts[q]; }
        Ktot = r;
    }
    __syncthreads();
    int K = Ktot;
    int pk = offs[t];
    for (int i = lo; i < hi; i++) {
        bool kept = (g_keep[i >> 6] >> (i & 63)) & 1ull;
        int pos = kept ? pk : (K + (i - pk));
        if (kept) pk++;
        if (pos < POST) {
            float4 b = g_sbox[i];
            out[pos * 4 + 0] = b.x;
            out[pos * 4 + 1] = b.y;
            out[pos * 4 + 2] = b.z - b.x + 1.f;
            out[pos * 4 + 3] = b.w - b.y + 1.f;
        }
    }
}

// ---------------- launch ----------------
extern "C" void kernel_launch(void* const* d_in, const int* in_sizes, int n_in,
                              void* d_out, int out_size) {
    const float* in_features = (const float*)d_in[0];
    const float* conv_w = (const float*)d_in[1];
    const float* conv_b = (const float*)d_in[2];
    const float* reg_w  = (const float*)d_in[3];
    const float* reg_b  = (const float*)d_in[4];
    const float* cls_w  = (const float*)d_in[5];
    const float* cls_b  = (const float*)d_in[6];
    float* out = (float*)d_out;

    // only batch index 7 feeds the output
    const float* in7 = in_features + (size_t)7 * 512 * NPIX;

    cudaFuncSetAttribute(conv3_kernel,
                         cudaFuncAttributeMaxDynamicSharedMemorySize, DSMSZ);

    int prep_total = WN + OC * PADCH;
    zero_hist_kernel<<<256, 512>>>();                            // 0
    prep_kernel<<<(prep_total + 255) / 256, 256>>>(in7, conv_w); // 1
    setup_misc_kernel<<<1, 256>>>();                             // 2
    conv3_kernel<<<dim3(32, 4), 512, DSMSZ>>>(conv_b);           // 3 <- profiled
    heads_part_kernel<<<dim3(37, 4), 128>>>(reg_w, cls_w);       // 4
    heads_fin_kernel<<<20, 128>>>(reg_b, cls_b);                 // 5
    bucket_sum_kernel<<<256, 256>>>();                           // 6
    bucket_pref_kernel<<<256, 256>>>();                          // 7
    bucket_fill_kernel<<<88, 256>>>();                           // 8
    rank_scatter_kernel<<<88, 256>>>();                          // 9
    nms_mask_kernel<<<dim3(NW, NW), 64>>>();                     // 10
    nms_scan_kernel<<<1, 128>>>();                               // 11
    output_kernel<<<1, 256>>>(out);                              // 12
}

// round 12
// speedup vs baseline: 3.9520x; 1.0071x over previous
#include <cuda_runtime.h>
#include <cstdint>

#define FSZ   50
#define NPIX  2500
#define OC    512
#define KTOT  4608      // 512*9
#define NANCH 22500     // 2500*9
#define PRE   6000
#define NW    94        // ceil(6000/64)
#define ROWS  6016
#define POST  300
#define PADW  52
#define PADCH 2704      // 52*52

// ---------------- scratch (static device allocations) ----------------
__device__ float               g_wre[OC * KTOT];           // weights, k' = r*512+ch
__device__ float               g_inpad[OC * PADCH + 256];  // padded batch-7 input
__device__ float               g_feat[OC * NPIX];
__device__ float4              g_boxes[NANCH];
__device__ unsigned            g_score[NANCH];
__device__ float               g_hpart[4][54 * NPIX];
__device__ unsigned            g_hist[65536];
__device__ unsigned            g_bsum[256];
__device__ unsigned            g_pref[65536];
__device__ unsigned            g_bfill[65536];
__device__ unsigned long long  g_bkey[NANCH];
__device__ float4              g_sbox[ROWS];
__device__ float               g_area[ROWS];
__device__ unsigned long long  g_maskT[(size_t)NW * ROWS];
__device__ unsigned long long  g_keep[NW];

// packed fp32x2 ops (sm_103a — only reachable via PTX)
#define FMA2(c, a, b) asm("fma.rn.f32x2 %0, %1, %2, %3;" : "=l"(c) : "l"(a), "l"(b), "l"(c))
#define ADD2(c, a, b) asm("add.rn.f32x2 %0, %1, %2;" : "=l"(c) : "l"(a), "l"(b))
__device__ __forceinline__ unsigned long long dup2(float x) {
    unsigned long long d;
    asm("mov.b64 %0, {%1, %1};" : "=l"(d) : "f"(x));
    return d;
}
__device__ __forceinline__ uint32_t smem_u32(const void* p) {
    uint32_t a;
    asm("{ .reg .u64 t; cvta.to.shared.u64 t, %1; cvt.u32.u64 %0, t; }" : "=r"(a) : "l"(p));
    return a;
}
#define CPA16(dst, src) asm volatile("cp.async.cg.shared.global [%0], [%1], 16;" :: "r"(dst), "l"(src))
#define CPA4(dst, src)  asm volatile("cp.async.ca.shared.global [%0], [%1], 4;"  :: "r"(dst), "l"(src))
#define CPCOMMIT()      asm volatile("cp.async.commit_group;" ::: "memory")
#define CPWAIT1()       asm volatile("cp.async.wait_group 1;" ::: "memory")

// ---------------- launch 0: zero hist + bucket fill counters ----------------
__global__ void zero_hist_kernel() {
    int i = blockIdx.x * 512 + threadIdx.x;
    if (i < 65536) g_hist[i] = 0u;
    else g_bfill[i - 65536] = 0u;
}

// ---------------- launch 1: prep (weight reorder + input pad) ----------------
#define WN (OC * KTOT)
__global__ void prep_kernel(const float* __restrict__ in7, const float* __restrict__ cw) {
    int i = blockIdx.x * 256 + threadIdx.x;
    if (i < WN) {
        int oc = i / KTOT, rem = i - oc * KTOT;
        int r = rem >> 9, ch = rem & 511;
        g_wre[i] = cw[oc * KTOT + ch * 9 + r];
    } else {
        int j = i - WN;
        if (j >= OC * PADCH) return;
        int c = j / PADCH, rem = j - c * PADCH;
        int y = rem / PADW, x = rem - y * PADW;
        float v = 0.f;
        if (y >= 1 && y <= 50 && x >= 1 && x <= 50)
            v = in7[c * NPIX + (y - 1) * FSZ + (x - 1)];
        g_inpad[j] = v;
    }
}

// ---------------- launch 2: misc setup ----------------
__global__ void setup_misc_kernel() {
    int i = blockIdx.x * 256 + threadIdx.x;
    if (i < ROWS - PRE) {
        g_sbox[PRE + i] = make_float4(0.f, 0.f, 0.f, 0.f);
        g_area[PRE + i] = 1.f;
    }
    if (i < NW) g_keep[i] = 0ull;
}

// ---------------- launch 3: conv 3x3 (batch 7) + leaky relu ----------------
// implicit GEMM 512x2500x4608. CTA = 256 threads = 2 split-K warpgroups x 128.
// CTA tile 64oc x 80px; grid (32,8) = 256 CTAs -> 2 CTAs/SM (independent
// barrier/pipeline domains cover each other's stalls). Thread tile 4oc x 5
// px-pairs (pairs pg+8j). A tile og-group-swizzled: group(4 rows) stride 352B,
// row 80B -> conflict-free LDS.128. cp.async 2-stage pipeline per wg.
#define CBK    16
#define NCHK2  144                    // chunks per warpgroup (4608/2/16)
#define A_TILE 5632                   // 16 og-groups * 352B
#define B_OFF  5632
#define STG    11008                  // A 5632 + B 5376
#define WGB    22016                  // 2 stages
#define DSMSZ  44032
extern __shared__ char dsm[];

__global__ __launch_bounds__(256, 2) void conv3_kernel(const float* __restrict__ bias) {
    uint32_t sb = smem_u32(dsm);
    int t = threadIdx.x;
    int wg = t >> 7;                  // 0 / 1
    int wt = t & 127;
    int px0 = blockIdx.x * 80, oc0 = blockIdx.y * 64;
    int og = wt >> 3;                 // 0..15 (4 oc each)
    int pg = wt & 7;                  // 0..7  (pairs pg+8j)
    int wgk0 = wg * 2304;             // k-range start
    uint32_t wgbase = sb + wg * WGB;

    // A staging: 2 x 16B granules per thread (64oc x 4ks = 256 granules)
    int a_oc0 = wt >> 2,          a_ks0 = wt & 3;
    int a_oc1 = (wt + 128) >> 2,  a_ks1 = (wt + 128) & 3;
    const float* a_src0 = g_wre + (size_t)(oc0 + a_oc0) * KTOT + a_ks0 * 4 + wgk0;
    const float* a_src1 = g_wre + (size_t)(oc0 + a_oc1) * KTOT + a_ks1 * 4 + wgk0;
    uint32_t a_so0 = (a_oc0 >> 2) * 352 + (a_oc0 & 3) * 80 + a_ks0 * 16;
    uint32_t a_so1 = (a_oc1 >> 2) * 352 + (a_oc1 & 3) * 80 + a_ks1 * 16;

    // B staging: 10 x 4B per thread (1280 granules = 16kk x 80px)
    int b_kk[10], b_pix[10];
    uint32_t b_so[10];
#pragma unroll
    for (int s = 0; s < 10; s++) {
        int g = wt + 128 * s;
        int kk = g / 80, c = g - 80 * kk;
        int p = px0 + c;
        int py = p / 50, px = p - 50 * py;
        b_kk[s] = kk;
        b_pix[s] = py * PADW + px;
        b_so[s] = B_OFF + kk * 336 + c * 4;
    }

    unsigned long long acc[4][5];
#pragma unroll
    for (int i = 0; i < 4; i++)
#pragma unroll
        for (int j = 0; j < 5; j++) acc[i][j] = 0ull;

    auto issue = [&](int q, int st) {
        int kb = wgk0 + q * CBK;
        int r = kb >> 9, ch0 = kb & 511;
        int ry = r / 3;
        const float* ib = g_inpad + (size_t)ch0 * PADCH + ry * PADW + (r - 3 * ry);
        uint32_t sbase = wgbase + st * STG;
        CPA16(sbase + a_so0, a_src0 + q * CBK);
        CPA16(sbase + a_so1, a_src1 + q * CBK);
#pragma unroll
        for (int s = 0; s < 10; s++)
            CPA4(sbase + b_so[s], ib + (size_t)b_kk[s] * PADCH + b_pix[s]);
    };

    issue(0, 0); CPCOMMIT();
    issue(1, 1); CPCOMMIT();

    int barid = wg + 1;
    for (int q = 0; q < NCHK2; q++) {
        int st = q & 1;
        CPWAIT1();
        asm volatile("bar.sync %0, 128;" :: "r"(barid) : "memory");
        const float* A_ = (const float*)(dsm + wg * WGB + st * STG) + og * 88;
        const char*  B_ = dsm + wg * WGB + st * STG + B_OFF + pg * 8;

        // b2 double buffer: preload kk=0
        unsigned long long b2c[5], b2n[5];
#pragma unroll
        for (int j = 0; j < 5; j++)
            b2c[j] = *(const unsigned long long*)(B_ + j * 64);

#pragma unroll
        for (int kk4 = 0; kk4 < CBK; kk4 += 4) {
            float4 av[4];
#pragma unroll
            for (int i = 0; i < 4; i++)
                av[i] = *(const float4*)(A_ + i * 20 + kk4);
#pragma unroll
            for (int kk = 0; kk < 4; kk++) {
                int gk = kk4 + kk;
                if (gk < CBK - 1) {
                    const char* brow = B_ + (gk + 1) * 336;
#pragma unroll
                    for (int j = 0; j < 5; j++)
                        b2n[j] = *(const unsigned long long*)(brow + j * 64);
                }
#pragma unroll
                for (int i = 0; i < 4; i++) {
                    float afv = (kk == 0) ? av[i].x : (kk == 1) ? av[i].y
                              : (kk == 2) ? av[i].z : av[i].w;
                    unsigned long long da = dup2(afv);
#pragma unroll
                    for (int j = 0; j < 5; j++)
                        FMA2(acc[i][j], da, b2c[j]);
                }
                if (gk < CBK - 1) {
#pragma unroll
                    for (int j = 0; j < 5; j++) b2c[j] = b2n[j];
                }
            }
        }
        // issue next-next chunk into the stage just freed
        asm volatile("bar.sync %0, 128;" :: "r"(barid) : "memory");
        if (q + 2 < NCHK2) issue(q + 2, st);
        CPCOMMIT();
    }

    // combine split-K halves (reuse stage smem), wg0 finishes
    __syncthreads();
    unsigned long long* epi = (unsigned long long*)dsm;
    if (wg == 1) {
#pragma unroll
        for (int i = 0; i < 4; i++)
#pragma unroll
            for (int j = 0; j < 5; j++) epi[wt * 21 + i * 5 + j] = acc[i][j];
    }
    __syncthreads();
    if (wg == 0) {
#pragma unroll
        for (int i = 0; i < 4; i++) {
            int oc = oc0 + og * 4 + i;
            float bv = bias[oc];
#pragma unroll
            for (int j = 0; j < 5; j++) {
                ADD2(acc[i][j], acc[i][j], epi[wt * 21 + i * 5 + j]);
                int p = px0 + (pg + 8 * j) * 2;
                if (p < NPIX) {
                    float lo, hi;
                    asm("mov.b64 {%0, %1}, %2;" : "=f"(lo), "=f"(hi) : "l"(acc[i][j]));
                    lo += bv; hi += bv;
                    lo = (lo >= 0.f) ? lo : 0.01f * lo;
                    hi = (hi >= 0.f) ? hi : 0.01f * hi;
                    *(float2*)&g_feat[(size_t)oc * NPIX + p] = make_float2(lo, hi);
                }
            }
        }
    }
}

// ---------------- heads part 1: 1x1 convs, 4 channel-group partials ----------------
// grid (37, 4): 148 blocks (one per SM), 68 px per block.
__global__ __launch_bounds__(128) void heads_part_kernel(const float* __restrict__ reg_w,
                                                         const float* __restrict__ cls_w) {
    __shared__ float wsm[128][56];
    int t = threadIdx.x;
    int cg = blockIdx.y;
    int c0 = cg * 128;
    int p = blockIdx.x * 68 + t;
    bool act = (t < 68) && (p < NPIX);

    for (int i = t; i < 54 * 128; i += 128) {
        int o = i / 128, c = i - o * 128;
        float v = (o < 36) ? reg_w[o * 512 + c0 + c] : cls_w[(o - 36) * 512 + c0 + c];
        wsm[c][o] = v;
    }
    __syncthreads();

    float acc[54];
#pragma unroll
    for (int o = 0; o < 54; o++) acc[o] = 0.f;
    if (act) {
        for (int c = 0; c < 128; c++) {
            float f = g_feat[(size_t)(c0 + c) * NPIX + p];
#pragma unroll
            for (int o = 0; o < 54; o++) acc[o] += f * wsm[c][o];
        }
#pragma unroll
        for (int o = 0; o < 54; o++)
            g_hpart[cg][o * NPIX + p] = acc[o];
    }
}

// ---------------- heads part 2: combine + softmax + decode + scores + histogram ----------------
__global__ __launch_bounds__(128) void heads_fin_kernel(const float* __restrict__ reg_b,
                                                        const float* __restrict__ cls_b) {
    int p = blockIdx.x * 128 + threadIdx.x;
    if (p >= NPIX) return;
    float acc[54];
#pragma unroll
    for (int o = 0; o < 54; o++)
        acc[o] = (g_hpart[0][o * NPIX + p] + g_hpart[1][o * NPIX + p]) +
                 (g_hpart[2][o * NPIX + p] + g_hpart[3][o * NPIX + p]);
#pragma unroll
    for (int o = 0; o < 36; o++) acc[o] += reg_b[o];
#pragma unroll
    for (int o = 0; o < 18; o++) acc[36 + o] += cls_b[o];

    int pq = p / FSZ, pr = p - pq * FSZ;
    float cxv = 16.f * (float)pq + 8.f;
    float cyv = 16.f * (float)pr + 8.f;
    const float ssv[3]  = {8.f, 16.f, 32.f};
    const float sqr[3]  = {0.70710678f, 1.0f, 1.41421356f};
    const float sqi[3]  = {1.41421356f, 1.0f, 0.70710678f};
    const float NEGINF = __int_as_float(0xff800000);

#pragma unroll
    for (int k = 0; k < 9; k++) {
        float pr0 = acc[k * 4 + 0], pr1 = acc[k * 4 + 1];
        float pr2 = acc[k * 4 + 2], pr3 = acc[k * 4 + 3];
        float l0 = acc[36 + k * 2], l1 = acc[36 + k * 2 + 1];
        float m  = fmaxf(l0, l1);
        float e0 = expf(l0 - m), e1 = expf(l1 - m);
        float sc = e1 / (e0 + e1);

        int ri = k / 3, si = k - 3 * ri;
        float hk = (16.f * ssv[si]) * sqr[ri];
        float wk = (16.f * ssv[si]) * sqi[ri];
        float ax1 = cxv - wk * 0.5f;
        float ay1 = cyv - hk * 0.5f;
        const float hi = 799.f;
        float rx1 = fminf(fmaxf(pr0 + ax1, 0.f), hi);
        float ry1 = fminf(fmaxf(pr1 + ay1, 0.f), hi);
        float rx2 = fminf(fmaxf(((pr0 + ax1) + pr2) + wk, 0.f), hi);
        float ry2 = fminf(fmaxf(((pr1 + ay1) + pr3) + hk, 0.f), hi);
        float wv = pr2 + wk, hv = pr3 + hk;
        bool valid = (wv >= 16.f) && (hv >= 16.f);
        float s = valid ? sc : NEGINF;

        int a = p * 9 + k;
        g_boxes[a] = make_float4(rx1, ry1, rx2, ry2);
        unsigned u = __float_as_uint(s);
        u = (u >> 31) ? ~u : (u | 0x80000000u);
        g_score[a] = u;
        atomicAdd(&g_hist[u >> 16], 1u);
    }
}

// ---------------- bucket sums (coalesced) ----------------
__global__ __launch_bounds__(256) void bucket_sum_kernel() {
    __shared__ unsigned sh[256];
    int b = blockIdx.x, t = threadIdx.x;
    sh[t] = g_hist[b * 256 + t];
    __syncthreads();
    for (int off = 128; off; off >>= 1) {
        if (t < off) sh[t] += sh[t + off];
        __syncthreads();
    }
    if (t == 0) g_bsum[b] = sh[0];
}

// ---------------- suffix-prefix per bucket (coalesced) ----------------
__global__ __launch_bounds__(256) void bucket_pref_kernel() {
    __shared__ unsigned sh[256];
    __shared__ unsigned above_s;
    int b = blockIdx.x, t = threadIdx.x;
    unsigned v = (t > b) ? g_bsum[t] : 0u;
    sh[t] = v;
    __syncthreads();
    for (int off = 128; off; off >>= 1) {
        if (t < off) sh[t] += sh[t + off];
        __syncthreads();
    }
    if (t == 0) above_s = sh[0];
    __syncthreads();
    unsigned above = above_s;
    unsigned h = g_hist[b * 256 + t];
    __syncthreads();
    sh[t] = h;
    __syncthreads();
    for (int off = 1; off < 256; off <<= 1) {
        unsigned x = (t + off < 256) ? sh[t + off] : 0u;
        __syncthreads();
        sh[t] += x;
        __syncthreads();
    }
    g_pref[b * 256 + t] = above + sh[t] - h;   // count strictly higher
}

// ---------------- bucket fill (only buckets that can reach top-6000) ----------------
__global__ void bucket_fill_kernel() {
    int i = blockIdx.x * 256 + threadIdx.x;
    if (i >= NANCH) return;
    unsigned s = g_score[i];
    unsigned b = s >> 16;
    unsigned base = g_pref[b];
    if (base >= PRE) return;
    unsigned slot = atomicAdd(&g_bfill[b], 1u);
    g_bkey[base + slot] = ((unsigned long long)s << 32) | (unsigned)(~i);
}

// ---------------- exact rank + scatter ----------------
__global__ void rank_scatter_kernel() {
    int i = blockIdx.x * 256 + threadIdx.x;
    if (i >= NANCH) return;
    unsigned s = g_score[i];
    unsigned b = s >> 16;
    unsigned base = g_pref[b];
    if (base >= PRE) return;
    unsigned cnt = g_hist[b];
    unsigned long long my = ((unsigned long long)s << 32) | (unsigned)(~i);
    unsigned r = base;
    for (unsigned q = 0; q < cnt; q++)
        r += (g_bkey[base + q] > my);
    if (r < PRE) {
        float4 bx = g_boxes[i];
        g_sbox[r] = bx;
        g_area[r] = (bx.z - bx.x + 1.f) * (bx.w - bx.y + 1.f);
    }
}

// ---------------- NMS mask, transposed layout (yy2 = max bug preserved) ----------------
__global__ __launch_bounds__(64) void nms_mask_kernel() {
    int gi = blockIdx.y, gj = blockIdx.x;
    if (gj < gi) return;
    __shared__ float4 cbx[64];
    __shared__ float  car[64];
    int t = threadIdx.x;
    int j0 = gj * 64;
    cbx[t] = g_sbox[j0 + t];
    car[t] = g_area[j0 + t];
    __syncthreads();
    int i = gi * 64 + t;
    float4 bi = g_sbox[i];
    float  ai = g_area[i];
    unsigned long long word = 0;
#pragma unroll 8
    for (int jj = 0; jj < 64; jj++) {
        float4 bj = cbx[jj];
        float xx1 = fmaxf(bi.x, bj.x);
        float yy1 = fmaxf(bi.y, bj.y);
        float xx2 = fminf(bi.z, bj.z);
        float yy2 = fmaxf(bi.w, bj.w);   // reference bug: maximum, not minimum
        float w = fmaxf(0.f, xx2 - xx1 + 1.f);
        float h = fmaxf(0.f, yy2 - yy1 + 1.f);
        float inter = w * h;
        float ov = inter / (ai + car[jj] - inter);
        word |= ((unsigned long long)(ov > 0.7f)) << jj;
    }
    g_maskT[(size_t)gj * ROWS + i] = word;   // coalesced across t
}

// ---------------- greedy NMS scan (ffs skip-loop, 8-wide MLP) ----------------
__global__ __launch_bounds__(128) void nms_scan_kernel() {
    __shared__ unsigned long long ms[64];
    __shared__ unsigned long long s_remv, s_kept;
    int t = threadIdx.x;
    unsigned long long remv = 0;                       // thread t owns word g=t
    unsigned long long nextdiag = (t < 64) ? g_maskT[t] : 0ull;
    for (int cb = 0; cb < NW; cb++) {
        if (t < 64) ms[t] = nextdiag;
        if (t == cb) s_remv = remv;
        __syncthreads();
        if (t < 64 && cb + 1 < NW)
            nextdiag = g_maskT[(size_t)(cb + 1) * ROWS + (cb + 1) * 64 + t];
        if (t == 0) {
            unsigned long long v = s_remv, kept = 0ull;
            int lim = PRE - cb * 64; if (lim > 64) lim = 64;
            unsigned long long avail = ~v;
            if (lim < 64) avail &= (1ull << lim) - 1ull;
            while (avail) {
                int j = __ffsll((long long)avail) - 1;
                kept |= 1ull << j;
                v |= ms[j];
                avail &= ~v;
                avail &= (j < 63) ? (~0ull << (j + 1)) : 0ull;
            }
            s_kept = kept;
            g_keep[cb] = kept;
        }
        __syncthreads();
        if (t > cb && t < NW) {
            unsigned long long kk = s_kept;
            const unsigned long long* rowT = g_maskT + (size_t)t * ROWS + cb * 64;
            while (kk) {
                unsigned long long m[8];
#pragma unroll
                for (int u = 0; u < 8; u++) m[u] = 0ull;
#pragma unroll
                for (int u = 0; u < 8; u++) {
                    if (!kk) break;
                    int j = __ffsll((long long)kk) - 1; kk &= kk - 1;
                    m[u] = rowT[j];
                }
                remv |= ((m[0] | m[1]) | (m[2] | m[3])) |
                        ((m[4] | m[5]) | (m[6] | m[7]));
            }
        }
    }
}

// ---------------- emit top-300 ----------------
__global__ __launch_bounds__(256) void output_kernel(float* __restrict__ out) {
    __shared__ int cnts[256];
    __shared__ int offs[256];
    __shared__ int Ktot;
    int t = threadIdx.x;
    int lo = t * 24;
    int hi = lo + 24; if (hi > PRE) hi = PRE;
    int c = 0;
    for (int i = lo; i < hi; i++)
        c += (int)((g_keep[i >> 6] >> (i & 63)) & 1ull);
    cnts[t] = c;
    __syncthreads();
    if (t == 0) {
        int r = 0;
        for (int q = 0; q < 256; q++) { offs[q] = r; r += cnts[q]; }
        Ktot = r;
    }
    __syncthreads();
    int K = Ktot;
    int pk = offs[t];
    for (int i = lo; i < hi; i++) {
        bool kept = (g_keep[i >> 6] >> (i & 63)) & 1ull;
        int pos = kept ? pk : (K + (i - pk));
        if (kept) pk++;
        if (pos < POST) {
            float4 b = g_sbox[i];
            out[pos * 4 + 0] = b.x;
            out[pos * 4 + 1] = b.y;
            out[pos * 4 + 2] = b.z - b.x + 1.f;
            out[pos * 4 + 3] = b.w - b.y + 1.f;
        }
    }
}

// ---------------- launch ----------------
extern "C" void kernel_launch(void* const* d_in, const int* in_sizes, int n_in,
                              void* d_out, int out_size) {
    const float* in_features = (const float*)d_in[0];
    const float* conv_w = (const float*)d_in[1];
    const float* conv_b = (const float*)d_in[2];
    const float* reg_w  = (const float*)d_in[3];
    const float* reg_b  = (const float*)d_in[4];
    const float* cls_w  = (const float*)d_in[5];
    const float* cls_b  = (const float*)d_in[6];
    float* out = (float*)d_out;

    // only batch index 7 feeds the output
    const float* in7 = in_features + (size_t)7 * 512 * NPIX;

    cudaFuncSetAttribute(conv3_kernel,
                         cudaFuncAttributeMaxDynamicSharedMemorySize, DSMSZ);

    int prep_total = WN + OC * PADCH;
    zero_hist_kernel<<<256, 512>>>();                            // 0
    prep_kernel<<<(prep_total + 255) / 256, 256>>>(in7, conv_w); // 1
    setup_misc_kernel<<<1, 256>>>();                             // 2
    conv3_kernel<<<dim3(32, 8), 256, DSMSZ>>>(conv_b);           // 3 <- profiled
    heads_part_kernel<<<dim3(37, 4), 128>>>(reg_w, cls_w);       // 4
    heads_fin_kernel<<<20, 128>>>(reg_b, cls_b);                 // 5
    bucket_sum_kernel<<<256, 256>>>();                           // 6
    bucket_pref_kernel<<<256, 256>>>();                          // 7
    bucket_fill_kernel<<<88, 256>>>();                           // 8
    rank_scatter_kernel<<<88, 256>>>();                          // 9
    nms_mask_kernel<<<dim3(NW, NW), 64>>>();                     // 10
    nms_scan_kernel<<<1, 128>>>();                               // 11
    output_kernel<<<1, 256>>>(out);                              // 12
}

// round 13
// speedup vs baseline: 4.0990x; 1.0372x over previous
#include <cuda_runtime.h>
#include <cstdint>

#define FSZ   50
#define NPIX  2500
#define OC    512
#define KTOT  4608      // 512*9
#define NANCH 22500     // 2500*9
#define PRE   6000
#define NW    94        // ceil(6000/64)
#define ROWS  6016
#define POST  300
#define PADW  52
#define PADCH 2704      // 52*52

// ---------------- scratch (static device allocations) ----------------
__device__ float               g_wre[OC * KTOT];           // weights, k' = r*512+ch
__device__ float               g_inpad[OC * PADCH + 256];  // padded batch-7 input
__device__ float               g_feat[OC * NPIX];
__device__ float4              g_boxes[NANCH];
__device__ unsigned            g_score[NANCH];
__device__ float               g_hpart[4][54 * NPIX];
__device__ unsigned            g_hist[65536];
__device__ unsigned            g_bsum[256];
__device__ unsigned            g_pref[65536];
__device__ unsigned            g_bfill[65536];
__device__ unsigned long long  g_bkey[NANCH];
__device__ float4              g_sbox[ROWS];
__device__ float               g_area[ROWS];
__device__ unsigned long long  g_maskT[(size_t)NW * ROWS];
__device__ unsigned long long  g_keep[NW];

// packed fp32x2 ops (sm_103a — only reachable via PTX)
#define FMA2(c, a, b) asm("fma.rn.f32x2 %0, %1, %2, %3;" : "=l"(c) : "l"(a), "l"(b), "l"(c))
#define ADD2(c, a, b) asm("add.rn.f32x2 %0, %1, %2;" : "=l"(c) : "l"(a), "l"(b))
__device__ __forceinline__ unsigned long long dup2(float x) {
    unsigned long long d;
    asm("mov.b64 %0, {%1, %1};" : "=l"(d) : "f"(x));
    return d;
}
__device__ __forceinline__ uint32_t smem_u32(const void* p) {
    uint32_t a;
    asm("{ .reg .u64 t; cvta.to.shared.u64 t, %1; cvt.u32.u64 %0, t; }" : "=r"(a) : "l"(p));
    return a;
}
#define CPA16(dst, src) asm volatile("cp.async.cg.shared.global [%0], [%1], 16;" :: "r"(dst), "l"(src))
#define CPA4(dst, src)  asm volatile("cp.async.ca.shared.global [%0], [%1], 4;"  :: "r"(dst), "l"(src))
#define CPCOMMIT()      asm volatile("cp.async.commit_group;" ::: "memory")
#define CPWAIT1()       asm volatile("cp.async.wait_group 1;" ::: "memory")

// ---------------- launch 0: zero hist + bucket fill counters ----------------
__global__ void zero_hist_kernel() {
    int i = blockIdx.x * 512 + threadIdx.x;
    if (i < 65536) g_hist[i] = 0u;
    else g_bfill[i - 65536] = 0u;
}

// ---------------- launch 1: prep (weight reorder + input pad) ----------------
#define WN (OC * KTOT)
__global__ void prep_kernel(const float* __restrict__ in7, const float* __restrict__ cw) {
    int i = blockIdx.x * 256 + threadIdx.x;
    if (i < WN) {
        int oc = i / KTOT, rem = i - oc * KTOT;
        int r = rem >> 9, ch = rem & 511;
        g_wre[i] = cw[oc * KTOT + ch * 9 + r];
    } else {
        int j = i - WN;
        if (j >= OC * PADCH) return;
        int c = j / PADCH, rem = j - c * PADCH;
        int y = rem / PADW, x = rem - y * PADW;
        float v = 0.f;
        if (y >= 1 && y <= 50 && x >= 1 && x <= 50)
            v = in7[c * NPIX + (y - 1) * FSZ + (x - 1)];
        g_inpad[j] = v;
    }
}

// ---------------- launch 2: misc setup ----------------
__global__ void setup_misc_kernel() {
    int i = blockIdx.x * 256 + threadIdx.x;
    if (i < ROWS - PRE) {
        g_sbox[PRE + i] = make_float4(0.f, 0.f, 0.f, 0.f);
        g_area[PRE + i] = 1.f;
    }
    if (i < NW) g_keep[i] = 0ull;
}

// ---------------- launch 3: conv 3x3 (batch 7) + leaky relu ----------------
// implicit GEMM 512x2500x4608. CTA = 256 threads = 2 split-K warpgroups x 128.
// CTA tile 64oc x 80px; grid (32,8) = 256 CTAs -> 2 CTAs/SM. Thread tile 4oc x
// 5 px-pairs, pairs {2pg, 2pg+1, 16+2pg, 17+2pg, 32+pg} so B reads are two
// LDS.128 (1 wavefront each) + one LDS.64 -> 3 wf/kk (was 5). A og-group
// swizzle (352B group stride) keeps A LDS.128 conflict-free.
#define CBK    16
#define NCHK2  144                    // chunks per warpgroup (4608/2/16)
#define A_TILE 5632                   // 16 og-groups * 352B
#define B_OFF  5632
#define STG    11008                  // A 5632 + B 5376
#define WGB    22016                  // 2 stages
#define DSMSZ  44032
extern __shared__ char dsm[];

__global__ __launch_bounds__(256, 2) void conv3_kernel(const float* __restrict__ bias) {
    uint32_t sb = smem_u32(dsm);
    int t = threadIdx.x;
    int wg = t >> 7;                  // 0 / 1
    int wt = t & 127;
    int px0 = blockIdx.x * 80, oc0 = blockIdx.y * 64;
    int og = wt >> 3;                 // 0..15 (4 oc each)
    int pg = wt & 7;                  // 0..7
    int wgk0 = wg * 2304;             // k-range start
    uint32_t wgbase = sb + wg * WGB;

    // pair indices handled by this thread
    int prs[5] = {2 * pg, 2 * pg + 1, 16 + 2 * pg, 17 + 2 * pg, 32 + pg};

    // A staging: 2 x 16B granules per thread (64oc x 4ks = 256 granules)
    int a_oc0 = wt >> 2,          a_ks0 = wt & 3;
    int a_oc1 = (wt + 128) >> 2,  a_ks1 = (wt + 128) & 3;
    const float* a_src0 = g_wre + (size_t)(oc0 + a_oc0) * KTOT + a_ks0 * 4 + wgk0;
    const float* a_src1 = g_wre + (size_t)(oc0 + a_oc1) * KTOT + a_ks1 * 4 + wgk0;
    uint32_t a_so0 = (a_oc0 >> 2) * 352 + (a_oc0 & 3) * 80 + a_ks0 * 16;
    uint32_t a_so1 = (a_oc1 >> 2) * 352 + (a_oc1 & 3) * 80 + a_ks1 * 16;

    // B staging: 10 x 4B per thread (1280 granules = 16kk x 80px, linear c*4)
    int b_kk[10], b_pix[10];
    uint32_t b_so[10];
#pragma unroll
    for (int s = 0; s < 10; s++) {
        int g = wt + 128 * s;
        int kk = g / 80, c = g - 80 * kk;
        int p = px0 + c;
        int py = p / 50, px = p - 50 * py;
        b_kk[s] = kk;
        b_pix[s] = py * PADW + px;
        b_so[s] = B_OFF + kk * 336 + c * 4;
    }

    unsigned long long acc[4][5];
#pragma unroll
    for (int i = 0; i < 4; i++)
#pragma unroll
        for (int j = 0; j < 5; j++) acc[i][j] = 0ull;

    auto issue = [&](int q, int st) {
        int kb = wgk0 + q * CBK;
        int r = kb >> 9, ch0 = kb & 511;
        int ry = r / 3;
        const float* ib = g_inpad + (size_t)ch0 * PADCH + ry * PADW + (r - 3 * ry);
        uint32_t sbase = wgbase + st * STG;
        CPA16(sbase + a_so0, a_src0 + q * CBK);
        CPA16(sbase + a_so1, a_src1 + q * CBK);
#pragma unroll
        for (int s = 0; s < 10; s++)
            CPA4(sbase + b_so[s], ib + (size_t)b_kk[s] * PADCH + b_pix[s]);
    };

    issue(0, 0); CPCOMMIT();
    issue(1, 1); CPCOMMIT();

    int barid = wg + 1;
    for (int q = 0; q < NCHK2; q++) {
        int st = q & 1;
        CPWAIT1();
        asm volatile("bar.sync %0, 128;" :: "r"(barid) : "memory");
        const float* A_ = (const float*)(dsm + wg * WGB + st * STG) + og * 88;
        const char*  B_ = dsm + wg * WGB + st * STG + B_OFF;

        // b2 double buffer: preload kk=0 (2x LDS.128 + 1x LDS.64)
        unsigned long long b2c[5], b2n[5];
        {
            ulonglong2 u0 = *(const ulonglong2*)(B_ + pg * 16);
            ulonglong2 u1 = *(const ulonglong2*)(B_ + 128 + pg * 16);
            b2c[0] = u0.x; b2c[1] = u0.y;
            b2c[2] = u1.x; b2c[3] = u1.y;
            b2c[4] = *(const unsigned long long*)(B_ + 256 + pg * 8);
        }

#pragma unroll
        for (int kk4 = 0; kk4 < CBK; kk4 += 4) {
            float4 av[4];
#pragma unroll
            for (int i = 0; i < 4; i++)
                av[i] = *(const float4*)(A_ + i * 20 + kk4);
#pragma unroll
            for (int kk = 0; kk < 4; kk++) {
                int gk = kk4 + kk;
                if (gk < CBK - 1) {
                    const char* brow = B_ + (gk + 1) * 336;
                    ulonglong2 u0 = *(const ulonglong2*)(brow + pg * 16);
                    ulonglong2 u1 = *(const ulonglong2*)(brow + 128 + pg * 16);
                    b2n[0] = u0.x; b2n[1] = u0.y;
                    b2n[2] = u1.x; b2n[3] = u1.y;
                    b2n[4] = *(const unsigned long long*)(brow + 256 + pg * 8);
                }
#pragma unroll
                for (int i = 0; i < 4; i++) {
                    float afv = (kk == 0) ? av[i].x : (kk == 1) ? av[i].y
                              : (kk == 2) ? av[i].z : av[i].w;
                    unsigned long long da = dup2(afv);
#pragma unroll
                    for (int j = 0; j < 5; j++)
                        FMA2(acc[i][j], da, b2c[j]);
                }
                if (gk < CBK - 1) {
#pragma unroll
                    for (int j = 0; j < 5; j++) b2c[j] = b2n[j];
                }
            }
        }
        // issue next-next chunk into the stage just freed
        asm volatile("bar.sync %0, 128;" :: "r"(barid) : "memory");
        if (q + 2 < NCHK2) issue(q + 2, st);
        CPCOMMIT();
    }

    // combine split-K halves (reuse stage smem), wg0 finishes
    __syncthreads();
    unsigned long long* epi = (unsigned long long*)dsm;
    if (wg == 1) {
#pragma unroll
        for (int i = 0; i < 4; i++)
#pragma unroll
            for (int j = 0; j < 5; j++) epi[wt * 21 + i * 5 + j] = acc[i][j];
    }
    __syncthreads();
    if (wg == 0) {
#pragma unroll
        for (int i = 0; i < 4; i++) {
            int oc = oc0 + og * 4 + i;
            float bv = bias[oc];
#pragma unroll
            for (int j = 0; j < 5; j++) {
                ADD2(acc[i][j], acc[i][j], epi[wt * 21 + i * 5 + j]);
                int p = px0 + 2 * prs[j];
                if (p < NPIX) {   // NPIX even -> pair-granular validity
                    float lo, hi;
                    asm("mov.b64 {%0, %1}, %2;" : "=f"(lo), "=f"(hi) : "l"(acc[i][j]));
                    lo += bv; hi += bv;
                    lo = (lo >= 0.f) ? lo : 0.01f * lo;
                    hi = (hi >= 0.f) ? hi : 0.01f * hi;
                    *(float2*)&g_feat[(size_t)oc * NPIX + p] = make_float2(lo, hi);
                }
            }
        }
    }
}

// ---------------- heads part 1: 1x1 convs, 4 channel-group partials ----------------
// grid (37, 4): 148 blocks (one per SM), 68 px per block.
__global__ __launch_bounds__(128) void heads_part_kernel(const float* __restrict__ reg_w,
                                                         const float* __restrict__ cls_w) {
    __shared__ float wsm[128][56];
    int t = threadIdx.x;
    int cg = blockIdx.y;
    int c0 = cg * 128;
    int p = blockIdx.x * 68 + t;
    bool act = (t < 68) && (p < NPIX);

    for (int i = t; i < 54 * 128; i += 128) {
        int o = i / 128, c = i - o * 128;
        float v = (o < 36) ? reg_w[o * 512 + c0 + c] : cls_w[(o - 36) * 512 + c0 + c];
        wsm[c][o] = v;
    }
    __syncthreads();

    float acc[54];
#pragma unroll
    for (int o = 0; o < 54; o++) acc[o] = 0.f;
    if (act) {
        for (int c = 0; c < 128; c++) {
            float f = g_feat[(size_t)(c0 + c) * NPIX + p];
#pragma unroll
            for (int o = 0; o < 54; o++) acc[o] += f * wsm[c][o];
        }
#pragma unroll
        for (int o = 0; o < 54; o++)
            g_hpart[cg][o * NPIX + p] = acc[o];
    }
}

// ---------------- heads part 2: combine + softmax + decode + scores + histogram ----------------
__global__ __launch_bounds__(128) void heads_fin_kernel(const float* __restrict__ reg_b,
                                                        const float* __restrict__ cls_b) {
    int p = blockIdx.x * 128 + threadIdx.x;
    if (p >= NPIX) return;
    float acc[54];
#pragma unroll
    for (int o = 0; o < 54; o++)
        acc[o] = (g_hpart[0][o * NPIX + p] + g_hpart[1][o * NPIX + p]) +
                 (g_hpart[2][o * NPIX + p] + g_hpart[3][o * NPIX + p]);
#pragma unroll
    for (int o = 0; o < 36; o++) acc[o] += reg_b[o];
#pragma unroll
    for (int o = 0; o < 18; o++) acc[36 + o] += cls_b[o];

    int pq = p / FSZ, pr = p - pq * FSZ;
    float cxv = 16.f * (float)pq + 8.f;
    float cyv = 16.f * (float)pr + 8.f;
    const float ssv[3]  = {8.f, 16.f, 32.f};
    const float sqr[3]  = {0.70710678f, 1.0f, 1.41421356f};
    const float sqi[3]  = {1.41421356f, 1.0f, 0.70710678f};
    const float NEGINF = __int_as_float(0xff800000);

#pragma unroll
    for (int k = 0; k < 9; k++) {
        float pr0 = acc[k * 4 + 0], pr1 = acc[k * 4 + 1];
        float pr2 = acc[k * 4 + 2], pr3 = acc[k * 4 + 3];
        float l0 = acc[36 + k * 2], l1 = acc[36 + k * 2 + 1];
        float m  = fmaxf(l0, l1);
        float e0 = expf(l0 - m), e1 = expf(l1 - m);
        float sc = e1 / (e0 + e1);

        int ri = k / 3, si = k - 3 * ri;
        float hk = (16.f * ssv[si]) * sqr[ri];
        float wk = (16.f * ssv[si]) * sqi[ri];
        float ax1 = cxv - wk * 0.5f;
        float ay1 = cyv - hk * 0.5f;
        const float hi = 799.f;
        float rx1 = fminf(fmaxf(pr0 + ax1, 0.f), hi);
        float ry1 = fminf(fmaxf(pr1 + ay1, 0.f), hi);
        float rx2 = fminf(fmaxf(((pr0 + ax1) + pr2) + wk, 0.f), hi);
        float ry2 = fminf(fmaxf(((pr1 + ay1) + pr3) + hk, 0.f), hi);
        float wv = pr2 + wk, hv = pr3 + hk;
        bool valid = (wv >= 16.f) && (hv >= 16.f);
        float s = valid ? sc : NEGINF;

        int a = p * 9 + k;
        g_boxes[a] = make_float4(rx1, ry1, rx2, ry2);
        unsigned u = __float_as_uint(s);
        u = (u >> 31) ? ~u : (u | 0x80000000u);
        g_score[a] = u;
        atomicAdd(&g_hist[u >> 16], 1u);
    }
}

// ---------------- bucket sums (coalesced) ----------------
__global__ __launch_bounds__(256) void bucket_sum_kernel() {
    __shared__ unsigned sh[256];
    int b = blockIdx.x, t = threadIdx.x;
    sh[t] = g_hist[b * 256 + t];
    __syncthreads();
    for (int off = 128; off; off >>= 1) {
        if (t < off) sh[t] += sh[t + off];
        __syncthreads();
    }
    if (t == 0) g_bsum[b] = sh[0];
}

// ---------------- suffix-prefix per bucket (coalesced) ----------------
__global__ __launch_bounds__(256) void bucket_pref_kernel() {
    __shared__ unsigned sh[256];
    __shared__ unsigned above_s;
    int b = blockIdx.x, t = threadIdx.x;
    unsigned v = (t > b) ? g_bsum[t] : 0u;
    sh[t] = v;
    __syncthreads();
    for (int off = 128; off; off >>= 1) {
        if (t < off) sh[t] += sh[t + off];
        __syncthreads();
    }
    if (t == 0) above_s = sh[0];
    __syncthreads();
    unsigned above = above_s;
    unsigned h = g_hist[b * 256 + t];
    __syncthreads();
    sh[t] = h;
    __syncthreads();
    for (int off = 1; off < 256; off <<= 1) {
        unsigned x = (t + off < 256) ? sh[t + off] : 0u;
        __syncthreads();
        sh[t] += x;
        __syncthreads();
    }
    g_pref[b * 256 + t] = above + sh[t] - h;   // count strictly higher
}

// ---------------- bucket fill (only buckets that can reach top-6000) ----------------
__global__ void bucket_fill_kernel() {
    int i = blockIdx.x * 256 + threadIdx.x;
    if (i >= NANCH) return;
    unsigned s = g_score[i];
    unsigned b = s >> 16;
    unsigned base = g_pref[b];
    if (base >= PRE) return;
    unsigned slot = atomicAdd(&g_bfill[b], 1u);
    g_bkey[base + slot] = ((unsigned long long)s << 32) | (unsigned)(~i);
}

// ---------------- exact rank + scatter ----------------
__global__ void rank_scatter_kernel() {
    int i = blockIdx.x * 256 + threadIdx.x;
    if (i >= NANCH) return;
    unsigned s = g_score[i];
    unsigned b = s >> 16;
    unsigned base = g_pref[b];
    if (base >= PRE) return;
    unsigned cnt = g_hist[b];
    unsigned long long my = ((unsigned long long)s << 32) | (unsigned)(~i);
    unsigned r = base;
    for (unsigned q = 0; q < cnt; q++)
        r += (g_bkey[base + q] > my);
    if (r < PRE) {
        float4 bx = g_boxes[i];
        g_sbox[r] = bx;
        g_area[r] = (bx.z - bx.x + 1.f) * (bx.w - bx.y + 1.f);
    }
}

// ---------------- NMS mask, transposed layout (yy2 = max bug preserved) ----------------
// division-free: ov > 0.7  <=>  (den>0 && inter > 0.7*den) || (den==0 && inter>0)
// (den<0 -> ov<0 -> no suppress; den==0: inter>0 -> +inf -> suppress, inter==0 -> nan -> no)
__global__ __launch_bounds__(64) void nms_mask_kernel() {
    int gi = blockIdx.y, gj = blockIdx.x;
    if (gj < gi) return;
    __shared__ float4 cbx[64];
    __shared__ float  car[64];
    int t = threadIdx.x;
    int j0 = gj * 64;
    cbx[t] = g_sbox[j0 + t];
    car[t] = g_area[j0 + t];
    __syncthreads();
    int i = gi * 64 + t;
    float4 bi = g_sbox[i];
    float  ai = g_area[i];
    unsigned long long word = 0;
#pragma unroll 8
    for (int jj = 0; jj < 64; jj++) {
        float4 bj = cbx[jj];
        float xx1 = fmaxf(bi.x, bj.x);
        float yy1 = fmaxf(bi.y, bj.y);
        float xx2 = fminf(bi.z, bj.z);
        float yy2 = fmaxf(bi.w, bj.w);   // reference bug: maximum, not minimum
        float w = fmaxf(0.f, xx2 - xx1 + 1.f);
        float h = fmaxf(0.f, yy2 - yy1 + 1.f);
        float inter = w * h;
        float den = ai + car[jj] - inter;
        bool sup = (den > 0.f) ? (inter > 0.7f * den) : ((den == 0.f) && (inter > 0.f));
        word |= ((unsigned long long)sup) << jj;
    }
    g_maskT[(size_t)gj * ROWS + i] = word;   // coalesced across t
}

// ---------------- greedy NMS scan (ffs skip-loop, 8-wide MLP) ----------------
__global__ __launch_bounds__(128) void nms_scan_kernel() {
    __shared__ unsigned long long ms[64];
    __shared__ unsigned long long s_remv, s_kept;
    int t = threadIdx.x;
    unsigned long long remv = 0;                       // thread t owns word g=t
    unsigned long long nextdiag = (t < 64) ? g_maskT[t] : 0ull;
    for (int cb = 0; cb < NW; cb++) {
        if (t < 64) ms[t] = nextdiag;
        if (t == cb) s_remv = remv;
        __syncthreads();
        if (t < 64 && cb + 1 < NW)
            nextdiag = g_maskT[(size_t)(cb + 1) * ROWS + (cb + 1) * 64 + t];
        if (t == 0) {
            unsigned long long v = s_remv, kept = 0ull;
            int lim = PRE - cb * 64; if (lim > 64) lim = 64;
            unsigned long long avail = ~v;
            if (lim < 64) avail &= (1ull << lim) - 1ull;
            while (avail) {
                int j = __ffsll((long long)avail) - 1;
                kept |= 1ull << j;
                v |= ms[j];
                avail &= ~v;
                avail &= (j < 63) ? (~0ull << (j + 1)) : 0ull;
            }
            s_kept = kept;
            g_keep[cb] = kept;
        }
        __syncthreads();
        if (t > cb && t < NW) {
            unsigned long long kk = s_kept;
            const unsigned long long* rowT = g_maskT + (size_t)t * ROWS + cb * 64;
            while (kk) {
                unsigned long long m[8];
#pragma unroll
                for (int u = 0; u < 8; u++) m[u] = 0ull;
#pragma unroll
                for (int u = 0; u < 8; u++) {
                    if (!kk) break;
                    int j = __ffsll((long long)kk) - 1; kk &= kk - 1;
                    m[u] = rowT[j];
                }
                remv |= ((m[0] | m[1]) | (m[2] | m[3])) |
                        ((m[4] | m[5]) | (m[6] | m[7]));
            }
        }
    }
}

// ---------------- emit top-300 ----------------
__global__ __launch_bounds__(256) void output_kernel(float* __restrict__ out) {
    __shared__ int cnts[256];
    __shared__ int offs[256];
    __shared__ int Ktot;
    int t = threadIdx.x;
    int lo = t * 24;
    int hi = lo + 24; if (hi > PRE) hi = PRE;
    int c = 0;
    for (int i = lo; i < hi; i++)
        c += (int)((g_keep[i >> 6] >> (i & 63)) & 1ull);
    cnts[t] = c;
    __syncthreads();
    if (t == 0) {
        int r = 0;
        for (int q = 0; q < 256; q++) { offs[q] = r; r += cnts[q]; }
        Ktot = r;
    }
    __syncthreads();
    int K = Ktot;
    int pk = offs[t];
    for (int i = lo; i < hi; i++) {
        bool kept = (g_keep[i >> 6] >> (i & 63)) & 1ull;
        int pos = kept ? pk : (K + (i - pk));
        if (kept) pk++;
        if (pos < POST) {
            float4 b = g_sbox[i];
            out[pos * 4 + 0] = b.x;
            out[pos * 4 + 1] = b.y;
            out[pos * 4 + 2] = b.z - b.x + 1.f;
            out[pos * 4 + 3] = b.w - b.y + 1.f;
        }
    }
}

// ---------------- launch ----------------
extern "C" void kernel_launch(void* const* d_in, const int* in_sizes, int n_in,
                              void* d_out, int out_size) {
    const float* in_features = (const float*)d_in[0];
    const float* conv_w = (const float*)d_in[1];
    const float* conv_b = (const float*)d_in[2];
    const float* reg_w  = (const float*)d_in[3];
    const float* reg_b  = (const float*)d_in[4];
    const float* cls_w  = (const float*)d_in[5];
    const float* cls_b  = (const float*)d_in[6];
    float* out = (float*)d_out;

    // only batch index 7 feeds the output
    const float* in7 = in_features + (size_t)7 * 512 * NPIX;

    cudaFuncSetAttribute(conv3_kernel,
                         cudaFuncAttributeMaxDynamicSharedMemorySize, DSMSZ);

    int prep_total = WN + OC * PADCH;
    zero_hist_kernel<<<256, 512>>>();                            // 0
    prep_kernel<<<(prep_total + 255) / 256, 256>>>(in7, conv_w); // 1
    setup_misc_kernel<<<1, 256>>>();                             // 2
    conv3_kernel<<<dim3(32, 8), 256, DSMSZ>>>(conv_b);           // 3 <- profiled
    heads_part_kernel<<<dim3(37, 4), 128>>>(reg_w, cls_w);       // 4
    heads_fin_kernel<<<20, 128>>>(reg_b, cls_b);                 // 5
    bucket_sum_kernel<<<256, 256>>>();                           // 6
    bucket_pref_kernel<<<256, 256>>>();                          // 7
    bucket_fill_kernel<<<88, 256>>>();                           // 8
    rank_scatter_kernel<<<88, 256>>>();                          // 9
    nms_mask_kernel<<<dim3(NW, NW), 64>>>();                     // 10
    nms_scan_kernel<<<1, 128>>>();                               // 11
    output_kernel<<<1, 256>>>(out);                              // 12
}

// round 14
// speedup vs baseline: 4.3324x; 1.0569x over previous
#include <cuda_runtime.h>
#include <cstdint>

#define FSZ   50
#define NPIX  2500
#define OC    512
#define KTOT  4608      // 512*9
#define NANCH 22500     // 2500*9
#define PRE   6000
#define NW    94        // ceil(6000/64)
#define ROWS  6016
#define POST  300
#define PADW  52
#define PADCH 2704      // 52*52

// ---------------- scratch (static device allocations) ----------------
__device__ float               g_wre[OC * KTOT];           // weights, k' = r*512+ch
__device__ float               g_inpad[OC * PADCH + 256];  // padded batch-7 input
__device__ float               g_feat[OC * NPIX];
__device__ float4              g_boxes[NANCH];
__device__ unsigned            g_score[NANCH];
__device__ float               g_hpart[4][54 * NPIX];
__device__ unsigned            g_hist[65536];
__device__ unsigned            g_bsum[256];
__device__ unsigned            g_pref[65536];
__device__ unsigned            g_bfill[65536];
__device__ unsigned long long  g_bkey[NANCH];
__device__ float4              g_sbox[ROWS];
__device__ float               g_area[ROWS];
__device__ unsigned long long  g_maskT[(size_t)NW * ROWS];
__device__ unsigned long long  g_keep[NW];

// packed fp32x2 ops (sm_103a — only reachable via PTX)
#define FMA2(c, a, b) asm("fma.rn.f32x2 %0, %1, %2, %3;" : "=l"(c) : "l"(a), "l"(b), "l"(c))
#define ADD2(c, a, b) asm("add.rn.f32x2 %0, %1, %2;" : "=l"(c) : "l"(a), "l"(b))
__device__ __forceinline__ unsigned long long dup2(float x) {
    unsigned long long d;
    asm("mov.b64 %0, {%1, %1};" : "=l"(d) : "f"(x));
    return d;
}
__device__ __forceinline__ uint32_t smem_u32(const void* p) {
    uint32_t a;
    asm("{ .reg .u64 t; cvta.to.shared.u64 t, %1; cvt.u32.u64 %0, t; }" : "=r"(a) : "l"(p));
    return a;
}
#define CPA16(dst, src) asm volatile("cp.async.cg.shared.global [%0], [%1], 16;" :: "r"(dst), "l"(src))
#define CPA4(dst, src)  asm volatile("cp.async.ca.shared.global [%0], [%1], 4;"  :: "r"(dst), "l"(src))
#define CPCOMMIT()      asm volatile("cp.async.commit_group;" ::: "memory")
#define CPWAIT1()       asm volatile("cp.async.wait_group 1;" ::: "memory")

// ---------------- launch 0: weight transpose (coalesced both sides) + zero hist ----------------
__global__ __launch_bounds__(256) void prep_w_kernel(const float* __restrict__ cw) {
    __shared__ float ws[KTOT / 512 * 512];   // 4608 floats
    int b = blockIdx.x;    // = oc
    int t = threadIdx.x;
    for (int i = t; i < KTOT; i += 256) ws[i] = cw[b * KTOT + i];
    int idx = b * 256 + t;
    if (idx < 65536) g_hist[idx] = 0u;
    else g_bfill[idx - 65536] = 0u;
    __syncthreads();
    for (int k = t; k < KTOT; k += 256) {
        int ch = k & 511, r = k >> 9;
        g_wre[b * KTOT + k] = ws[ch * 9 + r];
    }
}

// ---------------- launch 1: input pad ----------------
__global__ void prep_in_kernel(const float* __restrict__ in7) {
    int j = blockIdx.x * 256 + threadIdx.x;
    if (j >= OC * PADCH) return;
    int c = j / PADCH, rem = j - c * PADCH;
    int y = rem / PADW, x = rem - y * PADW;
    float v = 0.f;
    if (y >= 1 && y <= 50 && x >= 1 && x <= 50)
        v = in7[c * NPIX + (y - 1) * FSZ + (x - 1)];
    g_inpad[j] = v;
}

// ---------------- launch 2: misc setup ----------------
__global__ void setup_misc_kernel() {
    int i = blockIdx.x * 256 + threadIdx.x;
    if (i < ROWS - PRE) {
        g_sbox[PRE + i] = make_float4(0.f, 0.f, 0.f, 0.f);
        g_area[PRE + i] = 1.f;
    }
    if (i < NW) g_keep[i] = 0ull;
}

// ---------------- launch 3: conv 3x3 (batch 7) + leaky relu ----------------
// implicit GEMM 512x2500x4608. CTA = 256 threads = 2 split-K warpgroups x 128.
// CTA tile 128oc x 80px; grid (32,4) = 128 CTAs. Thread tile 8oc x 5 px-pairs
// (40 FFMA2 per kk -> ~75% fma instruction mix). B pairs {2pg,2pg+1,16+2pg,
// 17+2pg,32+pg}: 2x LDS.128 + 1x LDS.64 per kk. A og-groups (8 rows x 80B)
// padded to 656B so the 4 broadcast addresses per warp hit distinct banks.
#define CBK    16
#define NCHK2  144                    // chunks per warpgroup (4608/2/16)
#define A_SZ   10496                  // 16 og-groups * 656B
#define B_OFF  10496
#define STG    15872                  // A 10496 + B 5376
#define WGB    31744                  // 2 stages
#define DSMSZ  63488
extern __shared__ char dsm[];

__global__ __launch_bounds__(256) void conv3_kernel(const float* __restrict__ bias) {
    uint32_t sb = smem_u32(dsm);
    int t = threadIdx.x;
    int wg = t >> 7;                  // 0 / 1
    int wt = t & 127;
    int px0 = blockIdx.x * 80, oc0 = blockIdx.y * 128;
    int og = wt >> 3;                 // 0..15 (8 oc each)
    int pg = wt & 7;                  // 0..7
    int wgk0 = wg * 2304;             // k-range start
    uint32_t wgbase = sb + wg * WGB;

    // pair indices handled by this thread
    int prs[5] = {2 * pg, 2 * pg + 1, 16 + 2 * pg, 17 + 2 * pg, 32 + pg};

    // A staging: 4 x 16B granules per thread (128oc x 4ks = 512 granules)
    int a_oc[4], a_ks[4];
    const float* a_src[4];
    uint32_t a_so[4];
#pragma unroll
    for (int s = 0; s < 4; s++) {
        int idx = wt + 128 * s;
        a_oc[s] = idx >> 2; a_ks[s] = idx & 3;
        a_src[s] = g_wre + (size_t)(oc0 + a_oc[s]) * KTOT + a_ks[s] * 4 + wgk0;
        a_so[s] = (a_oc[s] >> 3) * 656 + (a_oc[s] & 7) * 80 + a_ks[s] * 16;
    }

    // B staging: 10 x 4B per thread (1280 granules = 16kk x 80px, linear c*4)
    int b_kk[10], b_pix[10];
    uint32_t b_so[10];
#pragma unroll
    for (int s = 0; s < 10; s++) {
        int g = wt + 128 * s;
        int kk = g / 80, c = g - 80 * kk;
        int p = px0 + c;
        int py = p / 50, px = p - 50 * py;
        b_kk[s] = kk;
        b_pix[s] = py * PADW + px;
        b_so[s] = B_OFF + kk * 336 + c * 4;
    }

    unsigned long long acc[8][5];
#pragma unroll
    for (int i = 0; i < 8; i++)
#pragma unroll
        for (int j = 0; j < 5; j++) acc[i][j] = 0ull;

    auto issue = [&](int q, int st) {
        int kb = wgk0 + q * CBK;
        int r = kb >> 9, ch0 = kb & 511;
        int ry = r / 3;
        const float* ib = g_inpad + (size_t)ch0 * PADCH + ry * PADW + (r - 3 * ry);
        uint32_t sbase = wgbase + st * STG;
#pragma unroll
        for (int s = 0; s < 4; s++)
            CPA16(sbase + a_so[s], a_src[s] + q * CBK);
#pragma unroll
        for (int s = 0; s < 10; s++)
            CPA4(sbase + b_so[s], ib + (size_t)b_kk[s] * PADCH + b_pix[s]);
    };

    issue(0, 0); CPCOMMIT();
    issue(1, 1); CPCOMMIT();

    int barid = wg + 1;
    for (int q = 0; q < NCHK2; q++) {
        int st = q & 1;
        CPWAIT1();
        asm volatile("bar.sync %0, 128;" :: "r"(barid) : "memory");
        const char* A_ = dsm + wg * WGB + st * STG + og * 656;
        const char* B_ = dsm + wg * WGB + st * STG + B_OFF;

        // b2 double buffer: preload kk=0 (2x LDS.128 + 1x LDS.64)
        unsigned long long b2c[5], b2n[5];
        {
            ulonglong2 u0 = *(const ulonglong2*)(B_ + pg * 16);
            ulonglong2 u1 = *(const ulonglong2*)(B_ + 128 + pg * 16);
            b2c[0] = u0.x; b2c[1] = u0.y;
            b2c[2] = u1.x; b2c[3] = u1.y;
            b2c[4] = *(const unsigned long long*)(B_ + 256 + pg * 8);
        }

#pragma unroll
        for (int kk4 = 0; kk4 < CBK; kk4 += 4) {
            float4 av[8];
#pragma unroll
            for (int i = 0; i < 8; i++)
                av[i] = *(const float4*)(A_ + i * 80 + kk4 * 4);
#pragma unroll
            for (int kk = 0; kk < 4; kk++) {
                int gk = kk4 + kk;
                if (gk < CBK - 1) {
                    const char* brow = B_ + (gk + 1) * 336;
                    ulonglong2 u0 = *(const ulonglong2*)(brow + pg * 16);
                    ulonglong2 u1 = *(const ulonglong2*)(brow + 128 + pg * 16);
                    b2n[0] = u0.x; b2n[1] = u0.y;
                    b2n[2] = u1.x; b2n[3] = u1.y;
                    b2n[4] = *(const unsigned long long*)(brow + 256 + pg * 8);
                }
#pragma unroll
                for (int i = 0; i < 8; i++) {
                    float afv = (kk == 0) ? av[i].x : (kk == 1) ? av[i].y
                              : (kk == 2) ? av[i].z : av[i].w;
                    unsigned long long da = dup2(afv);
#pragma unroll
                    for (int j = 0; j < 5; j++)
                        FMA2(acc[i][j], da, b2c[j]);
                }
                if (gk < CBK - 1) {
#pragma unroll
                    for (int j = 0; j < 5; j++) b2c[j] = b2n[j];
                }
            }
        }
        // issue next-next chunk into the stage just freed
        asm volatile("bar.sync %0, 128;" :: "r"(barid) : "memory");
        if (q + 2 < NCHK2) issue(q + 2, st);
        CPCOMMIT();
    }

    // combine split-K halves (reuse stage smem), wg0 finishes
    __syncthreads();
    unsigned long long* epi = (unsigned long long*)dsm;
    if (wg == 1) {
#pragma unroll
        for (int i = 0; i < 8; i++)
#pragma unroll
            for (int j = 0; j < 5; j++) epi[wt * 41 + i * 5 + j] = acc[i][j];
    }
    __syncthreads();
    if (wg == 0) {
#pragma unroll
        for (int i = 0; i < 8; i++) {
            int oc = oc0 + og * 8 + i;
            float bv = bias[oc];
#pragma unroll
            for (int j = 0; j < 5; j++) {
                ADD2(acc[i][j], acc[i][j], epi[wt * 41 + i * 5 + j]);
                int p = px0 + 2 * prs[j];
                if (p < NPIX) {   // NPIX even -> pair-granular validity
                    float lo, hi;
                    asm("mov.b64 {%0, %1}, %2;" : "=f"(lo), "=f"(hi) : "l"(acc[i][j]));
                    lo += bv; hi += bv;
                    lo = (lo >= 0.f) ? lo : 0.01f * lo;
                    hi = (hi >= 0.f) ? hi : 0.01f * hi;
                    *(float2*)&g_feat[(size_t)oc * NPIX + p] = make_float2(lo, hi);
                }
            }
        }
    }
}

// ---------------- heads part 1: 1x1 convs, 4 channel-group partials ----------------
// grid (37, 4): 148 blocks (one per SM), 68 px per block.
__global__ __launch_bounds__(128) void heads_part_kernel(const float* __restrict__ reg_w,
                                                         const float* __restrict__ cls_w) {
    __shared__ float wsm[128][56];
    int t = threadIdx.x;
    int cg = blockIdx.y;
    int c0 = cg * 128;
    int p = blockIdx.x * 68 + t;
    bool act = (t < 68) && (p < NPIX);

    for (int i = t; i < 54 * 128; i += 128) {
        int o = i / 128, c = i - o * 128;
        float v = (o < 36) ? reg_w[o * 512 + c0 + c] : cls_w[(o - 36) * 512 + c0 + c];
        wsm[c][o] = v;
    }
    __syncthreads();

    float acc[54];
#pragma unroll
    for (int o = 0; o < 54; o++) acc[o] = 0.f;
    if (act) {
        for (int c = 0; c < 128; c++) {
            float f = g_feat[(size_t)(c0 + c) * NPIX + p];
#pragma unroll
            for (int o = 0; o < 54; o++) acc[o] += f * wsm[c][o];
        }
#pragma unroll
        for (int o = 0; o < 54; o++)
            g_hpart[cg][o * NPIX + p] = acc[o];
    }
}

// ---------------- heads part 2: combine + softmax + decode + scores + histogram ----------------
__global__ __launch_bounds__(128) void heads_fin_kernel(const float* __restrict__ reg_b,
                                                        const float* __restrict__ cls_b) {
    int p = blockIdx.x * 128 + threadIdx.x;
    if (p >= NPIX) return;
    float acc[54];
#pragma unroll
    for (int o = 0; o < 54; o++)
        acc[o] = (g_hpart[0][o * NPIX + p] + g_hpart[1][o * NPIX + p]) +
                 (g_hpart[2][o * NPIX + p] + g_hpart[3][o * NPIX + p]);
#pragma unroll
    for (int o = 0; o < 36; o++) acc[o] += reg_b[o];
#pragma unroll
    for (int o = 0; o < 18; o++) acc[36 + o] += cls_b[o];

    int pq = p / FSZ, pr = p - pq * FSZ;
    float cxv = 16.f * (float)pq + 8.f;
    float cyv = 16.f * (float)pr + 8.f;
    const float ssv[3]  = {8.f, 16.f, 32.f};
    const float sqr[3]  = {0.70710678f, 1.0f, 1.41421356f};
    const float sqi[3]  = {1.41421356f, 1.0f, 0.70710678f};
    const float NEGINF = __int_as_float(0xff800000);

#pragma unroll
    for (int k = 0; k < 9; k++) {
        float pr0 = acc[k * 4 + 0], pr1 = acc[k * 4 + 1];
        float pr2 = acc[k * 4 + 2], pr3 = acc[k * 4 + 3];
        float l0 = acc[36 + k * 2], l1 = acc[36 + k * 2 + 1];
        float m  = fmaxf(l0, l1);
        float e0 = expf(l0 - m), e1 = expf(l1 - m);
        float sc = e1 / (e0 + e1);

        int ri = k / 3, si = k - 3 * ri;
        float hk = (16.f * ssv[si]) * sqr[ri];
        float wk = (16.f * ssv[si]) * sqi[ri];
        float ax1 = cxv - wk * 0.5f;
        float ay1 = cyv - hk * 0.5f;
        const float hi = 799.f;
        float rx1 = fminf(fmaxf(pr0 + ax1, 0.f), hi);
        float ry1 = fminf(fmaxf(pr1 + ay1, 0.f), hi);
        float rx2 = fminf(fmaxf(((pr0 + ax1) + pr2) + wk, 0.f), hi);
        float ry2 = fminf(fmaxf(((pr1 + ay1) + pr3) + hk, 0.f), hi);
        float wv = pr2 + wk, hv = pr3 + hk;
        bool valid = (wv >= 16.f) && (hv >= 16.f);
        float s = valid ? sc : NEGINF;

        int a = p * 9 + k;
        g_boxes[a] = make_float4(rx1, ry1, rx2, ry2);
        unsigned u = __float_as_uint(s);
        u = (u >> 31) ? ~u : (u | 0x80000000u);
        g_score[a] = u;
        atomicAdd(&g_hist[u >> 16], 1u);
    }
}

// ---------------- bucket sums (coalesced) ----------------
__global__ __launch_bounds__(256) void bucket_sum_kernel() {
    __shared__ unsigned sh[256];
    int b = blockIdx.x, t = threadIdx.x;
    sh[t] = g_hist[b * 256 + t];
    __syncthreads();
    for (int off = 128; off; off >>= 1) {
        if (t < off) sh[t] += sh[t + off];
        __syncthreads();
    }
    if (t == 0) g_bsum[b] = sh[0];
}

// ---------------- suffix-prefix per bucket (coalesced) ----------------
__global__ __launch_bounds__(256) void bucket_pref_kernel() {
    __shared__ unsigned sh[256];
    __shared__ unsigned above_s;
    int b = blockIdx.x, t = threadIdx.x;
    unsigned v = (t > b) ? g_bsum[t] : 0u;
    sh[t] = v;
    __syncthreads();
    for (int off = 128; off; off >>= 1) {
        if (t < off) sh[t] += sh[t + off];
        __syncthreads();
    }
    if (t == 0) above_s = sh[0];
    __syncthreads();
    unsigned above = above_s;
    unsigned h = g_hist[b * 256 + t];
    __syncthreads();
    sh[t] = h;
    __syncthreads();
    for (int off = 1; off < 256; off <<= 1) {
        unsigned x = (t + off < 256) ? sh[t + off] : 0u;
        __syncthreads();
        sh[t] += x;
        __syncthreads();
    }
    g_pref[b * 256 + t] = above + sh[t] - h;   // count strictly higher
}

// ---------------- bucket fill (only buckets that can reach top-6000) ----------------
__global__ void bucket_fill_kernel() {
    int i = blockIdx.x * 256 + threadIdx.x;
    if (i >= NANCH) return;
    unsigned s = g_score[i];
    unsigned b = s >> 16;
    unsigned base = g_pref[b];
    if (base >= PRE) return;
    unsigned slot = atomicAdd(&g_bfill[b], 1u);
    g_bkey[base + slot] = ((unsigned long long)s << 32) | (unsigned)(~i);
}

// ---------------- exact rank + scatter ----------------
__global__ void rank_scatter_kernel() {
    int i = blockIdx.x * 256 + threadIdx.x;
    if (i >= NANCH) return;
    unsigned s = g_score[i];
    unsigned b = s >> 16;
    unsigned base = g_pref[b];
    if (base >= PRE) return;
    unsigned cnt = g_hist[b];
    unsigned long long my = ((unsigned long long)s << 32) | (unsigned)(~i);
    unsigned r = base;
    for (unsigned q = 0; q < cnt; q++)
        r += (g_bkey[base + q] > my);
    if (r < PRE) {
        float4 bx = g_boxes[i];
        g_sbox[r] = bx;
        g_area[r] = (bx.z - bx.x + 1.f) * (bx.w - bx.y + 1.f);
    }
}

// ---------------- NMS mask, transposed layout (yy2 = max bug preserved) ----------------
// division-free: ov > 0.7  <=>  (den>0 && inter > 0.7*den) || (den==0 && inter>0)
// 256 threads cover 4 j-tiles per block; grid (24, 94), early-out below diagonal.
__global__ __launch_bounds__(256) void nms_mask_kernel() {
    int gi = blockIdx.y;
    int jb = blockIdx.x * 4;
    if (jb + 3 < gi) return;
    __shared__ float4 cbx[4][64];
    __shared__ float  car[4][64];
    int t = threadIdx.x;
    int jt = t >> 6, tt = t & 63;
    int gj = jb + jt;
    if (gj < NW) {
        cbx[jt][tt] = g_sbox[gj * 64 + tt];
        car[jt][tt] = g_area[gj * 64 + tt];
    }
    __syncthreads();
    if (gj < gi || gj >= NW) return;
    int i = gi * 64 + tt;
    float4 bi = g_sbox[i];
    float  ai = g_area[i];
    unsigned long long word = 0;
#pragma unroll 8
    for (int jj = 0; jj < 64; jj++) {
        float4 bj = cbx[jt][jj];
        float xx1 = fmaxf(bi.x, bj.x);
        float yy1 = fmaxf(bi.y, bj.y);
        float xx2 = fminf(bi.z, bj.z);
        float yy2 = fmaxf(bi.w, bj.w);   // reference bug: maximum, not minimum
        float w = fmaxf(0.f, xx2 - xx1 + 1.f);
        float h = fmaxf(0.f, yy2 - yy1 + 1.f);
        float inter = w * h;
        float den = ai + car[jt][jj] - inter;
        bool sup = (den > 0.f) ? (inter > 0.7f * den) : ((den == 0.f) && (inter > 0.f));
        word |= ((unsigned long long)sup) << jj;
    }
    g_maskT[(size_t)gj * ROWS + i] = word;   // coalesced across tt
}

// ---------------- greedy NMS scan (ffs skip-loop, 8-wide MLP) ----------------
__global__ __launch_bounds__(128) void nms_scan_kernel() {
    __shared__ unsigned long long ms[64];
    __shared__ unsigned long long s_remv, s_kept;
    int t = threadIdx.x;
    unsigned long long remv = 0;                       // thread t owns word g=t
    unsigned long long nextdiag = (t < 64) ? g_maskT[t] : 0ull;
    for (int cb = 0; cb < NW; cb++) {
        if (t < 64) ms[t] = nextdiag;
        if (t == cb) s_remv = remv;
        __syncthreads();
        if (t < 64 && cb + 1 < NW)
            nextdiag = g_maskT[(size_t)(cb + 1) * ROWS + (cb + 1) * 64 + t];
        if (t == 0) {
            unsigned long long v = s_remv, kept = 0ull;
            int lim = PRE - cb * 64; if (lim > 64) lim = 64;
            unsigned long long avail = ~v;
            if (lim < 64) avail &= (1ull << lim) - 1ull;
            while (avail) {
                int j = __ffsll((long long)avail) - 1;
                kept |= 1ull << j;
                v |= ms[j];
                avail &= ~v;
                avail &= (j < 63) ? (~0ull << (j + 1)) : 0ull;
            }
            s_kept = kept;
            g_keep[cb] = kept;
        }
        __syncthreads();
        if (t > cb && t < NW) {
            unsigned long long kk = s_kept;
            const unsigned long long* rowT = g_maskT + (size_t)t * ROWS + cb * 64;
            while (kk) {
                unsigned long long m[8];
#pragma unroll
                for (int u = 0; u < 8; u++) m[u] = 0ull;
#pragma unroll
                for (int u = 0; u < 8; u++) {
                    if (!kk) break;
                    int j = __ffsll((long long)kk) - 1; kk &= kk - 1;
                    m[u] = rowT[j];
                }
                remv |= ((m[0] | m[1]) | (m[2] | m[3])) |
                        ((m[4] | m[5]) | (m[6] | m[7]));
            }
        }
    }
}

// ---------------- emit top-300 ----------------
__global__ __launch_bounds__(256) void output_kernel(float* __restrict__ out) {
    __shared__ int cnts[256];
    __shared__ int offs[256];
    __shared__ int Ktot;
    int t = threadIdx.x;
    int lo = t * 24;
    int hi = lo + 24; if (hi > PRE) hi = PRE;
    int c = 0;
    for (int i = lo; i < hi; i++)
        c += (int)((g_keep[i >> 6] >> (i & 63)) & 1ull);
    cnts[t] = c;
    __syncthreads();
    if (t == 0) {
        int r = 0;
        for (int q = 0; q < 256; q++) { offs[q] = r; r += cnts[q]; }
        Ktot = r;
    }
    __syncthreads();
    int K = Ktot;
    int pk = offs[t];
    for (int i = lo; i < hi; i++) {
        bool kept = (g_keep[i >> 6] >> (i & 63)) & 1ull;
        int pos = kept ? pk : (K + (i - pk));
        if (kept) pk++;
        if (pos < POST) {
            float4 b = g_sbox[i];
            out[pos * 4 + 0] = b.x;
            out[pos * 4 + 1] = b.y;
            out[pos * 4 + 2] = b.z - b.x + 1.f;
            out[pos * 4 + 3] = b.w - b.y + 1.f;
        }
    }
}

// ---------------- launch ----------------
extern "C" void kernel_launch(void* const* d_in, const int* in_sizes, int n_in,
                              void* d_out, int out_size) {
    const float* in_features = (const float*)d_in[0];
    const float* conv_w = (const float*)d_in[1];
    const float* conv_b = (const float*)d_in[2];
    const float* reg_w  = (const float*)d_in[3];
    const float* reg_b  = (const float*)d_in[4];
    const float* cls_w  = (const float*)d_in[5];
    const float* cls_b  = (const float*)d_in[6];
    float* out = (float*)d_out;

    // only batch index 7 feeds the output
    const float* in7 = in_features + (size_t)7 * 512 * NPIX;

    cudaFuncSetAttribute(conv3_kernel,
                         cudaFuncAttributeMaxDynamicSharedMemorySize, DSMSZ);

    prep_w_kernel<<<512, 256>>>(conv_w);                         // 0
    prep_in_kernel<<<(OC * PADCH + 255) / 256, 256>>>(in7);      // 1
    setup_misc_kernel<<<1, 256>>>();                             // 2
    conv3_kernel<<<dim3(32, 4), 256, DSMSZ>>>(conv_b);           // 3 <- profiled
    heads_part_kernel<<<dim3(37, 4), 128>>>(reg_w, cls_w);       // 4
    heads_fin_kernel<<<20, 128>>>(reg_b, cls_b);                 // 5
    bucket_sum_kernel<<<256, 256>>>();                           // 6
    bucket_pref_kernel<<<256, 256>>>();                          // 7
    bucket_fill_kernel<<<88, 256>>>();                           // 8
    rank_scatter_kernel<<<88, 256>>>();                          // 9
    nms_mask_kernel<<<dim3(24, NW), 256>>>();                    // 10
    nms_scan_kernel<<<1, 128>>>();                               // 11
    output_kernel<<<1, 256>>>(out);                              // 12
}